// round 6
// baseline (speedup 1.0000x reference)
#include <cuda_runtime.h>
#include <math.h>

#define NN   50000
#define EE   1600000
#define ET   (EE + NN)
#define INC  256
#define HC   128
#define H1   4
#define C1   32
#define BN_EPS 1e-5f
#define NB   196            // ceil(NN/256)

typedef unsigned long long ull;

// ---------------- scratch ----------------
struct __align__(32) Slot { float w0, w1, w2, w3; int src; int dst; float ea; float pad; };

__device__ float g_xs1 [NN * HC];
__device__ float g_out1[NN * HC];
__device__ float g_xs2 [NN * C1];
__device__ float g_als1[NN * H1];
__device__ float g_ald1[NN * H1];
__device__ float g_als2[NN];
__device__ float g_ald2[NN];
__device__ float g_w2  [ET];
__device__ int   g_deg   [NN];
__device__ int   g_rowptr[NN + 1];
__device__ int   g_cursor[NN];
__device__ int   g_bsum[NB];
__device__ int   g_boff[NB];
__device__ Slot  g_slot[ET];
__device__ float g_partial[512];
__device__ float g_mean;
__device__ float g_k1v[H1];
__device__ float g_k2;

// ---------------- f32x2 helpers ----------------
__device__ __forceinline__ void fma2(ull &d, ull a, ull b) {
    asm("fma.rn.f32x2 %0, %1, %2, %0;" : "+l"(d) : "l"(a), "l"(b));
}
__device__ __forceinline__ ull pack2(float x, float y) {
    ull r; asm("mov.b64 %0, {%1, %2};" : "=l"(r) : "f"(x), "f"(y)); return r;
}
__device__ __forceinline__ float2 unpack2(ull v) {
    float2 f; asm("mov.b64 {%0, %1}, %2;" : "=f"(f.x), "=f"(f.y) : "l"(v)); return f;
}

__device__ __forceinline__ float leaky(float x) { return x > 0.f ? x : 0.2f * x; }
__device__ __forceinline__ float elu(float x)   { return x > 0.f ? x : expm1f(x); }
__device__ __forceinline__ float wexp(float x)  { return __expf(fminf(x, 80.f)); }

// ---------------- CSR build ----------------
__global__ void init_deg_kernel() {
    int i = blockIdx.x * blockDim.x + threadIdx.x;
    if (i < NN) g_deg[i] = 1;   // self loop
}

__global__ void hist_mean_kernel(const int* __restrict__ ei, const float* __restrict__ ea) {
    __shared__ float s[256];
    float v = 0.f;
    for (int e = blockIdx.x * blockDim.x + threadIdx.x; e < EE; e += gridDim.x * blockDim.x) {
        atomicAdd(&g_deg[ei[EE + e]], 1);
        v += ea[e];
    }
    s[threadIdx.x] = v; __syncthreads();
    for (int o = 128; o > 0; o >>= 1) {
        if (threadIdx.x < o) s[threadIdx.x] += s[threadIdx.x + o];
        __syncthreads();
    }
    if (threadIdx.x == 0) g_partial[blockIdx.x] = s[0];
}

__global__ void mean_fin_kernel(const float* __restrict__ We1, const float* __restrict__ ae1,
                                const float* __restrict__ We2, const float* __restrict__ ae2) {
    __shared__ float s[512];
    int t = threadIdx.x;
    s[t] = g_partial[t]; __syncthreads();
    for (int o = 256; o > 0; o >>= 1) {
        if (t < o) s[t] += s[t + o];
        __syncthreads();
    }
    if (t == 0) g_mean = s[0] / (float)EE;
    if (t < H1) {
        float k = 0.f;
        for (int c = 0; c < C1; c++) k += We1[t * C1 + c] * ae1[t * C1 + c];
        g_k1v[t] = k;
    }
    if (t == H1) {
        float k = 0.f;
        for (int c = 0; c < C1; c++) k += We2[c] * ae2[c];
        g_k2 = k;
    }
}

// ---- 3-phase parallel scan ----
__global__ void scan_part_kernel() {
    __shared__ int s[256];
    int t = threadIdx.x, b = blockIdx.x;
    int i = b * 256 + t;
    int v = (i < NN) ? g_deg[i] : 0;
    s[t] = v; __syncthreads();
    for (int o = 128; o > 0; o >>= 1) {
        if (t < o) s[t] += s[t + o];
        __syncthreads();
    }
    if (t == 0) g_bsum[b] = s[0];
}

__global__ void scan_mid_kernel() {
    __shared__ int s[256];
    int t = threadIdx.x;
    int v = (t < NB) ? g_bsum[t] : 0;
    s[t] = v; __syncthreads();
    for (int o = 1; o < 256; o <<= 1) {
        int u = (t >= o) ? s[t - o] : 0;
        __syncthreads();
        s[t] += u;
        __syncthreads();
    }
    if (t < NB) g_boff[t] = s[t] - v;   // exclusive
}

__global__ void scan_fin_kernel() {
    __shared__ int s[256];
    int t = threadIdx.x, b = blockIdx.x;
    int i = b * 256 + t;
    int v = (i < NN) ? g_deg[i] : 0;
    s[t] = v; __syncthreads();
    for (int o = 1; o < 256; o <<= 1) {
        int u = (t >= o) ? s[t - o] : 0;
        __syncthreads();
        s[t] += u;
        __syncthreads();
    }
    int excl = s[t] - v + g_boff[b];
    if (i < NN) { g_rowptr[i] = excl; g_cursor[i] = excl; }
    if (b == 0 && t == 0) g_rowptr[NN] = ET;
}

// ---------------- GEMM1: [NN,256] @ [256,128], BM=64 tiles, f32x2 ----------------
__global__ void __launch_bounds__(256, 3) sgemm1_kernel(const float* __restrict__ A,
                                                        const float* __restrict__ B) {
    const int K = INC, Nn = HC;
    __shared__ float As[8][64];
    __shared__ float Bs[8][128];
    int tid  = threadIdx.x;
    int brow = blockIdx.x;
    int trow = (tid / 16) * 4;          // 0..60
    int tcol = (tid % 16) * 8;          // 0..120
    int rowA = tid & 63;                // 0..63
    int kA   = (tid >> 6) * 2;          // 0,2,4,6
    int rowB = tid / 32, colB = (tid % 32) * 4;
    int ag = brow * 64 + rowA;

    ull acc2[2][8];                     // row pairs (trow+2p, +1) x 8 cols
#pragma unroll
    for (int p = 0; p < 2; p++)
#pragma unroll
        for (int j = 0; j < 8; j++) acc2[p][j] = 0ULL;

    for (int k0 = 0; k0 < K; k0 += 8) {
        float2 av = make_float2(0.f, 0.f);
        if (ag < NN) av = *(const float2*)(A + (size_t)ag * K + k0 + kA);
        As[kA + 0][rowA] = av.x;
        As[kA + 1][rowA] = av.y;
        float4 bv = *(const float4*)(B + (size_t)(k0 + rowB) * Nn + colB);
        *(float4*)(&Bs[rowB][colB]) = bv;
        __syncthreads();
#pragma unroll
        for (int kk = 0; kk < 8; kk++) {
            ull ar2[2];
#pragma unroll
            for (int p = 0; p < 2; p++) {
                float2 a2 = *(const float2*)(&As[kk][trow + 2 * p]);
                ar2[p] = pack2(a2.x, a2.y);
            }
            ull br2[8];
#pragma unroll
            for (int j = 0; j < 8; j++) {
                float b = Bs[kk][tcol + j];
                br2[j] = pack2(b, b);
            }
#pragma unroll
            for (int p = 0; p < 2; p++)
#pragma unroll
                for (int j = 0; j < 8; j++) fma2(acc2[p][j], ar2[p], br2[j]);
        }
        __syncthreads();
    }
#pragma unroll
    for (int p = 0; p < 2; p++) {
        float c0[8], c1[8];
#pragma unroll
        for (int j = 0; j < 8; j++) {
            float2 v = unpack2(acc2[p][j]);
            c0[j] = v.x; c1[j] = v.y;
        }
        int r = brow * 64 + trow + 2 * p;
        if (r < NN) {
            float* cp = g_xs1 + (size_t)r * Nn + tcol;
            *(float4*)(cp)     = make_float4(c0[0], c0[1], c0[2], c0[3]);
            *(float4*)(cp + 4) = make_float4(c0[4], c0[5], c0[6], c0[7]);
        }
        if (r + 1 < NN) {
            float* cp = g_xs1 + (size_t)(r + 1) * Nn + tcol;
            *(float4*)(cp)     = make_float4(c1[0], c1[1], c1[2], c1[3]);
            *(float4*)(cp + 4) = make_float4(c1[4], c1[5], c1[6], c1[7]);
        }
    }
}

// ---------------- attention coefficients (layer 1), float4 ----------------
__global__ void al1_kernel(const float* __restrict__ as1, const float* __restrict__ ad1) {
    int idx = blockIdx.x * blockDim.x + threadIdx.x;
    if (idx >= NN * H1) return;
    int n = idx >> 2, h = idx & 3;
    const float4* xp = (const float4*)(g_xs1 + (size_t)n * HC + h * C1);
    const float4* ap = (const float4*)(as1 + h * C1);
    const float4* dp = (const float4*)(ad1 + h * C1);
    float s = 0.f, d = 0.f;
#pragma unroll
    for (int c = 0; c < 8; c++) {
        float4 v = xp[c], a = ap[c], b = dp[c];
        s += v.x * a.x + v.y * a.y + v.z * a.z + v.w * a.w;
        d += v.x * b.x + v.y * b.y + v.z * b.z + v.w * b.w;
    }
    g_als1[idx] = s;
    g_ald1[idx] = d;
}

// ---------------- scatter + fused layer-1 softmax weights (R4-proven) ----------------
__global__ void scatter_fused_kernel(const int* __restrict__ ei, const float* __restrict__ ea) {
    float mn = g_mean;
    float k0 = g_k1v[0], k1 = g_k1v[1], k2 = g_k1v[2], k3 = g_k1v[3];
    for (int idx = blockIdx.x * blockDim.x + threadIdx.x; idx < ET; idx += gridDim.x * blockDim.x) {
        int srcn, dstn; float eav;
        if (idx < EE) {
            srcn = ei[idx];
            dstn = ei[EE + idx];
            eav  = ea[idx];
        } else {
            srcn = dstn = idx - EE;
            eav  = mn;
        }
        int slot = atomicAdd(&g_cursor[dstn], 1);
        float4 als = *(const float4*)(g_als1 + srcn * 4);
        float4 ald = *(const float4*)(g_ald1 + dstn * 4);
        float4 w;
        w.x = wexp(leaky(als.x + ald.x + k0 * eav));
        w.y = wexp(leaky(als.y + ald.y + k1 * eav));
        w.z = wexp(leaky(als.z + ald.z + k2 * eav));
        w.w = wexp(leaky(als.w + ald.w + k3 * eav));
        float4 meta = make_float4(__int_as_float(srcn), __int_as_float(dstn), eav, 0.f);
        float4* sp = (float4*)&g_slot[slot];
        sp[0] = w;
        sp[1] = meta;
    }
}

// ---------------- agg1: warp per node, all 4 heads; fused bias+bn+elu (R4-proven) ----
__global__ void agg1_kernel(const float* __restrict__ b1, const float* __restrict__ g1,
                            const float* __restrict__ be1) {
    int n    = (blockIdx.x * blockDim.x + threadIdx.x) >> 5;
    int lane = threadIdx.x & 31;
    if (n >= NN) return;
    int beg = g_rowptr[n], end = g_rowptr[n + 1];

    float acc0 = 0.f, acc1 = 0.f, acc2 = 0.f, acc3 = 0.f;
    float den0 = 0.f, den1 = 0.f, den2 = 0.f, den3 = 0.f;
    int e = beg;
    for (; e + 2 <= end; e += 2) {
        float4 wA = *(const float4*)&g_slot[e];
        float4 wB = *(const float4*)&g_slot[e + 1];
        int sA = ((const int*)&g_slot[e])[4];
        int sB = ((const int*)&g_slot[e + 1])[4];
        const float* xA = g_xs1 + (size_t)sA * HC + lane;
        const float* xB = g_xs1 + (size_t)sB * HC + lane;
        float a0 = xA[0], a1 = xA[32], a2 = xA[64], a3 = xA[96];
        float c0 = xB[0], c1 = xB[32], c2 = xB[64], c3 = xB[96];
        acc0 += wA.x * a0 + wB.x * c0;
        acc1 += wA.y * a1 + wB.y * c1;
        acc2 += wA.z * a2 + wB.z * c2;
        acc3 += wA.w * a3 + wB.w * c3;
        den0 += wA.x + wB.x;
        den1 += wA.y + wB.y;
        den2 += wA.z + wB.z;
        den3 += wA.w + wB.w;
    }
    for (; e < end; ++e) {
        float4 w = *(const float4*)&g_slot[e];
        int s = ((const int*)&g_slot[e])[4];
        const float* xr = g_xs1 + (size_t)s * HC + lane;
        acc0 += w.x * xr[0];  den0 += w.x;
        acc1 += w.y * xr[32]; den1 += w.y;
        acc2 += w.z * xr[64]; den2 += w.z;
        acc3 += w.w * xr[96]; den3 += w.w;
    }
    float inv = rsqrtf(1.f + BN_EPS);
    float* op = g_out1 + (size_t)n * HC + lane;
#pragma unroll
    for (int h = 0; h < 4; h++) {
        float a = (h == 0) ? acc0 : (h == 1) ? acc1 : (h == 2) ? acc2 : acc3;
        float d = (h == 0) ? den0 : (h == 1) ? den1 : (h == 2) ? den2 : den3;
        int c = h * 32 + lane;
        float v = a / (d + 1e-16f) + b1[c];
        v = v * (g1[c] * inv) + be1[c];
        op[h * 32] = elu(v);
    }
}

// ---------------- GEMM2 + fused al2 ----------------
__global__ void gemm2_kernel(const float* __restrict__ W2, const float* __restrict__ as2,
                             const float* __restrict__ ad2) {
    __shared__ float Ws[HC * C1];
    for (int i = threadIdx.x; i < HC * C1; i += blockDim.x) Ws[i] = W2[i];
    __syncthreads();
    int node = blockIdx.x * 8 + threadIdx.x / 32;
    int lane = threadIdx.x & 31;
    if (node >= NN) return;
    const float* row = g_out1 + (size_t)node * HC;
    float s = 0.f;
#pragma unroll 8
    for (int k = 0; k < HC; k++) s += row[k] * Ws[k * C1 + lane];
    g_xs2[(size_t)node * C1 + lane] = s;

    float ps = s * as2[lane];
    float pd = s * ad2[lane];
#pragma unroll
    for (int off = 16; off > 0; off >>= 1) {
        ps += __shfl_xor_sync(0xffffffffu, ps, off);
        pd += __shfl_xor_sync(0xffffffffu, pd, off);
    }
    if (lane == 0) { g_als2[node] = ps; g_ald2[node] = pd; }
}

// ---------------- layer-2 softmax weights (slot-parallel, R4-proven) ----------------
__global__ void logits2_kernel() {
    float k2 = g_k2;
    for (int e = blockIdx.x * blockDim.x + threadIdx.x; e < ET; e += gridDim.x * blockDim.x) {
        float4 meta = ((const float4*)&g_slot[e])[1];
        int src = __float_as_int(meta.x);
        int dst = __float_as_int(meta.y);
        float l = leaky(g_als2[src] + g_ald2[dst] + k2 * meta.z);
        g_w2[e] = wexp(l);
    }
}

// ---------------- agg2: warp/node + fused bn+elu + heads ----------------
__global__ void agg2_heads_kernel(const float* __restrict__ b2, const float* __restrict__ g2,
                                  const float* __restrict__ be2,
                                  const float* __restrict__ Wc1, const float* __restrict__ bc1,
                                  const float* __restrict__ Wc2, const float* __restrict__ bc2,
                                  const float* __restrict__ Wr1, const float* __restrict__ br1,
                                  const float* __restrict__ Wr2, const float* __restrict__ br2,
                                  float* __restrict__ out) {
    __shared__ float sWc1[C1 * 16], sWr1[C1 * 16];
    __shared__ float sWc2[32], sWr2[16];
    __shared__ float sbc1[16], sbr1[16], sbc2[2], sbr2v[1];
    __shared__ float sh[8][32];
    int t = threadIdx.x;
    for (int i = t; i < C1 * 16; i += blockDim.x) { sWc1[i] = Wc1[i]; sWr1[i] = Wr1[i]; }
    if (t < 32) sWc2[t] = Wc2[t];
    if (t < 16) { sWr2[t] = Wr2[t]; sbc1[t] = bc1[t]; sbr1[t] = br1[t]; }
    if (t < 2)  sbc2[t] = bc2[t];
    if (t == 32) sbr2v[0] = br2[0];
    __syncthreads();

    int wi   = t >> 5;
    int lane = t & 31;
    int n    = blockIdx.x * 8 + wi;
    if (n >= NN) return;
    int beg = g_rowptr[n], end = g_rowptr[n + 1];

    float den = 0.f, acc = 0.f;
    int e = beg;
    for (; e + 2 <= end; e += 2) {
        float wA = g_w2[e], wB = g_w2[e + 1];
        int sA = ((const int*)&g_slot[e])[4];
        int sB = ((const int*)&g_slot[e + 1])[4];
        float xA = g_xs2[(size_t)sA * C1 + lane];
        float xB = g_xs2[(size_t)sB * C1 + lane];
        acc += wA * xA + wB * xB;
        den += wA + wB;
    }
    for (; e < end; ++e) {
        float w = g_w2[e];
        int s = ((const int*)&g_slot[e])[4];
        acc += w * g_xs2[(size_t)s * C1 + lane];
        den += w;
    }
    float v = acc / (den + 1e-16f) + b2[lane];
    v = v * (g2[lane] * rsqrtf(1.f + BN_EPS)) + be2[lane];
    float h = elu(v);
    out[3 * NN + (size_t)n * C1 + lane] = h;
    sh[wi][lane] = h;
    __syncwarp();

    int j = lane & 15;
    const float* W = (lane < 16) ? sWc1 : sWr1;
    float tt = (lane < 16) ? sbc1[j] : sbr1[j];
#pragma unroll
    for (int c = 0; c < C1; c++) tt += sh[wi][c] * W[c * 16 + j];
    tt = fmaxf(tt, 0.f);
    float pa = (lane < 16) ? tt * sWc2[j * 2 + 0] : tt * sWr2[j];
    float pb = (lane < 16) ? tt * sWc2[j * 2 + 1] : 0.f;
#pragma unroll
    for (int off = 8; off > 0; off >>= 1) {
        pa += __shfl_xor_sync(0xffffffffu, pa, off);
        pb += __shfl_xor_sync(0xffffffffu, pb, off);
    }
    if (lane == 0) {
        out[(size_t)n * 2 + 0] = pa + sbc2[0];
        out[(size_t)n * 2 + 1] = pb + sbc2[1];
    }
    if (lane == 16) {
        out[2 * NN + n] = pa + sbr2v[0];
    }
}

// ---------------- launch (stream-forked graph) ----------------
extern "C" void kernel_launch(void* const* d_in, const int* in_sizes, int n_in,
                              void* d_out, int out_size) {
    const float* x   = (const float*)d_in[0];
    const int*   ei  = (const int*)d_in[1];     // int32 (JAX x64 disabled)
    const float* ea  = (const float*)d_in[2];
    const float* W1  = (const float*)d_in[3];
    const float* as1 = (const float*)d_in[4];
    const float* ad1 = (const float*)d_in[5];
    const float* We1 = (const float*)d_in[6];
    const float* ae1 = (const float*)d_in[7];
    const float* b1  = (const float*)d_in[8];
    const float* g1  = (const float*)d_in[9];
    const float* be1 = (const float*)d_in[10];
    const float* W2  = (const float*)d_in[11];
    const float* as2 = (const float*)d_in[12];
    const float* ad2 = (const float*)d_in[13];
    const float* We2 = (const float*)d_in[14];
    const float* ae2 = (const float*)d_in[15];
    const float* b2  = (const float*)d_in[16];
    const float* g2  = (const float*)d_in[17];
    const float* be2 = (const float*)d_in[18];
    const float* Wc1 = (const float*)d_in[19];
    const float* bc1 = (const float*)d_in[20];
    const float* Wc2 = (const float*)d_in[21];
    const float* bc2 = (const float*)d_in[22];
    const float* Wr1 = (const float*)d_in[23];
    const float* br1 = (const float*)d_in[24];
    const float* Wr2 = (const float*)d_in[25];
    const float* br2 = (const float*)d_in[26];
    float* out = (float*)d_out;

    // Fork a side branch for the CSR build (independent of GEMM1 chain).
    cudaStream_t sB;
    cudaStreamCreateWithFlags(&sB, cudaStreamNonBlocking);
    cudaEvent_t eFork, eJoin;
    cudaEventCreateWithFlags(&eFork, cudaEventDisableTiming);
    cudaEventCreateWithFlags(&eJoin, cudaEventDisableTiming);

    cudaEventRecord(eFork, 0);
    cudaStreamWaitEvent(sB, eFork, 0);

    // Branch B (CSR): launches 0-2 then 5-7
    init_deg_kernel<<<(NN + 255) / 256, 256, 0, sB>>>();           // 0
    hist_mean_kernel<<<512, 256, 0, sB>>>(ei, ea);                 // 1
    mean_fin_kernel<<<1, 512, 0, sB>>>(We1, ae1, We2, ae2);        // 2
    // Branch A (GEMM1): launch 3 = profiled slot
    sgemm1_kernel<<<(NN + 63) / 64, 256>>>(x, W1);                 // 3 <- profiled
    al1_kernel<<<(NN * H1 + 255) / 256, 256>>>(as1, ad1);          // 4
    scan_part_kernel<<<NB, 256, 0, sB>>>();                        // 5
    scan_mid_kernel<<<1, 256, 0, sB>>>();                          // 6
    scan_fin_kernel<<<NB, 256, 0, sB>>>();                         // 7

    cudaEventRecord(eJoin, sB);
    cudaStreamWaitEvent(0, eJoin, 0);

    // Joined tail on main stream
    scatter_fused_kernel<<<2048, 256>>>(ei, ea);                   // 8
    agg1_kernel<<<(NN + 7) / 8, 256>>>(b1, g1, be1);               // 9
    gemm2_kernel<<<(NN + 7) / 8, 256>>>(W2, as2, ad2);             // 10
    logits2_kernel<<<2048, 256>>>();                               // 11
    agg2_heads_kernel<<<(NN + 7) / 8, 256>>>(b2, g2, be2,
        Wc1, bc1, Wc2, bc2, Wr1, br1, Wr2, br2, out);              // 12

    // Events are consumed by the captured graph; destroying them here is safe.
    cudaEventDestroy(eFork);
    cudaEventDestroy(eJoin);
    // NOTE: sB intentionally not destroyed (its capture state belongs to the
    // ongoing capture); leaked once per capture call, never during replay.
}

// round 7
// speedup vs baseline: 1.1297x; 1.1297x over previous
#include <cuda_runtime.h>
#include <math.h>

#define NN   50000
#define EE   1600000
#define ET   (EE + NN)
#define INC  256
#define HC   128
#define H1   4
#define C1   32
#define BN_EPS 1e-5f
#define NB   196            // ceil(NN/256)

typedef unsigned long long ull;

// ---------------- scratch ----------------
struct __align__(32) Slot { float w0, w1, w2, w3; int src; int dst; float ea; float pad; };

__device__ float g_xs1 [NN * HC];
__device__ float g_out1[NN * HC];
__device__ float g_xs2 [NN * C1];
__device__ float g_als1[NN * H1];
__device__ float g_ald1[NN * H1];
__device__ float g_als2[NN];
__device__ float g_ald2[NN];
__device__ float g_w2  [ET];
__device__ int   g_deg   [NN];
__device__ int   g_rowptr[NN + 1];
__device__ int   g_cursor[NN];
__device__ int   g_bsum[NB];
__device__ int   g_boff[NB];
__device__ Slot  g_slot[ET];
__device__ float g_partial[512];
__device__ float g_mean;
__device__ float g_k1v[H1];
__device__ float g_k2;

// ---------------- f32x2 helpers ----------------
__device__ __forceinline__ void fma2(ull &d, ull a, ull b) {
    asm("fma.rn.f32x2 %0, %1, %2, %0;" : "+l"(d) : "l"(a), "l"(b));
}
__device__ __forceinline__ ull pack2(float x, float y) {
    ull r; asm("mov.b64 %0, {%1, %2};" : "=l"(r) : "f"(x), "f"(y)); return r;
}
__device__ __forceinline__ float2 unpack2(ull v) {
    float2 f; asm("mov.b64 {%0, %1}, %2;" : "=f"(f.x), "=f"(f.y) : "l"(v)); return f;
}

__device__ __forceinline__ float leaky(float x) { return x > 0.f ? x : 0.2f * x; }
__device__ __forceinline__ float elu(float x)   { return x > 0.f ? x : expm1f(x); }
__device__ __forceinline__ float wexp(float x)  { return __expf(fminf(x, 80.f)); }

// ---------------- CSR build ----------------
__global__ void init_deg_kernel() {
    int i = blockIdx.x * blockDim.x + threadIdx.x;
    if (i < NN) g_deg[i] = 1;   // self loop
}

__global__ void hist_mean_kernel(const int* __restrict__ ei, const float* __restrict__ ea) {
    __shared__ float s[256];
    float v = 0.f;
    for (int e = blockIdx.x * blockDim.x + threadIdx.x; e < EE; e += gridDim.x * blockDim.x) {
        atomicAdd(&g_deg[ei[EE + e]], 1);
        v += ea[e];
    }
    s[threadIdx.x] = v; __syncthreads();
    for (int o = 128; o > 0; o >>= 1) {
        if (threadIdx.x < o) s[threadIdx.x] += s[threadIdx.x + o];
        __syncthreads();
    }
    if (threadIdx.x == 0) g_partial[blockIdx.x] = s[0];
}

__global__ void mean_fin_kernel(const float* __restrict__ We1, const float* __restrict__ ae1,
                                const float* __restrict__ We2, const float* __restrict__ ae2) {
    __shared__ float s[512];
    int t = threadIdx.x;
    s[t] = g_partial[t]; __syncthreads();
    for (int o = 256; o > 0; o >>= 1) {
        if (t < o) s[t] += s[t + o];
        __syncthreads();
    }
    if (t == 0) g_mean = s[0] / (float)EE;
    if (t < H1) {
        float k = 0.f;
        for (int c = 0; c < C1; c++) k += We1[t * C1 + c] * ae1[t * C1 + c];
        g_k1v[t] = k;
    }
    if (t == H1) {
        float k = 0.f;
        for (int c = 0; c < C1; c++) k += We2[c] * ae2[c];
        g_k2 = k;
    }
}

// ---- 3-phase parallel scan ----
__global__ void scan_part_kernel() {
    __shared__ int s[256];
    int t = threadIdx.x, b = blockIdx.x;
    int i = b * 256 + t;
    int v = (i < NN) ? g_deg[i] : 0;
    s[t] = v; __syncthreads();
    for (int o = 128; o > 0; o >>= 1) {
        if (t < o) s[t] += s[t + o];
        __syncthreads();
    }
    if (t == 0) g_bsum[b] = s[0];
}

__global__ void scan_mid_kernel() {
    __shared__ int s[256];
    int t = threadIdx.x;
    int v = (t < NB) ? g_bsum[t] : 0;
    s[t] = v; __syncthreads();
    for (int o = 1; o < 256; o <<= 1) {
        int u = (t >= o) ? s[t - o] : 0;
        __syncthreads();
        s[t] += u;
        __syncthreads();
    }
    if (t < NB) g_boff[t] = s[t] - v;   // exclusive
}

__global__ void scan_fin_kernel() {
    __shared__ int s[256];
    int t = threadIdx.x, b = blockIdx.x;
    int i = b * 256 + t;
    int v = (i < NN) ? g_deg[i] : 0;
    s[t] = v; __syncthreads();
    for (int o = 1; o < 256; o <<= 1) {
        int u = (t >= o) ? s[t - o] : 0;
        __syncthreads();
        s[t] += u;
        __syncthreads();
    }
    int excl = s[t] - v + g_boff[b];
    if (i < NN) { g_rowptr[i] = excl; g_cursor[i] = excl; }
    if (b == 0 && t == 0) g_rowptr[NN] = ET;
}

// ---------------- GEMM1: [NN,256] @ [256,128], BM=128/TM=8 (R4-proven), f32x2 ----
__global__ void sgemm1_kernel(const float* __restrict__ A, const float* __restrict__ B) {
    const int K = INC, Nn = HC;
    __shared__ float As[8][128];
    __shared__ float Bs[8][128];
    int tid  = threadIdx.x;
    int brow = blockIdx.x;
    int trow = (tid / 16) * 8;
    int tcol = (tid % 16) * 8;
    int rowA = tid / 2,  colA = (tid % 2) * 4;
    int rowB = tid / 32, colB = (tid % 32) * 4;
    int ag = brow * 128 + rowA;

    ull acc2[4][8];
#pragma unroll
    for (int p = 0; p < 4; p++)
#pragma unroll
        for (int j = 0; j < 8; j++) acc2[p][j] = 0ULL;

    for (int k0 = 0; k0 < K; k0 += 8) {
        float4 av = make_float4(0.f, 0.f, 0.f, 0.f);
        if (ag < NN) av = *(const float4*)(A + (size_t)ag * K + k0 + colA);
        As[colA + 0][rowA] = av.x;
        As[colA + 1][rowA] = av.y;
        As[colA + 2][rowA] = av.z;
        As[colA + 3][rowA] = av.w;
        float4 bv = *(const float4*)(B + (size_t)(k0 + rowB) * Nn + colB);
        *(float4*)(&Bs[rowB][colB]) = bv;
        __syncthreads();
#pragma unroll
        for (int kk = 0; kk < 8; kk++) {
            ull ar2[4];
#pragma unroll
            for (int p = 0; p < 4; p++) {
                float2 a2 = *(const float2*)(&As[kk][trow + 2 * p]);
                ar2[p] = pack2(a2.x, a2.y);
            }
            ull br2[8];
#pragma unroll
            for (int j = 0; j < 8; j++) {
                float b = Bs[kk][tcol + j];
                br2[j] = pack2(b, b);
            }
#pragma unroll
            for (int p = 0; p < 4; p++)
#pragma unroll
                for (int j = 0; j < 8; j++) fma2(acc2[p][j], ar2[p], br2[j]);
        }
        __syncthreads();
    }
#pragma unroll
    for (int p = 0; p < 4; p++) {
        float c0[8], c1[8];
#pragma unroll
        for (int j = 0; j < 8; j++) {
            float2 v = unpack2(acc2[p][j]);
            c0[j] = v.x; c1[j] = v.y;
        }
        int r = brow * 128 + trow + 2 * p;
        if (r < NN) {
            float* cp = g_xs1 + (size_t)r * Nn + tcol;
            *(float4*)(cp)     = make_float4(c0[0], c0[1], c0[2], c0[3]);
            *(float4*)(cp + 4) = make_float4(c0[4], c0[5], c0[6], c0[7]);
        }
        if (r + 1 < NN) {
            float* cp = g_xs1 + (size_t)(r + 1) * Nn + tcol;
            *(float4*)(cp)     = make_float4(c1[0], c1[1], c1[2], c1[3]);
            *(float4*)(cp + 4) = make_float4(c1[4], c1[5], c1[6], c1[7]);
        }
    }
}

// ---------------- attention coefficients (layer 1), float4 ----------------
__global__ void al1_kernel(const float* __restrict__ as1, const float* __restrict__ ad1) {
    int idx = blockIdx.x * blockDim.x + threadIdx.x;
    if (idx >= NN * H1) return;
    int n = idx >> 2, h = idx & 3;
    const float4* xp = (const float4*)(g_xs1 + (size_t)n * HC + h * C1);
    const float4* ap = (const float4*)(as1 + h * C1);
    const float4* dp = (const float4*)(ad1 + h * C1);
    float s = 0.f, d = 0.f;
#pragma unroll
    for (int c = 0; c < 8; c++) {
        float4 v = xp[c], a = ap[c], b = dp[c];
        s += v.x * a.x + v.y * a.y + v.z * a.z + v.w * a.w;
        d += v.x * b.x + v.y * b.y + v.z * b.z + v.w * b.w;
    }
    g_als1[idx] = s;
    g_ald1[idx] = d;
}

// ---------------- scatter + fused layer-1 softmax weights ----------------
__global__ void scatter_fused_kernel(const int* __restrict__ ei, const float* __restrict__ ea) {
    float mn = g_mean;
    float k0 = g_k1v[0], k1 = g_k1v[1], k2 = g_k1v[2], k3 = g_k1v[3];
    for (int idx = blockIdx.x * blockDim.x + threadIdx.x; idx < ET; idx += gridDim.x * blockDim.x) {
        int srcn, dstn; float eav;
        if (idx < EE) {
            srcn = ei[idx];
            dstn = ei[EE + idx];
            eav  = ea[idx];
        } else {
            srcn = dstn = idx - EE;
            eav  = mn;
        }
        int slot = atomicAdd(&g_cursor[dstn], 1);
        float4 als = *(const float4*)(g_als1 + srcn * 4);
        float4 ald = *(const float4*)(g_ald1 + dstn * 4);
        float4 w;
        w.x = wexp(leaky(als.x + ald.x + k0 * eav));
        w.y = wexp(leaky(als.y + ald.y + k1 * eav));
        w.z = wexp(leaky(als.z + ald.z + k2 * eav));
        w.w = wexp(leaky(als.w + ald.w + k3 * eav));
        float4 meta = make_float4(__int_as_float(srcn), __int_as_float(dstn), eav, 0.f);
        float4* sp = (float4*)&g_slot[slot];
        sp[0] = w;
        sp[1] = meta;
    }
}

// ---------------- agg1: warp per node, all 4 heads; fused bias+bn+elu ----------------
__global__ void agg1_kernel(const float* __restrict__ b1, const float* __restrict__ g1,
                            const float* __restrict__ be1) {
    int n    = (blockIdx.x * blockDim.x + threadIdx.x) >> 5;
    int lane = threadIdx.x & 31;
    if (n >= NN) return;
    int beg = g_rowptr[n], end = g_rowptr[n + 1];

    float acc0 = 0.f, acc1 = 0.f, acc2 = 0.f, acc3 = 0.f;
    float den0 = 0.f, den1 = 0.f, den2 = 0.f, den3 = 0.f;
    int e = beg;
    for (; e + 2 <= end; e += 2) {
        float4 wA = *(const float4*)&g_slot[e];
        float4 wB = *(const float4*)&g_slot[e + 1];
        int sA = ((const int*)&g_slot[e])[4];
        int sB = ((const int*)&g_slot[e + 1])[4];
        const float* xA = g_xs1 + (size_t)sA * HC + lane;
        const float* xB = g_xs1 + (size_t)sB * HC + lane;
        float a0 = xA[0], a1 = xA[32], a2 = xA[64], a3 = xA[96];
        float c0 = xB[0], c1 = xB[32], c2 = xB[64], c3 = xB[96];
        acc0 += wA.x * a0 + wB.x * c0;
        acc1 += wA.y * a1 + wB.y * c1;
        acc2 += wA.z * a2 + wB.z * c2;
        acc3 += wA.w * a3 + wB.w * c3;
        den0 += wA.x + wB.x;
        den1 += wA.y + wB.y;
        den2 += wA.z + wB.z;
        den3 += wA.w + wB.w;
    }
    for (; e < end; ++e) {
        float4 w = *(const float4*)&g_slot[e];
        int s = ((const int*)&g_slot[e])[4];
        const float* xr = g_xs1 + (size_t)s * HC + lane;
        acc0 += w.x * xr[0];  den0 += w.x;
        acc1 += w.y * xr[32]; den1 += w.y;
        acc2 += w.z * xr[64]; den2 += w.z;
        acc3 += w.w * xr[96]; den3 += w.w;
    }
    float inv = rsqrtf(1.f + BN_EPS);
    float* op = g_out1 + (size_t)n * HC + lane;
#pragma unroll
    for (int h = 0; h < 4; h++) {
        float a = (h == 0) ? acc0 : (h == 1) ? acc1 : (h == 2) ? acc2 : acc3;
        float d = (h == 0) ? den0 : (h == 1) ? den1 : (h == 2) ? den2 : den3;
        int c = h * 32 + lane;
        float v = a / (d + 1e-16f) + b1[c];
        v = v * (g1[c] * inv) + be1[c];
        op[h * 32] = elu(v);
    }
}

// ---------------- GEMM2 + fused al2 ----------------
__global__ void gemm2_kernel(const float* __restrict__ W2, const float* __restrict__ as2,
                             const float* __restrict__ ad2) {
    __shared__ float Ws[HC * C1];
    for (int i = threadIdx.x; i < HC * C1; i += blockDim.x) Ws[i] = W2[i];
    __syncthreads();
    int node = blockIdx.x * 8 + threadIdx.x / 32;
    int lane = threadIdx.x & 31;
    if (node >= NN) return;
    const float* row = g_out1 + (size_t)node * HC;
    float s = 0.f;
#pragma unroll 8
    for (int k = 0; k < HC; k++) s += row[k] * Ws[k * C1 + lane];
    g_xs2[(size_t)node * C1 + lane] = s;

    float ps = s * as2[lane];
    float pd = s * ad2[lane];
#pragma unroll
    for (int off = 16; off > 0; off >>= 1) {
        ps += __shfl_xor_sync(0xffffffffu, ps, off);
        pd += __shfl_xor_sync(0xffffffffu, pd, off);
    }
    if (lane == 0) { g_als2[node] = ps; g_ald2[node] = pd; }
}

// ---------------- layer-2 softmax weights (slot-parallel) ----------------
__global__ void logits2_kernel() {
    float k2 = g_k2;
    for (int e = blockIdx.x * blockDim.x + threadIdx.x; e < ET; e += gridDim.x * blockDim.x) {
        float4 meta = ((const float4*)&g_slot[e])[1];
        int src = __float_as_int(meta.x);
        int dst = __float_as_int(meta.y);
        float l = leaky(g_als2[src] + g_ald2[dst] + k2 * meta.z);
        g_w2[e] = wexp(l);
    }
}

// ---------------- agg2: warp/node + fused bn+elu + heads ----------------
__global__ void agg2_heads_kernel(const float* __restrict__ b2, const float* __restrict__ g2,
                                  const float* __restrict__ be2,
                                  const float* __restrict__ Wc1, const float* __restrict__ bc1,
                                  const float* __restrict__ Wc2, const float* __restrict__ bc2,
                                  const float* __restrict__ Wr1, const float* __restrict__ br1,
                                  const float* __restrict__ Wr2, const float* __restrict__ br2,
                                  float* __restrict__ out) {
    __shared__ float sWc1[C1 * 16], sWr1[C1 * 16];
    __shared__ float sWc2[32], sWr2[16];
    __shared__ float sbc1[16], sbr1[16], sbc2[2], sbr2v[1];
    __shared__ float sh[8][32];
    int t = threadIdx.x;
    for (int i = t; i < C1 * 16; i += blockDim.x) { sWc1[i] = Wc1[i]; sWr1[i] = Wr1[i]; }
    if (t < 32) sWc2[t] = Wc2[t];
    if (t < 16) { sWr2[t] = Wr2[t]; sbc1[t] = bc1[t]; sbr1[t] = br1[t]; }
    if (t < 2)  sbc2[t] = bc2[t];
    if (t == 32) sbr2v[0] = br2[0];
    __syncthreads();

    int wi   = t >> 5;
    int lane = t & 31;
    int n    = blockIdx.x * 8 + wi;
    if (n >= NN) return;
    int beg = g_rowptr[n], end = g_rowptr[n + 1];

    float den = 0.f, acc = 0.f;
    int e = beg;
    for (; e + 2 <= end; e += 2) {
        float wA = g_w2[e], wB = g_w2[e + 1];
        int sA = ((const int*)&g_slot[e])[4];
        int sB = ((const int*)&g_slot[e + 1])[4];
        float xA = g_xs2[(size_t)sA * C1 + lane];
        float xB = g_xs2[(size_t)sB * C1 + lane];
        acc += wA * xA + wB * xB;
        den += wA + wB;
    }
    for (; e < end; ++e) {
        float w = g_w2[e];
        int s = ((const int*)&g_slot[e])[4];
        acc += w * g_xs2[(size_t)s * C1 + lane];
        den += w;
    }
    float v = acc / (den + 1e-16f) + b2[lane];
    v = v * (g2[lane] * rsqrtf(1.f + BN_EPS)) + be2[lane];
    float h = elu(v);
    out[3 * NN + (size_t)n * C1 + lane] = h;
    sh[wi][lane] = h;
    __syncwarp();

    int j = lane & 15;
    const float* W = (lane < 16) ? sWc1 : sWr1;
    float tt = (lane < 16) ? sbc1[j] : sbr1[j];
#pragma unroll
    for (int c = 0; c < C1; c++) tt += sh[wi][c] * W[c * 16 + j];
    tt = fmaxf(tt, 0.f);
    float pa = (lane < 16) ? tt * sWc2[j * 2 + 0] : tt * sWr2[j];
    float pb = (lane < 16) ? tt * sWc2[j * 2 + 1] : 0.f;
#pragma unroll
    for (int off = 8; off > 0; off >>= 1) {
        pa += __shfl_xor_sync(0xffffffffu, pa, off);
        pb += __shfl_xor_sync(0xffffffffu, pb, off);
    }
    if (lane == 0) {
        out[(size_t)n * 2 + 0] = pa + sbc2[0];
        out[(size_t)n * 2 + 1] = pb + sbc2[1];
    }
    if (lane == 16) {
        out[2 * NN + n] = pa + sbr2v[0];
    }
}

// ---------------- launch (stream-forked graph) ----------------
extern "C" void kernel_launch(void* const* d_in, const int* in_sizes, int n_in,
                              void* d_out, int out_size) {
    const float* x   = (const float*)d_in[0];
    const int*   ei  = (const int*)d_in[1];     // int32 (JAX x64 disabled)
    const float* ea  = (const float*)d_in[2];
    const float* W1  = (const float*)d_in[3];
    const float* as1 = (const float*)d_in[4];
    const float* ad1 = (const float*)d_in[5];
    const float* We1 = (const float*)d_in[6];
    const float* ae1 = (const float*)d_in[7];
    const float* b1  = (const float*)d_in[8];
    const float* g1  = (const float*)d_in[9];
    const float* be1 = (const float*)d_in[10];
    const float* W2  = (const float*)d_in[11];
    const float* as2 = (const float*)d_in[12];
    const float* ad2 = (const float*)d_in[13];
    const float* We2 = (const float*)d_in[14];
    const float* ae2 = (const float*)d_in[15];
    const float* b2  = (const float*)d_in[16];
    const float* g2  = (const float*)d_in[17];
    const float* be2 = (const float*)d_in[18];
    const float* Wc1 = (const float*)d_in[19];
    const float* bc1 = (const float*)d_in[20];
    const float* Wc2 = (const float*)d_in[21];
    const float* bc2 = (const float*)d_in[22];
    const float* Wr1 = (const float*)d_in[23];
    const float* br1 = (const float*)d_in[24];
    const float* Wr2 = (const float*)d_in[25];
    const float* br2 = (const float*)d_in[26];
    float* out = (float*)d_out;

    // Fork a side branch for the CSR build (independent of GEMM1 chain).
    cudaStream_t sB;
    cudaStreamCreateWithFlags(&sB, cudaStreamNonBlocking);
    cudaEvent_t eFork, eJoin;
    cudaEventCreateWithFlags(&eFork, cudaEventDisableTiming);
    cudaEventCreateWithFlags(&eJoin, cudaEventDisableTiming);

    cudaEventRecord(eFork, 0);
    cudaStreamWaitEvent(sB, eFork, 0);

    // Branch B (CSR)
    init_deg_kernel<<<(NN + 255) / 256, 256, 0, sB>>>();           // 0
    hist_mean_kernel<<<512, 256, 0, sB>>>(ei, ea);                 // 1
    mean_fin_kernel<<<1, 512, 0, sB>>>(We1, ae1, We2, ae2);        // 2
    // Branch A (GEMM1): launch 3 = profiled slot
    sgemm1_kernel<<<(NN + 127) / 128, 256>>>(x, W1);               // 3 <- profiled
    al1_kernel<<<(NN * H1 + 255) / 256, 256>>>(as1, ad1);          // 4
    scan_part_kernel<<<NB, 256, 0, sB>>>();                        // 5
    scan_mid_kernel<<<1, 256, 0, sB>>>();                          // 6
    scan_fin_kernel<<<NB, 256, 0, sB>>>();                         // 7

    cudaEventRecord(eJoin, sB);
    cudaStreamWaitEvent(0, eJoin, 0);

    // Joined tail on main stream
    scatter_fused_kernel<<<2048, 256>>>(ei, ea);                   // 8
    agg1_kernel<<<(NN + 7) / 8, 256>>>(b1, g1, be1);               // 9
    gemm2_kernel<<<(NN + 7) / 8, 256>>>(W2, as2, ad2);             // 10
    logits2_kernel<<<2048, 256>>>();                               // 11
    agg2_heads_kernel<<<(NN + 7) / 8, 256>>>(b2, g2, be2,
        Wc1, bc1, Wc2, bc2, Wr1, br1, Wr2, br2, out);              // 12

    cudaEventDestroy(eFork);
    cudaEventDestroy(eJoin);
    // sB intentionally not destroyed during capture.
}

// round 8
// speedup vs baseline: 1.1529x; 1.0205x over previous
#include <cuda_runtime.h>
#include <cuda_fp16.h>
#include <math.h>

#define NN   50000
#define EE   1600000
#define ET   (EE + NN)
#define INC  256
#define HC   128
#define H1   4
#define C1   32
#define BN_EPS 1e-5f
#define NB   196            // ceil(NN/256)

typedef unsigned long long ull;

// ---------------- scratch ----------------
struct __align__(32) Slot { float w0, w1, w2, w3; int src; int dst; float ea; float pad; };

__device__ float  g_xs1 [NN * HC];
__device__ __half g_xs1h[NN * HC];    // fp16 mirror for agg1 gathers
__device__ float  g_out1[NN * HC];
__device__ float  g_xs2 [NN * C1];
__device__ __half g_xs2h[NN * C1];    // fp16 mirror for agg2 gathers
__device__ float  g_als1[NN * H1];
__device__ float  g_ald1[NN * H1];
__device__ float  g_als2[NN];
__device__ float  g_ald2[NN];
__device__ float  g_w2  [ET];
__device__ int    g_deg   [NN];
__device__ int    g_rowptr[NN + 1];
__device__ int    g_cursor[NN];
__device__ int    g_bsum[NB];
__device__ int    g_boff[NB];
__device__ Slot   g_slot[ET];
__device__ float  g_partial[512];
__device__ float  g_mean;
__device__ float  g_k1v[H1];
__device__ float  g_k2;

// ---------------- helpers ----------------
__device__ __forceinline__ void fma2(ull &d, ull a, ull b) {
    asm("fma.rn.f32x2 %0, %1, %2, %0;" : "+l"(d) : "l"(a), "l"(b));
}
__device__ __forceinline__ ull pack2(float x, float y) {
    ull r; asm("mov.b64 %0, {%1, %2};" : "=l"(r) : "f"(x), "f"(y)); return r;
}
__device__ __forceinline__ float2 unpack2(ull v) {
    float2 f; asm("mov.b64 {%0, %1}, %2;" : "=f"(f.x), "=f"(f.y) : "l"(v)); return f;
}
__device__ __forceinline__ unsigned h2u(__half2 h) { return *(unsigned*)&h; }

__device__ __forceinline__ float leaky(float x) { return x > 0.f ? x : 0.2f * x; }
__device__ __forceinline__ float elu(float x)   { return x > 0.f ? x : expm1f(x); }
__device__ __forceinline__ float wexp(float x)  { return __expf(fminf(x, 80.f)); }

// ---------------- CSR build ----------------
__global__ void init_deg_kernel() {
    int i = blockIdx.x * blockDim.x + threadIdx.x;
    if (i < NN) g_deg[i] = 1;   // self loop
}

__global__ void hist_mean_kernel(const int* __restrict__ ei, const float* __restrict__ ea) {
    __shared__ float s[256];
    float v = 0.f;
    for (int e = blockIdx.x * blockDim.x + threadIdx.x; e < EE; e += gridDim.x * blockDim.x) {
        atomicAdd(&g_deg[ei[EE + e]], 1);
        v += ea[e];
    }
    s[threadIdx.x] = v; __syncthreads();
    for (int o = 128; o > 0; o >>= 1) {
        if (threadIdx.x < o) s[threadIdx.x] += s[threadIdx.x + o];
        __syncthreads();
    }
    if (threadIdx.x == 0) g_partial[blockIdx.x] = s[0];
}

__global__ void mean_fin_kernel(const float* __restrict__ We1, const float* __restrict__ ae1,
                                const float* __restrict__ We2, const float* __restrict__ ae2) {
    __shared__ float s[512];
    int t = threadIdx.x;
    s[t] = g_partial[t]; __syncthreads();
    for (int o = 256; o > 0; o >>= 1) {
        if (t < o) s[t] += s[t + o];
        __syncthreads();
    }
    if (t == 0) g_mean = s[0] / (float)EE;
    if (t < H1) {
        float k = 0.f;
        for (int c = 0; c < C1; c++) k += We1[t * C1 + c] * ae1[t * C1 + c];
        g_k1v[t] = k;
    }
    if (t == H1) {
        float k = 0.f;
        for (int c = 0; c < C1; c++) k += We2[c] * ae2[c];
        g_k2 = k;
    }
}

// ---- 3-phase parallel scan ----
__global__ void scan_part_kernel() {
    __shared__ int s[256];
    int t = threadIdx.x, b = blockIdx.x;
    int i = b * 256 + t;
    int v = (i < NN) ? g_deg[i] : 0;
    s[t] = v; __syncthreads();
    for (int o = 128; o > 0; o >>= 1) {
        if (t < o) s[t] += s[t + o];
        __syncthreads();
    }
    if (t == 0) g_bsum[b] = s[0];
}

__global__ void scan_mid_kernel() {
    __shared__ int s[256];
    int t = threadIdx.x;
    int v = (t < NB) ? g_bsum[t] : 0;
    s[t] = v; __syncthreads();
    for (int o = 1; o < 256; o <<= 1) {
        int u = (t >= o) ? s[t - o] : 0;
        __syncthreads();
        s[t] += u;
        __syncthreads();
    }
    if (t < NB) g_boff[t] = s[t] - v;   // exclusive
}

__global__ void scan_fin_kernel() {
    __shared__ int s[256];
    int t = threadIdx.x, b = blockIdx.x;
    int i = b * 256 + t;
    int v = (i < NN) ? g_deg[i] : 0;
    s[t] = v; __syncthreads();
    for (int o = 1; o < 256; o <<= 1) {
        int u = (t >= o) ? s[t - o] : 0;
        __syncthreads();
        s[t] += u;
        __syncthreads();
    }
    int excl = s[t] - v + g_boff[b];
    if (i < NN) { g_rowptr[i] = excl; g_cursor[i] = excl; }
    if (b == 0 && t == 0) g_rowptr[NN] = ET;
}

// ---------------- GEMM1: [NN,256]@[256,128], BM=128/TM=8, double-buffered ----------
__global__ void __launch_bounds__(256, 2) sgemm1_kernel(const float* __restrict__ A,
                                                        const float* __restrict__ B) {
    const int K = INC, Nn = HC;
    __shared__ float As[2][8][128];
    __shared__ float Bs[2][8][128];
    int tid  = threadIdx.x;
    int brow = blockIdx.x;
    int trow = (tid / 16) * 8;
    int tcol = (tid % 16) * 8;
    int rowA = tid / 2,  colA = (tid % 2) * 4;
    int rowB = tid / 32, colB = (tid % 32) * 4;
    int ag = brow * 128 + rowA;
    bool inA = (ag < NN);

    ull acc2[4][8];
#pragma unroll
    for (int p = 0; p < 4; p++)
#pragma unroll
        for (int j = 0; j < 8; j++) acc2[p][j] = 0ULL;

    // preload tile 0
    float4 av = make_float4(0.f, 0.f, 0.f, 0.f);
    if (inA) av = *(const float4*)(A + (size_t)ag * K + colA);
    float4 bv = *(const float4*)(B + (size_t)rowB * Nn + colB);
    As[0][colA + 0][rowA] = av.x;
    As[0][colA + 1][rowA] = av.y;
    As[0][colA + 2][rowA] = av.z;
    As[0][colA + 3][rowA] = av.w;
    *(float4*)(&Bs[0][rowB][colB]) = bv;
    __syncthreads();

    int cur = 0;
    for (int k0 = 0; k0 < K; k0 += 8) {
        bool has = (k0 + 8 < K);
        float4 av2 = make_float4(0.f, 0.f, 0.f, 0.f), bv2;
        if (has) {
            if (inA) av2 = *(const float4*)(A + (size_t)ag * K + k0 + 8 + colA);
            bv2 = *(const float4*)(B + (size_t)(k0 + 8 + rowB) * Nn + colB);
        }
#pragma unroll
        for (int kk = 0; kk < 8; kk++) {
            ull ar2[4];
#pragma unroll
            for (int p = 0; p < 4; p++) {
                float2 a2 = *(const float2*)(&As[cur][kk][trow + 2 * p]);
                ar2[p] = pack2(a2.x, a2.y);
            }
            ull br2[8];
#pragma unroll
            for (int j = 0; j < 8; j++) {
                float b = Bs[cur][kk][tcol + j];
                br2[j] = pack2(b, b);
            }
#pragma unroll
            for (int p = 0; p < 4; p++)
#pragma unroll
                for (int j = 0; j < 8; j++) fma2(acc2[p][j], ar2[p], br2[j]);
        }
        if (has) {
            int nxt = cur ^ 1;
            As[nxt][colA + 0][rowA] = av2.x;
            As[nxt][colA + 1][rowA] = av2.y;
            As[nxt][colA + 2][rowA] = av2.z;
            As[nxt][colA + 3][rowA] = av2.w;
            *(float4*)(&Bs[nxt][rowB][colB]) = bv2;
        }
        __syncthreads();
        cur ^= 1;
    }

#pragma unroll
    for (int p = 0; p < 4; p++) {
        float c0[8], c1[8];
#pragma unroll
        for (int j = 0; j < 8; j++) {
            float2 v = unpack2(acc2[p][j]);
            c0[j] = v.x; c1[j] = v.y;
        }
        int r = brow * 128 + trow + 2 * p;
        if (r < NN) {
            float* cp = g_xs1 + (size_t)r * Nn + tcol;
            *(float4*)(cp)     = make_float4(c0[0], c0[1], c0[2], c0[3]);
            *(float4*)(cp + 4) = make_float4(c0[4], c0[5], c0[6], c0[7]);
            uint4 u;
            u.x = h2u(__floats2half2_rn(c0[0], c0[1]));
            u.y = h2u(__floats2half2_rn(c0[2], c0[3]));
            u.z = h2u(__floats2half2_rn(c0[4], c0[5]));
            u.w = h2u(__floats2half2_rn(c0[6], c0[7]));
            *(uint4*)(g_xs1h + (size_t)r * Nn + tcol) = u;
        }
        if (r + 1 < NN) {
            float* cp = g_xs1 + (size_t)(r + 1) * Nn + tcol;
            *(float4*)(cp)     = make_float4(c1[0], c1[1], c1[2], c1[3]);
            *(float4*)(cp + 4) = make_float4(c1[4], c1[5], c1[6], c1[7]);
            uint4 u;
            u.x = h2u(__floats2half2_rn(c1[0], c1[1]));
            u.y = h2u(__floats2half2_rn(c1[2], c1[3]));
            u.z = h2u(__floats2half2_rn(c1[4], c1[5]));
            u.w = h2u(__floats2half2_rn(c1[6], c1[7]));
            *(uint4*)(g_xs1h + (size_t)(r + 1) * Nn + tcol) = u;
        }
    }
}

// ---------------- attention coefficients (layer 1), float4 ----------------
__global__ void al1_kernel(const float* __restrict__ as1, const float* __restrict__ ad1) {
    int idx = blockIdx.x * blockDim.x + threadIdx.x;
    if (idx >= NN * H1) return;
    int n = idx >> 2, h = idx & 3;
    const float4* xp = (const float4*)(g_xs1 + (size_t)n * HC + h * C1);
    const float4* ap = (const float4*)(as1 + h * C1);
    const float4* dp = (const float4*)(ad1 + h * C1);
    float s = 0.f, d = 0.f;
#pragma unroll
    for (int c = 0; c < 8; c++) {
        float4 v = xp[c], a = ap[c], b = dp[c];
        s += v.x * a.x + v.y * a.y + v.z * a.z + v.w * a.w;
        d += v.x * b.x + v.y * b.y + v.z * b.z + v.w * b.w;
    }
    g_als1[idx] = s;
    g_ald1[idx] = d;
}

// ---------------- scatter + fused layer-1 softmax weights ----------------
__global__ void scatter_fused_kernel(const int* __restrict__ ei, const float* __restrict__ ea) {
    float mn = g_mean;
    float k0 = g_k1v[0], k1 = g_k1v[1], k2 = g_k1v[2], k3 = g_k1v[3];
    for (int idx = blockIdx.x * blockDim.x + threadIdx.x; idx < ET; idx += gridDim.x * blockDim.x) {
        int srcn, dstn; float eav;
        if (idx < EE) {
            srcn = ei[idx];
            dstn = ei[EE + idx];
            eav  = ea[idx];
        } else {
            srcn = dstn = idx - EE;
            eav  = mn;
        }
        int slot = atomicAdd(&g_cursor[dstn], 1);
        float4 als = *(const float4*)(g_als1 + srcn * 4);
        float4 ald = *(const float4*)(g_ald1 + dstn * 4);
        float4 w;
        w.x = wexp(leaky(als.x + ald.x + k0 * eav));
        w.y = wexp(leaky(als.y + ald.y + k1 * eav));
        w.z = wexp(leaky(als.z + ald.z + k2 * eav));
        w.w = wexp(leaky(als.w + ald.w + k3 * eav));
        float4 meta = make_float4(__int_as_float(srcn), __int_as_float(dstn), eav, 0.f);
        float4* sp = (float4*)&g_slot[slot];
        sp[0] = w;
        sp[1] = meta;
    }
}

// ---------------- agg1: warp/node, fp16 gathers, fused bias+bn+elu ----------------
__global__ void agg1_kernel(const float* __restrict__ b1, const float* __restrict__ g1,
                            const float* __restrict__ be1) {
    int n    = (blockIdx.x * blockDim.x + threadIdx.x) >> 5;
    int lane = threadIdx.x & 31;
    if (n >= NN) return;
    int beg = g_rowptr[n], end = g_rowptr[n + 1];

    float acc0 = 0.f, acc1 = 0.f, acc2 = 0.f, acc3 = 0.f;
    float den0 = 0.f, den1 = 0.f, den2 = 0.f, den3 = 0.f;
    int e = beg;
    for (; e + 2 <= end; e += 2) {
        float4 wA = *(const float4*)&g_slot[e];
        float4 wB = *(const float4*)&g_slot[e + 1];
        int sA = ((const int*)&g_slot[e])[4];
        int sB = ((const int*)&g_slot[e + 1])[4];
        const __half* xA = g_xs1h + (size_t)sA * HC + lane;
        const __half* xB = g_xs1h + (size_t)sB * HC + lane;
        float a0 = __half2float(xA[0]),  a1 = __half2float(xA[32]);
        float a2 = __half2float(xA[64]), a3 = __half2float(xA[96]);
        float c0 = __half2float(xB[0]),  c1 = __half2float(xB[32]);
        float c2 = __half2float(xB[64]), c3 = __half2float(xB[96]);
        acc0 += wA.x * a0 + wB.x * c0;
        acc1 += wA.y * a1 + wB.y * c1;
        acc2 += wA.z * a2 + wB.z * c2;
        acc3 += wA.w * a3 + wB.w * c3;
        den0 += wA.x + wB.x;
        den1 += wA.y + wB.y;
        den2 += wA.z + wB.z;
        den3 += wA.w + wB.w;
    }
    for (; e < end; ++e) {
        float4 w = *(const float4*)&g_slot[e];
        int s = ((const int*)&g_slot[e])[4];
        const __half* xr = g_xs1h + (size_t)s * HC + lane;
        acc0 += w.x * __half2float(xr[0]);  den0 += w.x;
        acc1 += w.y * __half2float(xr[32]); den1 += w.y;
        acc2 += w.z * __half2float(xr[64]); den2 += w.z;
        acc3 += w.w * __half2float(xr[96]); den3 += w.w;
    }
    float inv = rsqrtf(1.f + BN_EPS);
    float* op = g_out1 + (size_t)n * HC + lane;
#pragma unroll
    for (int h = 0; h < 4; h++) {
        float a = (h == 0) ? acc0 : (h == 1) ? acc1 : (h == 2) ? acc2 : acc3;
        float d = (h == 0) ? den0 : (h == 1) ? den1 : (h == 2) ? den2 : den3;
        int c = h * 32 + lane;
        float v = a / (d + 1e-16f) + b1[c];
        v = v * (g1[c] * inv) + be1[c];
        op[h * 32] = elu(v);
    }
}

// ---------------- GEMM2 + fused al2 ----------------
__global__ void gemm2_kernel(const float* __restrict__ W2, const float* __restrict__ as2,
                             const float* __restrict__ ad2) {
    __shared__ float Ws[HC * C1];
    for (int i = threadIdx.x; i < HC * C1; i += blockDim.x) Ws[i] = W2[i];
    __syncthreads();
    int node = blockIdx.x * 8 + threadIdx.x / 32;
    int lane = threadIdx.x & 31;
    if (node >= NN) return;
    const float* row = g_out1 + (size_t)node * HC;
    float s = 0.f;
#pragma unroll 8
    for (int k = 0; k < HC; k++) s += row[k] * Ws[k * C1 + lane];
    g_xs2[(size_t)node * C1 + lane] = s;
    g_xs2h[(size_t)node * C1 + lane] = __float2half_rn(s);

    float ps = s * as2[lane];
    float pd = s * ad2[lane];
#pragma unroll
    for (int off = 16; off > 0; off >>= 1) {
        ps += __shfl_xor_sync(0xffffffffu, ps, off);
        pd += __shfl_xor_sync(0xffffffffu, pd, off);
    }
    if (lane == 0) { g_als2[node] = ps; g_ald2[node] = pd; }
}

// ---------------- layer-2 softmax weights (slot-parallel) ----------------
__global__ void logits2_kernel() {
    float k2 = g_k2;
    for (int e = blockIdx.x * blockDim.x + threadIdx.x; e < ET; e += gridDim.x * blockDim.x) {
        float4 meta = ((const float4*)&g_slot[e])[1];
        int src = __float_as_int(meta.x);
        int dst = __float_as_int(meta.y);
        float l = leaky(g_als2[src] + g_ald2[dst] + k2 * meta.z);
        g_w2[e] = wexp(l);
    }
}

// ---------------- agg2: warp/node (fp16 gathers) + fused bn+elu + heads ----------
__global__ void agg2_heads_kernel(const float* __restrict__ b2, const float* __restrict__ g2,
                                  const float* __restrict__ be2,
                                  const float* __restrict__ Wc1, const float* __restrict__ bc1,
                                  const float* __restrict__ Wc2, const float* __restrict__ bc2,
                                  const float* __restrict__ Wr1, const float* __restrict__ br1,
                                  const float* __restrict__ Wr2, const float* __restrict__ br2,
                                  float* __restrict__ out) {
    __shared__ float sWc1[C1 * 16], sWr1[C1 * 16];
    __shared__ float sWc2[32], sWr2[16];
    __shared__ float sbc1[16], sbr1[16], sbc2[2], sbr2v[1];
    __shared__ float sh[8][32];
    int t = threadIdx.x;
    for (int i = t; i < C1 * 16; i += blockDim.x) { sWc1[i] = Wc1[i]; sWr1[i] = Wr1[i]; }
    if (t < 32) sWc2[t] = Wc2[t];
    if (t < 16) { sWr2[t] = Wr2[t]; sbc1[t] = bc1[t]; sbr1[t] = br1[t]; }
    if (t < 2)  sbc2[t] = bc2[t];
    if (t == 32) sbr2v[0] = br2[0];
    __syncthreads();

    int wi   = t >> 5;
    int lane = t & 31;
    int n    = blockIdx.x * 8 + wi;
    if (n >= NN) return;
    int beg = g_rowptr[n], end = g_rowptr[n + 1];

    float den = 0.f, acc = 0.f;
    int e = beg;
    for (; e + 2 <= end; e += 2) {
        float wA = g_w2[e], wB = g_w2[e + 1];
        int sA = ((const int*)&g_slot[e])[4];
        int sB = ((const int*)&g_slot[e + 1])[4];
        float xA = __half2float(g_xs2h[(size_t)sA * C1 + lane]);
        float xB = __half2float(g_xs2h[(size_t)sB * C1 + lane]);
        acc += wA * xA + wB * xB;
        den += wA + wB;
    }
    for (; e < end; ++e) {
        float w = g_w2[e];
        int s = ((const int*)&g_slot[e])[4];
        acc += w * __half2float(g_xs2h[(size_t)s * C1 + lane]);
        den += w;
    }
    float v = acc / (den + 1e-16f) + b2[lane];
    v = v * (g2[lane] * rsqrtf(1.f + BN_EPS)) + be2[lane];
    float h = elu(v);
    out[3 * NN + (size_t)n * C1 + lane] = h;
    sh[wi][lane] = h;
    __syncwarp();

    int j = lane & 15;
    const float* W = (lane < 16) ? sWc1 : sWr1;
    float tt = (lane < 16) ? sbc1[j] : sbr1[j];
#pragma unroll
    for (int c = 0; c < C1; c++) tt += sh[wi][c] * W[c * 16 + j];
    tt = fmaxf(tt, 0.f);
    float pa = (lane < 16) ? tt * sWc2[j * 2 + 0] : tt * sWr2[j];
    float pb = (lane < 16) ? tt * sWc2[j * 2 + 1] : 0.f;
#pragma unroll
    for (int off = 8; off > 0; off >>= 1) {
        pa += __shfl_xor_sync(0xffffffffu, pa, off);
        pb += __shfl_xor_sync(0xffffffffu, pb, off);
    }
    if (lane == 0) {
        out[(size_t)n * 2 + 0] = pa + sbc2[0];
        out[(size_t)n * 2 + 1] = pb + sbc2[1];
    }
    if (lane == 16) {
        out[2 * NN + n] = pa + sbr2v[0];
    }
}

// ---------------- launch (stream-forked graph) ----------------
extern "C" void kernel_launch(void* const* d_in, const int* in_sizes, int n_in,
                              void* d_out, int out_size) {
    const float* x   = (const float*)d_in[0];
    const int*   ei  = (const int*)d_in[1];     // int32 (JAX x64 disabled)
    const float* ea  = (const float*)d_in[2];
    const float* W1  = (const float*)d_in[3];
    const float* as1 = (const float*)d_in[4];
    const float* ad1 = (const float*)d_in[5];
    const float* We1 = (const float*)d_in[6];
    const float* ae1 = (const float*)d_in[7];
    const float* b1  = (const float*)d_in[8];
    const float* g1  = (const float*)d_in[9];
    const float* be1 = (const float*)d_in[10];
    const float* W2  = (const float*)d_in[11];
    const float* as2 = (const float*)d_in[12];
    const float* ad2 = (const float*)d_in[13];
    const float* We2 = (const float*)d_in[14];
    const float* ae2 = (const float*)d_in[15];
    const float* b2  = (const float*)d_in[16];
    const float* g2  = (const float*)d_in[17];
    const float* be2 = (const float*)d_in[18];
    const float* Wc1 = (const float*)d_in[19];
    const float* bc1 = (const float*)d_in[20];
    const float* Wc2 = (const float*)d_in[21];
    const float* bc2 = (const float*)d_in[22];
    const float* Wr1 = (const float*)d_in[23];
    const float* br1 = (const float*)d_in[24];
    const float* Wr2 = (const float*)d_in[25];
    const float* br2 = (const float*)d_in[26];
    float* out = (float*)d_out;

    // Fork a side branch for the CSR build (independent of GEMM1 chain).
    cudaStream_t sB;
    cudaStreamCreateWithFlags(&sB, cudaStreamNonBlocking);
    cudaEvent_t eFork, eJoin;
    cudaEventCreateWithFlags(&eFork, cudaEventDisableTiming);
    cudaEventCreateWithFlags(&eJoin, cudaEventDisableTiming);

    cudaEventRecord(eFork, 0);
    cudaStreamWaitEvent(sB, eFork, 0);

    // Branch B (CSR)
    init_deg_kernel<<<(NN + 255) / 256, 256, 0, sB>>>();           // 0
    hist_mean_kernel<<<512, 256, 0, sB>>>(ei, ea);                 // 1
    mean_fin_kernel<<<1, 512, 0, sB>>>(We1, ae1, We2, ae2);        // 2
    // Branch A (GEMM1): launch 3 = profiled slot
    sgemm1_kernel<<<(NN + 127) / 128, 256>>>(x, W1);               // 3 <- profiled
    al1_kernel<<<(NN * H1 + 255) / 256, 256>>>(as1, ad1);          // 4
    scan_part_kernel<<<NB, 256, 0, sB>>>();                        // 5
    scan_mid_kernel<<<1, 256, 0, sB>>>();                          // 6
    scan_fin_kernel<<<NB, 256, 0, sB>>>();                         // 7

    cudaEventRecord(eJoin, sB);
    cudaStreamWaitEvent(0, eJoin, 0);

    // Joined tail on main stream
    scatter_fused_kernel<<<2048, 256>>>(ei, ea);                   // 8
    agg1_kernel<<<(NN + 7) / 8, 256>>>(b1, g1, be1);               // 9
    gemm2_kernel<<<(NN + 7) / 8, 256>>>(W2, as2, ad2);             // 10
    logits2_kernel<<<2048, 256>>>();                               // 11
    agg2_heads_kernel<<<(NN + 7) / 8, 256>>>(b2, g2, be2,
        Wc1, bc1, Wc2, bc2, Wr1, br1, Wr2, br2, out);              // 12

    cudaEventDestroy(eFork);
    cudaEventDestroy(eJoin);
    // sB intentionally not destroyed during capture.
}

// round 9
// speedup vs baseline: 1.1651x; 1.0106x over previous
#include <cuda_runtime.h>
#include <cuda_fp16.h>
#include <math.h>

#define NN   50000
#define EE   1600000
#define ET   (EE + NN)
#define INC  256
#define HC   128
#define H1   4
#define C1   32
#define BN_EPS 1e-5f
#define NB   196            // ceil(NN/256)

typedef unsigned long long ull;

// ---------------- scratch ----------------
struct __align__(32) Slot { float w0, w1, w2, w3; int src; int dst; float ea; float pad; };

__device__ float  g_xs1 [NN * HC];
__device__ __half g_xs1h[NN * HC];    // fp16 mirror for agg1 gathers
__device__ float  g_out1[NN * HC];
__device__ float  g_xs2 [NN * C1];
__device__ __half g_xs2h[NN * C1];    // fp16 mirror for agg2 gathers
__device__ float  g_als1[NN * H1];
__device__ float  g_ald1[NN * H1];
__device__ float  g_als2[NN];
__device__ float  g_ald2[NN];
__device__ float  g_w2  [ET];
__device__ int    g_deg   [NN];
__device__ int    g_rowptr[NN + 1];
__device__ int    g_cursor[NN];
__device__ int    g_bsum[NB];
__device__ int    g_boff[NB];
__device__ Slot   g_slot[ET];
__device__ float  g_partial[512];
__device__ float  g_mean;
__device__ float  g_k1v[H1];
__device__ float  g_k2;

// ---------------- helpers ----------------
__device__ __forceinline__ void fma2(ull &d, ull a, ull b) {
    asm("fma.rn.f32x2 %0, %1, %2, %0;" : "+l"(d) : "l"(a), "l"(b));
}
__device__ __forceinline__ ull pack2(float x, float y) {
    ull r; asm("mov.b64 %0, {%1, %2};" : "=l"(r) : "f"(x), "f"(y)); return r;
}
__device__ __forceinline__ float2 unpack2(ull v) {
    float2 f; asm("mov.b64 {%0, %1}, %2;" : "=f"(f.x), "=f"(f.y) : "l"(v)); return f;
}
__device__ __forceinline__ unsigned h2u(__half2 h) { return *(unsigned*)&h; }

__device__ __forceinline__ float leaky(float x) { return x > 0.f ? x : 0.2f * x; }
__device__ __forceinline__ float elu(float x)   { return x > 0.f ? x : expm1f(x); }
__device__ __forceinline__ float wexp(float x)  { return __expf(fminf(x, 80.f)); }

// ---------------- CSR build ----------------
__global__ void init_deg_kernel() {
    int i = blockIdx.x * blockDim.x + threadIdx.x;
    if (i < NN) g_deg[i] = 1;   // self loop
}

__global__ void hist_mean_kernel(const int* __restrict__ ei, const float* __restrict__ ea) {
    __shared__ float s[256];
    float v = 0.f;
    for (int e = blockIdx.x * blockDim.x + threadIdx.x; e < EE; e += gridDim.x * blockDim.x) {
        atomicAdd(&g_deg[ei[EE + e]], 1);
        v += ea[e];
    }
    s[threadIdx.x] = v; __syncthreads();
    for (int o = 128; o > 0; o >>= 1) {
        if (threadIdx.x < o) s[threadIdx.x] += s[threadIdx.x + o];
        __syncthreads();
    }
    if (threadIdx.x == 0) g_partial[blockIdx.x] = s[0];
}

__global__ void mean_fin_kernel(const float* __restrict__ We1, const float* __restrict__ ae1,
                                const float* __restrict__ We2, const float* __restrict__ ae2) {
    __shared__ float s[512];
    int t = threadIdx.x;
    s[t] = g_partial[t]; __syncthreads();
    for (int o = 256; o > 0; o >>= 1) {
        if (t < o) s[t] += s[t + o];
        __syncthreads();
    }
    if (t == 0) g_mean = s[0] / (float)EE;
    if (t < H1) {
        float k = 0.f;
        for (int c = 0; c < C1; c++) k += We1[t * C1 + c] * ae1[t * C1 + c];
        g_k1v[t] = k;
    }
    if (t == H1) {
        float k = 0.f;
        for (int c = 0; c < C1; c++) k += We2[c] * ae2[c];
        g_k2 = k;
    }
}

// ---- 3-phase parallel scan ----
__global__ void scan_part_kernel() {
    __shared__ int s[256];
    int t = threadIdx.x, b = blockIdx.x;
    int i = b * 256 + t;
    int v = (i < NN) ? g_deg[i] : 0;
    s[t] = v; __syncthreads();
    for (int o = 128; o > 0; o >>= 1) {
        if (t < o) s[t] += s[t + o];
        __syncthreads();
    }
    if (t == 0) g_bsum[b] = s[0];
}

__global__ void scan_mid_kernel() {
    __shared__ int s[256];
    int t = threadIdx.x;
    int v = (t < NB) ? g_bsum[t] : 0;
    s[t] = v; __syncthreads();
    for (int o = 1; o < 256; o <<= 1) {
        int u = (t >= o) ? s[t - o] : 0;
        __syncthreads();
        s[t] += u;
        __syncthreads();
    }
    if (t < NB) g_boff[t] = s[t] - v;   // exclusive
}

__global__ void scan_fin_kernel() {
    __shared__ int s[256];
    int t = threadIdx.x, b = blockIdx.x;
    int i = b * 256 + t;
    int v = (i < NN) ? g_deg[i] : 0;
    s[t] = v; __syncthreads();
    for (int o = 1; o < 256; o <<= 1) {
        int u = (t >= o) ? s[t - o] : 0;
        __syncthreads();
        s[t] += u;
        __syncthreads();
    }
    int excl = s[t] - v + g_boff[b];
    if (i < NN) { g_rowptr[i] = excl; g_cursor[i] = excl; }
    if (b == 0 && t == 0) g_rowptr[NN] = ET;
}

// ---------------- scatter permutation only (no weights) — runs on CSR branch ----
__global__ void scatter_perm_kernel(const int* __restrict__ ei, const float* __restrict__ ea) {
    float mn = g_mean;
    for (int idx = blockIdx.x * blockDim.x + threadIdx.x; idx < ET; idx += gridDim.x * blockDim.x) {
        int srcn, dstn; float eav;
        if (idx < EE) {
            srcn = ei[idx];
            dstn = ei[EE + idx];
            eav  = ea[idx];
        } else {
            srcn = dstn = idx - EE;
            eav  = mn;
        }
        int slot = atomicAdd(&g_cursor[dstn], 1);
        ((float4*)&g_slot[slot])[1] =
            make_float4(__int_as_float(srcn), __int_as_float(dstn), eav, 0.f);
    }
}

// ---------------- GEMM1: [NN,256]@[256,128], BM=128/TM=8, double-buffered ----------
__global__ void __launch_bounds__(256, 2) sgemm1_kernel(const float* __restrict__ A,
                                                        const float* __restrict__ B) {
    const int K = INC, Nn = HC;
    __shared__ float As[2][8][128];
    __shared__ float Bs[2][8][128];
    int tid  = threadIdx.x;
    int brow = blockIdx.x;
    int trow = (tid / 16) * 8;
    int tcol = (tid % 16) * 8;
    int rowA = tid / 2,  colA = (tid % 2) * 4;
    int rowB = tid / 32, colB = (tid % 32) * 4;
    int ag = brow * 128 + rowA;
    bool inA = (ag < NN);

    ull acc2[4][8];
#pragma unroll
    for (int p = 0; p < 4; p++)
#pragma unroll
        for (int j = 0; j < 8; j++) acc2[p][j] = 0ULL;

    float4 av = make_float4(0.f, 0.f, 0.f, 0.f);
    if (inA) av = *(const float4*)(A + (size_t)ag * K + colA);
    float4 bv = *(const float4*)(B + (size_t)rowB * Nn + colB);
    As[0][colA + 0][rowA] = av.x;
    As[0][colA + 1][rowA] = av.y;
    As[0][colA + 2][rowA] = av.z;
    As[0][colA + 3][rowA] = av.w;
    *(float4*)(&Bs[0][rowB][colB]) = bv;
    __syncthreads();

    int cur = 0;
    for (int k0 = 0; k0 < K; k0 += 8) {
        bool has = (k0 + 8 < K);
        float4 av2 = make_float4(0.f, 0.f, 0.f, 0.f), bv2;
        if (has) {
            if (inA) av2 = *(const float4*)(A + (size_t)ag * K + k0 + 8 + colA);
            bv2 = *(const float4*)(B + (size_t)(k0 + 8 + rowB) * Nn + colB);
        }
#pragma unroll
        for (int kk = 0; kk < 8; kk++) {
            ull ar2[4];
#pragma unroll
            for (int p = 0; p < 4; p++) {
                float2 a2 = *(const float2*)(&As[cur][kk][trow + 2 * p]);
                ar2[p] = pack2(a2.x, a2.y);
            }
            ull br2[8];
#pragma unroll
            for (int j = 0; j < 8; j++) {
                float b = Bs[cur][kk][tcol + j];
                br2[j] = pack2(b, b);
            }
#pragma unroll
            for (int p = 0; p < 4; p++)
#pragma unroll
                for (int j = 0; j < 8; j++) fma2(acc2[p][j], ar2[p], br2[j]);
        }
        if (has) {
            int nxt = cur ^ 1;
            As[nxt][colA + 0][rowA] = av2.x;
            As[nxt][colA + 1][rowA] = av2.y;
            As[nxt][colA + 2][rowA] = av2.z;
            As[nxt][colA + 3][rowA] = av2.w;
            *(float4*)(&Bs[nxt][rowB][colB]) = bv2;
        }
        __syncthreads();
        cur ^= 1;
    }

#pragma unroll
    for (int p = 0; p < 4; p++) {
        float c0[8], c1[8];
#pragma unroll
        for (int j = 0; j < 8; j++) {
            float2 v = unpack2(acc2[p][j]);
            c0[j] = v.x; c1[j] = v.y;
        }
        int r = brow * 128 + trow + 2 * p;
        if (r < NN) {
            float* cp = g_xs1 + (size_t)r * Nn + tcol;
            *(float4*)(cp)     = make_float4(c0[0], c0[1], c0[2], c0[3]);
            *(float4*)(cp + 4) = make_float4(c0[4], c0[5], c0[6], c0[7]);
            uint4 u;
            u.x = h2u(__floats2half2_rn(c0[0], c0[1]));
            u.y = h2u(__floats2half2_rn(c0[2], c0[3]));
            u.z = h2u(__floats2half2_rn(c0[4], c0[5]));
            u.w = h2u(__floats2half2_rn(c0[6], c0[7]));
            *(uint4*)(g_xs1h + (size_t)r * Nn + tcol) = u;
        }
        if (r + 1 < NN) {
            float* cp = g_xs1 + (size_t)(r + 1) * Nn + tcol;
            *(float4*)(cp)     = make_float4(c1[0], c1[1], c1[2], c1[3]);
            *(float4*)(cp + 4) = make_float4(c1[4], c1[5], c1[6], c1[7]);
            uint4 u;
            u.x = h2u(__floats2half2_rn(c1[0], c1[1]));
            u.y = h2u(__floats2half2_rn(c1[2], c1[3]));
            u.z = h2u(__floats2half2_rn(c1[4], c1[5]));
            u.w = h2u(__floats2half2_rn(c1[6], c1[7]));
            *(uint4*)(g_xs1h + (size_t)(r + 1) * Nn + tcol) = u;
        }
    }
}

// ---------------- attention coefficients (layer 1), float4 ----------------
__global__ void al1_kernel(const float* __restrict__ as1, const float* __restrict__ ad1) {
    int idx = blockIdx.x * blockDim.x + threadIdx.x;
    if (idx >= NN * H1) return;
    int n = idx >> 2, h = idx & 3;
    const float4* xp = (const float4*)(g_xs1 + (size_t)n * HC + h * C1);
    const float4* ap = (const float4*)(as1 + h * C1);
    const float4* dp = (const float4*)(ad1 + h * C1);
    float s = 0.f, d = 0.f;
#pragma unroll
    for (int c = 0; c < 8; c++) {
        float4 v = xp[c], a = ap[c], b = dp[c];
        s += v.x * a.x + v.y * a.y + v.z * a.z + v.w * a.w;
        d += v.x * b.x + v.y * b.y + v.z * b.z + v.w * b.w;
    }
    g_als1[idx] = s;
    g_ald1[idx] = d;
}

// ---------------- layer-1 softmax weights (slot-parallel, after join) ----------------
__global__ void logits1_kernel() {
    float k0 = g_k1v[0], k1 = g_k1v[1], k2 = g_k1v[2], k3 = g_k1v[3];
    for (int e = blockIdx.x * blockDim.x + threadIdx.x; e < ET; e += gridDim.x * blockDim.x) {
        float4 meta = ((const float4*)&g_slot[e])[1];
        int src = __float_as_int(meta.x);
        int dst = __float_as_int(meta.y);
        float eav = meta.z;
        float4 als = *(const float4*)(g_als1 + src * 4);
        float4 ald = *(const float4*)(g_ald1 + dst * 4);   // dst nearly sorted -> coalesced
        float4 w;
        w.x = wexp(leaky(als.x + ald.x + k0 * eav));
        w.y = wexp(leaky(als.y + ald.y + k1 * eav));
        w.z = wexp(leaky(als.z + ald.z + k2 * eav));
        w.w = wexp(leaky(als.w + ald.w + k3 * eav));
        ((float4*)&g_slot[e])[0] = w;
    }
}

// ---------------- agg1: warp/node, fp16 gathers, 4x unroll, fused bias+bn+elu ------
__global__ void agg1_kernel(const float* __restrict__ b1, const float* __restrict__ g1,
                            const float* __restrict__ be1) {
    int n    = (blockIdx.x * blockDim.x + threadIdx.x) >> 5;
    int lane = threadIdx.x & 31;
    if (n >= NN) return;
    int beg = g_rowptr[n], end = g_rowptr[n + 1];

    float acc0 = 0.f, acc1 = 0.f, acc2 = 0.f, acc3 = 0.f;
    float den0 = 0.f, den1 = 0.f, den2 = 0.f, den3 = 0.f;
    int e = beg;
    for (; e + 4 <= end; e += 4) {
#pragma unroll
        for (int q = 0; q < 4; q++) {
            float4 w = *(const float4*)&g_slot[e + q];
            int s = ((const int*)&g_slot[e + q])[4];
            const __half* xr = g_xs1h + (size_t)s * HC + lane;
            float x0 = __half2float(xr[0]),  x1 = __half2float(xr[32]);
            float x2 = __half2float(xr[64]), x3 = __half2float(xr[96]);
            acc0 += w.x * x0;  den0 += w.x;
            acc1 += w.y * x1;  den1 += w.y;
            acc2 += w.z * x2;  den2 += w.z;
            acc3 += w.w * x3;  den3 += w.w;
        }
    }
    for (; e < end; ++e) {
        float4 w = *(const float4*)&g_slot[e];
        int s = ((const int*)&g_slot[e])[4];
        const __half* xr = g_xs1h + (size_t)s * HC + lane;
        acc0 += w.x * __half2float(xr[0]);  den0 += w.x;
        acc1 += w.y * __half2float(xr[32]); den1 += w.y;
        acc2 += w.z * __half2float(xr[64]); den2 += w.z;
        acc3 += w.w * __half2float(xr[96]); den3 += w.w;
    }
    float inv = rsqrtf(1.f + BN_EPS);
    float* op = g_out1 + (size_t)n * HC + lane;
#pragma unroll
    for (int h = 0; h < 4; h++) {
        float a = (h == 0) ? acc0 : (h == 1) ? acc1 : (h == 2) ? acc2 : acc3;
        float d = (h == 0) ? den0 : (h == 1) ? den1 : (h == 2) ? den2 : den3;
        int c = h * 32 + lane;
        float v = a / (d + 1e-16f) + b1[c];
        v = v * (g1[c] * inv) + be1[c];
        op[h * 32] = elu(v);
    }
}

// ---------------- GEMM2 + fused al2 ----------------
__global__ void gemm2_kernel(const float* __restrict__ W2, const float* __restrict__ as2,
                             const float* __restrict__ ad2) {
    __shared__ float Ws[HC * C1];
    for (int i = threadIdx.x; i < HC * C1; i += blockDim.x) Ws[i] = W2[i];
    __syncthreads();
    int node = blockIdx.x * 8 + threadIdx.x / 32;
    int lane = threadIdx.x & 31;
    if (node >= NN) return;
    const float* row = g_out1 + (size_t)node * HC;
    float s = 0.f;
#pragma unroll 8
    for (int k = 0; k < HC; k++) s += row[k] * Ws[k * C1 + lane];
    g_xs2[(size_t)node * C1 + lane] = s;
    g_xs2h[(size_t)node * C1 + lane] = __float2half_rn(s);

    float ps = s * as2[lane];
    float pd = s * ad2[lane];
#pragma unroll
    for (int off = 16; off > 0; off >>= 1) {
        ps += __shfl_xor_sync(0xffffffffu, ps, off);
        pd += __shfl_xor_sync(0xffffffffu, pd, off);
    }
    if (lane == 0) { g_als2[node] = ps; g_ald2[node] = pd; }
}

// ---------------- layer-2 softmax weights (slot-parallel) ----------------
__global__ void logits2_kernel() {
    float k2 = g_k2;
    for (int e = blockIdx.x * blockDim.x + threadIdx.x; e < ET; e += gridDim.x * blockDim.x) {
        float4 meta = ((const float4*)&g_slot[e])[1];
        int src = __float_as_int(meta.x);
        int dst = __float_as_int(meta.y);
        float l = leaky(g_als2[src] + g_ald2[dst] + k2 * meta.z);
        g_w2[e] = wexp(l);
    }
}

// ---------------- agg2: warp/node (fp16 gathers, 4x unroll) + bn+elu + heads ------
__global__ void agg2_heads_kernel(const float* __restrict__ b2, const float* __restrict__ g2,
                                  const float* __restrict__ be2,
                                  const float* __restrict__ Wc1, const float* __restrict__ bc1,
                                  const float* __restrict__ Wc2, const float* __restrict__ bc2,
                                  const float* __restrict__ Wr1, const float* __restrict__ br1,
                                  const float* __restrict__ Wr2, const float* __restrict__ br2,
                                  float* __restrict__ out) {
    __shared__ float sWc1[C1 * 16], sWr1[C1 * 16];
    __shared__ float sWc2[32], sWr2[16];
    __shared__ float sbc1[16], sbr1[16], sbc2[2], sbr2v[1];
    __shared__ float sh[8][32];
    int t = threadIdx.x;
    for (int i = t; i < C1 * 16; i += blockDim.x) { sWc1[i] = Wc1[i]; sWr1[i] = Wr1[i]; }
    if (t < 32) sWc2[t] = Wc2[t];
    if (t < 16) { sWr2[t] = Wr2[t]; sbc1[t] = bc1[t]; sbr1[t] = br1[t]; }
    if (t < 2)  sbc2[t] = bc2[t];
    if (t == 32) sbr2v[0] = br2[0];
    __syncthreads();

    int wi   = t >> 5;
    int lane = t & 31;
    int n    = blockIdx.x * 8 + wi;
    if (n >= NN) return;
    int beg = g_rowptr[n], end = g_rowptr[n + 1];

    float den = 0.f, acc = 0.f;
    int e = beg;
    for (; e + 4 <= end; e += 4) {
#pragma unroll
        for (int q = 0; q < 4; q++) {
            float w = g_w2[e + q];
            int s = ((const int*)&g_slot[e + q])[4];
            acc += w * __half2float(g_xs2h[(size_t)s * C1 + lane]);
            den += w;
        }
    }
    for (; e < end; ++e) {
        float w = g_w2[e];
        int s = ((const int*)&g_slot[e])[4];
        acc += w * __half2float(g_xs2h[(size_t)s * C1 + lane]);
        den += w;
    }
    float v = acc / (den + 1e-16f) + b2[lane];
    v = v * (g2[lane] * rsqrtf(1.f + BN_EPS)) + be2[lane];
    float h = elu(v);
    out[3 * NN + (size_t)n * C1 + lane] = h;
    sh[wi][lane] = h;
    __syncwarp();

    int j = lane & 15;
    const float* W = (lane < 16) ? sWc1 : sWr1;
    float tt = (lane < 16) ? sbc1[j] : sbr1[j];
#pragma unroll
    for (int c = 0; c < C1; c++) tt += sh[wi][c] * W[c * 16 + j];
    tt = fmaxf(tt, 0.f);
    float pa = (lane < 16) ? tt * sWc2[j * 2 + 0] : tt * sWr2[j];
    float pb = (lane < 16) ? tt * sWc2[j * 2 + 1] : 0.f;
#pragma unroll
    for (int off = 8; off > 0; off >>= 1) {
        pa += __shfl_xor_sync(0xffffffffu, pa, off);
        pb += __shfl_xor_sync(0xffffffffu, pb, off);
    }
    if (lane == 0) {
        out[(size_t)n * 2 + 0] = pa + sbc2[0];
        out[(size_t)n * 2 + 1] = pb + sbc2[1];
    }
    if (lane == 16) {
        out[2 * NN + n] = pa + sbr2v[0];
    }
}

// ---------------- launch (stream-forked graph) ----------------
extern "C" void kernel_launch(void* const* d_in, const int* in_sizes, int n_in,
                              void* d_out, int out_size) {
    const float* x   = (const float*)d_in[0];
    const int*   ei  = (const int*)d_in[1];     // int32 (JAX x64 disabled)
    const float* ea  = (const float*)d_in[2];
    const float* W1  = (const float*)d_in[3];
    const float* as1 = (const float*)d_in[4];
    const float* ad1 = (const float*)d_in[5];
    const float* We1 = (const float*)d_in[6];
    const float* ae1 = (const float*)d_in[7];
    const float* b1  = (const float*)d_in[8];
    const float* g1  = (const float*)d_in[9];
    const float* be1 = (const float*)d_in[10];
    const float* W2  = (const float*)d_in[11];
    const float* as2 = (const float*)d_in[12];
    const float* ad2 = (const float*)d_in[13];
    const float* We2 = (const float*)d_in[14];
    const float* ae2 = (const float*)d_in[15];
    const float* b2  = (const float*)d_in[16];
    const float* g2  = (const float*)d_in[17];
    const float* be2 = (const float*)d_in[18];
    const float* Wc1 = (const float*)d_in[19];
    const float* bc1 = (const float*)d_in[20];
    const float* Wc2 = (const float*)d_in[21];
    const float* bc2 = (const float*)d_in[22];
    const float* Wr1 = (const float*)d_in[23];
    const float* br1 = (const float*)d_in[24];
    const float* Wr2 = (const float*)d_in[25];
    const float* br2 = (const float*)d_in[26];
    float* out = (float*)d_out;

    // Fork CSR+permutation branch (independent of GEMM1 chain).
    cudaStream_t sB;
    cudaStreamCreateWithFlags(&sB, cudaStreamNonBlocking);
    cudaEvent_t eFork, eJoin;
    cudaEventCreateWithFlags(&eFork, cudaEventDisableTiming);
    cudaEventCreateWithFlags(&eJoin, cudaEventDisableTiming);

    cudaEventRecord(eFork, 0);
    cudaStreamWaitEvent(sB, eFork, 0);

    // Branch B (CSR + scatter permutation)
    init_deg_kernel<<<(NN + 255) / 256, 256, 0, sB>>>();           // 0
    hist_mean_kernel<<<512, 256, 0, sB>>>(ei, ea);                 // 1
    mean_fin_kernel<<<1, 512, 0, sB>>>(We1, ae1, We2, ae2);        // 2
    // Branch A (GEMM1): launch 3 = profiled slot
    sgemm1_kernel<<<(NN + 127) / 128, 256>>>(x, W1);               // 3 <- profiled
    al1_kernel<<<(NN * H1 + 255) / 256, 256>>>(as1, ad1);          // 4
    scan_part_kernel<<<NB, 256, 0, sB>>>();                        // 5
    scan_mid_kernel<<<1, 256, 0, sB>>>();                          // 6
    scan_fin_kernel<<<NB, 256, 0, sB>>>();                         // 7
    scatter_perm_kernel<<<2048, 256, 0, sB>>>(ei, ea);             // 8

    cudaEventRecord(eJoin, sB);
    cudaStreamWaitEvent(0, eJoin, 0);

    // Joined tail on main stream
    logits1_kernel<<<2048, 256>>>();                               // 9
    agg1_kernel<<<(NN + 7) / 8, 256>>>(b1, g1, be1);               // 10
    gemm2_kernel<<<(NN + 7) / 8, 256>>>(W2, as2, ad2);             // 11
    logits2_kernel<<<2048, 256>>>();                               // 12
    agg2_heads_kernel<<<(NN + 7) / 8, 256>>>(b2, g2, be2,
        Wc1, bc1, Wc2, bc2, Wr1, br1, Wr2, br2, out);              // 13

    cudaEventDestroy(eFork);
    cudaEventDestroy(eJoin);
    // sB intentionally not destroyed during capture.
}

// round 11
// speedup vs baseline: 1.2875x; 1.1050x over previous
#include <cuda_runtime.h>
#include <cuda_fp16.h>
#include <mma.h>
#include <math.h>

using namespace nvcuda;

#define NN   50000
#define EE   1600000
#define ET   (EE + NN)
#define INC  256
#define HC   128
#define H1   4
#define C1   32
#define BN_EPS 1e-5f
#define NB   196            // ceil(NN/256)
#define NROWS 50048         // 391*128, padded rows for GEMM1 stores

// ---------------- scratch ----------------
struct __align__(32) Slot { float w0, w1, w2, w3; int src; int dst; float ea; float pad; };

__device__ __half g_xh  [NN * INC];     // fp16 x
__device__ __half g_W1h [INC * HC];     // fp16 W1
__device__ float  g_xs1 [NROWS * HC];   // fp32 GEMM1 out (padded)
__device__ __half g_xs1h[NN * HC];      // fp16 mirror for agg1 gathers
__device__ float  g_out1[NN * HC];
__device__ float  g_xs2 [NN * C1];
__device__ __half g_xs2h[NN * C1];
__device__ float  g_als1[NN * H1];
__device__ float  g_ald1[NN * H1];
__device__ float  g_als2[NN];
__device__ float  g_ald2[NN];
__device__ int    g_deg   [NN];
__device__ int    g_rowptr[NN + 1];
__device__ int    g_cursor[NN];
__device__ int    g_bsum[NB];
__device__ int    g_boff[NB];
__device__ Slot   g_slot[ET];
__device__ float  g_partial[512];
__device__ float  g_mean;
__device__ float  g_k1v[H1];
__device__ float  g_k2;

// ---------------- helpers ----------------
__device__ __forceinline__ unsigned h2u(__half2 h) { return *(unsigned*)&h; }
__device__ __forceinline__ float leaky(float x) { return x > 0.f ? x : 0.2f * x; }
__device__ __forceinline__ float elu(float x)   { return x > 0.f ? x : expm1f(x); }
__device__ __forceinline__ float wexp(float x)  { return __expf(fminf(x, 80.f)); }

// ---------------- fp16 conversions (branch A head) ----------------
__global__ void convx_kernel(const float* __restrict__ x) {
    int stride = gridDim.x * blockDim.x;
    for (int i = blockIdx.x * blockDim.x + threadIdx.x; i < NN * INC / 8; i += stride) {
        const float4* p = (const float4*)x + (size_t)i * 2;
        float4 a = p[0], b = p[1];
        uint4 u;
        u.x = h2u(__floats2half2_rn(a.x, a.y));
        u.y = h2u(__floats2half2_rn(a.z, a.w));
        u.z = h2u(__floats2half2_rn(b.x, b.y));
        u.w = h2u(__floats2half2_rn(b.z, b.w));
        ((uint4*)g_xh)[i] = u;
    }
}

__global__ void convW1_kernel(const float* __restrict__ W1) {
    int i = blockIdx.x * blockDim.x + threadIdx.x;
    if (i >= INC * HC / 8) return;
    const float4* p = (const float4*)W1 + (size_t)i * 2;
    float4 a = p[0], b = p[1];
    uint4 u;
    u.x = h2u(__floats2half2_rn(a.x, a.y));
    u.y = h2u(__floats2half2_rn(a.z, a.w));
    u.z = h2u(__floats2half2_rn(b.x, b.y));
    u.w = h2u(__floats2half2_rn(b.z, b.w));
    ((uint4*)g_W1h)[i] = u;
}

// ---------------- GEMM1: wmma fp16 -> fp32, tile 128x128, 8 warps ----------------
// NOTE: reads g_xh / g_W1h directly (device globals CANNOT be passed as kernel
// args from host code — that was the R10 bug).
__global__ void __launch_bounds__(256) sgemm1_wmma() {
    __shared__ __align__(32) __half As[128][32];    // ld=32 (64B rows)
    __shared__ __align__(32) __half Bs[16][144];    // ld=144 (288B rows)
    int tid = threadIdx.x;
    int w = tid >> 5, wr = w >> 1, wc = w & 1;
    int brow = blockIdx.x;

    wmma::fragment<wmma::accumulator, 16, 16, 16, float> cf[2][4];
#pragma unroll
    for (int mi = 0; mi < 2; mi++)
#pragma unroll
        for (int ni = 0; ni < 4; ni++) wmma::fill_fragment(cf[mi][ni], 0.f);

    int rA = tid >> 1, segA = (tid & 1) * 8;
    int ag = brow * 128 + rA;
    int qB = tid >> 4, cB = (tid & 15) * 8;

    for (int k0 = 0; k0 < INC; k0 += 16) {
        uint4 ua = make_uint4(0, 0, 0, 0);
        if (ag < NN) ua = *(const uint4*)(g_xh + (size_t)ag * INC + k0 + segA);
        *(uint4*)&As[rA][segA] = ua;
        *(uint4*)&Bs[qB][cB] = *(const uint4*)(g_W1h + (size_t)(k0 + qB) * HC + cB);
        __syncthreads();

        wmma::fragment<wmma::matrix_b, 16, 16, 16, __half, wmma::row_major> bf[4];
#pragma unroll
        for (int ni = 0; ni < 4; ni++)
            wmma::load_matrix_sync(bf[ni], &Bs[0][wc * 64 + ni * 16], 144);
#pragma unroll
        for (int mi = 0; mi < 2; mi++) {
            wmma::fragment<wmma::matrix_a, 16, 16, 16, __half, wmma::row_major> af;
            wmma::load_matrix_sync(af, &As[wr * 32 + mi * 16][0], 32);
#pragma unroll
            for (int ni = 0; ni < 4; ni++)
                wmma::mma_sync(cf[mi][ni], af, bf[ni], cf[mi][ni]);
        }
        __syncthreads();
    }
#pragma unroll
    for (int mi = 0; mi < 2; mi++)
#pragma unroll
        for (int ni = 0; ni < 4; ni++)
            wmma::store_matrix_sync(
                g_xs1 + (size_t)(brow * 128 + wr * 32 + mi * 16) * HC + wc * 64 + ni * 16,
                cf[mi][ni], HC, wmma::mem_row_major);
}

// ---------------- post1: al1 dots + fp16 mirror (fused) ----------------
__global__ void post1_kernel(const float* __restrict__ as1, const float* __restrict__ ad1) {
    int idx = blockIdx.x * blockDim.x + threadIdx.x;
    if (idx >= NN * H1) return;
    int n = idx >> 2, h = idx & 3;
    const float4* xp = (const float4*)(g_xs1 + (size_t)n * HC + h * C1);
    const float4* ap = (const float4*)(as1 + h * C1);
    const float4* dp = (const float4*)(ad1 + h * C1);
    float s = 0.f, d = 0.f;
    float v[32];
#pragma unroll
    for (int c = 0; c < 8; c++) {
        float4 x = xp[c], a = ap[c], b = dp[c];
        v[4*c] = x.x; v[4*c+1] = x.y; v[4*c+2] = x.z; v[4*c+3] = x.w;
        s += x.x * a.x + x.y * a.y + x.z * a.z + x.w * a.w;
        d += x.x * b.x + x.y * b.y + x.z * b.z + x.w * b.w;
    }
    g_als1[idx] = s;
    g_ald1[idx] = d;
    uint4* op = (uint4*)(g_xs1h + (size_t)n * HC + h * C1);
#pragma unroll
    for (int q = 0; q < 4; q++) {
        uint4 u;
        u.x = h2u(__floats2half2_rn(v[8*q + 0], v[8*q + 1]));
        u.y = h2u(__floats2half2_rn(v[8*q + 2], v[8*q + 3]));
        u.z = h2u(__floats2half2_rn(v[8*q + 4], v[8*q + 5]));
        u.w = h2u(__floats2half2_rn(v[8*q + 6], v[8*q + 7]));
        op[q] = u;
    }
}

// ---------------- CSR build (branch B) ----------------
__global__ void init_deg_kernel() {
    int i = blockIdx.x * blockDim.x + threadIdx.x;
    if (i < NN) g_deg[i] = 1;
}

__global__ void hist_mean_kernel(const int* __restrict__ ei, const float* __restrict__ ea) {
    __shared__ float s[256];
    float v = 0.f;
    for (int e = blockIdx.x * blockDim.x + threadIdx.x; e < EE; e += gridDim.x * blockDim.x) {
        atomicAdd(&g_deg[ei[EE + e]], 1);
        v += ea[e];
    }
    s[threadIdx.x] = v; __syncthreads();
    for (int o = 128; o > 0; o >>= 1) {
        if (threadIdx.x < o) s[threadIdx.x] += s[threadIdx.x + o];
        __syncthreads();
    }
    if (threadIdx.x == 0) g_partial[blockIdx.x] = s[0];
}

__global__ void mean_fin_kernel(const float* __restrict__ We1, const float* __restrict__ ae1,
                                const float* __restrict__ We2, const float* __restrict__ ae2) {
    __shared__ float s[512];
    int t = threadIdx.x;
    s[t] = g_partial[t]; __syncthreads();
    for (int o = 256; o > 0; o >>= 1) {
        if (t < o) s[t] += s[t + o];
        __syncthreads();
    }
    if (t == 0) g_mean = s[0] / (float)EE;
    if (t < H1) {
        float k = 0.f;
        for (int c = 0; c < C1; c++) k += We1[t * C1 + c] * ae1[t * C1 + c];
        g_k1v[t] = k;
    }
    if (t == H1) {
        float k = 0.f;
        for (int c = 0; c < C1; c++) k += We2[c] * ae2[c];
        g_k2 = k;
    }
}

__global__ void scan_part_kernel() {
    __shared__ int s[256];
    int t = threadIdx.x, b = blockIdx.x;
    int i = b * 256 + t;
    int v = (i < NN) ? g_deg[i] : 0;
    s[t] = v; __syncthreads();
    for (int o = 128; o > 0; o >>= 1) {
        if (t < o) s[t] += s[t + o];
        __syncthreads();
    }
    if (t == 0) g_bsum[b] = s[0];
}

__global__ void scan_mid_kernel() {
    __shared__ int s[256];
    int t = threadIdx.x;
    int v = (t < NB) ? g_bsum[t] : 0;
    s[t] = v; __syncthreads();
    for (int o = 1; o < 256; o <<= 1) {
        int u = (t >= o) ? s[t - o] : 0;
        __syncthreads();
        s[t] += u;
        __syncthreads();
    }
    if (t < NB) g_boff[t] = s[t] - v;
}

__global__ void scan_fin_kernel() {
    __shared__ int s[256];
    int t = threadIdx.x, b = blockIdx.x;
    int i = b * 256 + t;
    int v = (i < NN) ? g_deg[i] : 0;
    s[t] = v; __syncthreads();
    for (int o = 1; o < 256; o <<= 1) {
        int u = (t >= o) ? s[t - o] : 0;
        __syncthreads();
        s[t] += u;
        __syncthreads();
    }
    int excl = s[t] - v + g_boff[b];
    if (i < NN) { g_rowptr[i] = excl; g_cursor[i] = excl; }
    if (b == 0 && t == 0) g_rowptr[NN] = ET;
}

__global__ void scatter_perm_kernel(const int* __restrict__ ei, const float* __restrict__ ea) {
    float mn = g_mean;
    for (int idx = blockIdx.x * blockDim.x + threadIdx.x; idx < ET; idx += gridDim.x * blockDim.x) {
        int srcn, dstn; float eav;
        if (idx < EE) {
            srcn = ei[idx];
            dstn = ei[EE + idx];
            eav  = ea[idx];
        } else {
            srcn = dstn = idx - EE;
            eav  = mn;
        }
        int slot = atomicAdd(&g_cursor[dstn], 1);
        ((float4*)&g_slot[slot])[1] =
            make_float4(__int_as_float(srcn), __int_as_float(dstn), eav, 0.f);
    }
}

// ---------------- layer-1 softmax weights (slot-parallel, after join) ----------------
__global__ void logits1_kernel() {
    float k0 = g_k1v[0], k1 = g_k1v[1], k2 = g_k1v[2], k3 = g_k1v[3];
    for (int e = blockIdx.x * blockDim.x + threadIdx.x; e < ET; e += gridDim.x * blockDim.x) {
        float4 meta = ((const float4*)&g_slot[e])[1];
        int src = __float_as_int(meta.x);
        int dst = __float_as_int(meta.y);
        float eav = meta.z;
        float4 als = *(const float4*)(g_als1 + src * 4);
        float4 ald = *(const float4*)(g_ald1 + dst * 4);
        float4 w;
        w.x = wexp(leaky(als.x + ald.x + k0 * eav));
        w.y = wexp(leaky(als.y + ald.y + k1 * eav));
        w.z = wexp(leaky(als.z + ald.z + k2 * eav));
        w.w = wexp(leaky(als.w + ald.w + k3 * eav));
        ((float4*)&g_slot[e])[0] = w;
    }
}

// ---------------- agg1: warp/node, fp16 gathers, 4x unroll, fused bias+bn+elu ------
__global__ void agg1_kernel(const float* __restrict__ b1, const float* __restrict__ g1,
                            const float* __restrict__ be1) {
    int n    = (blockIdx.x * blockDim.x + threadIdx.x) >> 5;
    int lane = threadIdx.x & 31;
    if (n >= NN) return;
    int beg = g_rowptr[n], end = g_rowptr[n + 1];

    float acc0 = 0.f, acc1 = 0.f, acc2 = 0.f, acc3 = 0.f;
    float den0 = 0.f, den1 = 0.f, den2 = 0.f, den3 = 0.f;
    int e = beg;
    for (; e + 4 <= end; e += 4) {
#pragma unroll
        for (int q = 0; q < 4; q++) {
            float4 w = *(const float4*)&g_slot[e + q];
            int s = ((const int*)&g_slot[e + q])[4];
            const __half* xr = g_xs1h + (size_t)s * HC + lane;
            acc0 += w.x * __half2float(xr[0]);  den0 += w.x;
            acc1 += w.y * __half2float(xr[32]); den1 += w.y;
            acc2 += w.z * __half2float(xr[64]); den2 += w.z;
            acc3 += w.w * __half2float(xr[96]); den3 += w.w;
        }
    }
    for (; e < end; ++e) {
        float4 w = *(const float4*)&g_slot[e];
        int s = ((const int*)&g_slot[e])[4];
        const __half* xr = g_xs1h + (size_t)s * HC + lane;
        acc0 += w.x * __half2float(xr[0]);  den0 += w.x;
        acc1 += w.y * __half2float(xr[32]); den1 += w.y;
        acc2 += w.z * __half2float(xr[64]); den2 += w.z;
        acc3 += w.w * __half2float(xr[96]); den3 += w.w;
    }
    float inv = rsqrtf(1.f + BN_EPS);
    float* op = g_out1 + (size_t)n * HC + lane;
#pragma unroll
    for (int h = 0; h < 4; h++) {
        float a = (h == 0) ? acc0 : (h == 1) ? acc1 : (h == 2) ? acc2 : acc3;
        float d = (h == 0) ? den0 : (h == 1) ? den1 : (h == 2) ? den2 : den3;
        int c = h * 32 + lane;
        float v = a / (d + 1e-16f) + b1[c];
        v = v * (g1[c] * inv) + be1[c];
        op[h * 32] = elu(v);
    }
}

// ---------------- GEMM2 + fused al2 ----------------
__global__ void gemm2_kernel(const float* __restrict__ W2, const float* __restrict__ as2,
                             const float* __restrict__ ad2) {
    __shared__ float Ws[HC * C1];
    for (int i = threadIdx.x; i < HC * C1; i += blockDim.x) Ws[i] = W2[i];
    __syncthreads();
    int node = blockIdx.x * 8 + threadIdx.x / 32;
    int lane = threadIdx.x & 31;
    if (node >= NN) return;
    const float* row = g_out1 + (size_t)node * HC;
    float s = 0.f;
#pragma unroll 8
    for (int k = 0; k < HC; k++) s += row[k] * Ws[k * C1 + lane];
    g_xs2[(size_t)node * C1 + lane] = s;
    g_xs2h[(size_t)node * C1 + lane] = __float2half_rn(s);

    float ps = s * as2[lane];
    float pd = s * ad2[lane];
#pragma unroll
    for (int off = 16; off > 0; off >>= 1) {
        ps += __shfl_xor_sync(0xffffffffu, ps, off);
        pd += __shfl_xor_sync(0xffffffffu, pd, off);
    }
    if (lane == 0) { g_als2[node] = ps; g_ald2[node] = pd; }
}

// ---------------- agg2: warp/node, inline weights, fp16 gathers + bn+elu + heads ----
__global__ void agg2_heads_kernel(const float* __restrict__ b2, const float* __restrict__ g2,
                                  const float* __restrict__ be2,
                                  const float* __restrict__ Wc1, const float* __restrict__ bc1,
                                  const float* __restrict__ Wc2, const float* __restrict__ bc2,
                                  const float* __restrict__ Wr1, const float* __restrict__ br1,
                                  const float* __restrict__ Wr2, const float* __restrict__ br2,
                                  float* __restrict__ out) {
    __shared__ float sWc1[C1 * 16], sWr1[C1 * 16];
    __shared__ float sWc2[32], sWr2[16];
    __shared__ float sbc1[16], sbr1[16], sbc2[2], sbr2v[1];
    __shared__ float sh[8][32];
    int t = threadIdx.x;
    for (int i = t; i < C1 * 16; i += blockDim.x) { sWc1[i] = Wc1[i]; sWr1[i] = Wr1[i]; }
    if (t < 32) sWc2[t] = Wc2[t];
    if (t < 16) { sWr2[t] = Wr2[t]; sbc1[t] = bc1[t]; sbr1[t] = br1[t]; }
    if (t < 2)  sbc2[t] = bc2[t];
    if (t == 32) sbr2v[0] = br2[0];
    __syncthreads();

    int wi   = t >> 5;
    int lane = t & 31;
    int n    = blockIdx.x * 8 + wi;
    if (n >= NN) return;
    int beg = g_rowptr[n], end = g_rowptr[n + 1];
    float ald = g_ald2[n];          // uniform per warp
    float k2  = g_k2;

    float den = 0.f, acc = 0.f;
    int e = beg;
    for (; e + 4 <= end; e += 4) {
#pragma unroll
        for (int q = 0; q < 4; q++) {
            float4 meta = ((const float4*)&g_slot[e + q])[1];
            int s = __float_as_int(meta.x);
            float w = wexp(leaky(g_als2[s] + ald + k2 * meta.z));
            acc += w * __half2float(g_xs2h[(size_t)s * C1 + lane]);
            den += w;
        }
    }
    for (; e < end; ++e) {
        float4 meta = ((const float4*)&g_slot[e])[1];
        int s = __float_as_int(meta.x);
        float w = wexp(leaky(g_als2[s] + ald + k2 * meta.z));
        acc += w * __half2float(g_xs2h[(size_t)s * C1 + lane]);
        den += w;
    }
    float v = acc / (den + 1e-16f) + b2[lane];
    v = v * (g2[lane] * rsqrtf(1.f + BN_EPS)) + be2[lane];
    float h = elu(v);
    out[3 * NN + (size_t)n * C1 + lane] = h;
    sh[wi][lane] = h;
    __syncwarp();

    int j = lane & 15;
    const float* W = (lane < 16) ? sWc1 : sWr1;
    float tt = (lane < 16) ? sbc1[j] : sbr1[j];
#pragma unroll
    for (int c = 0; c < C1; c++) tt += sh[wi][c] * W[c * 16 + j];
    tt = fmaxf(tt, 0.f);
    float pa = (lane < 16) ? tt * sWc2[j * 2 + 0] : tt * sWr2[j];
    float pb = (lane < 16) ? tt * sWc2[j * 2 + 1] : 0.f;
#pragma unroll
    for (int off = 8; off > 0; off >>= 1) {
        pa += __shfl_xor_sync(0xffffffffu, pa, off);
        pb += __shfl_xor_sync(0xffffffffu, pb, off);
    }
    if (lane == 0) {
        out[(size_t)n * 2 + 0] = pa + sbc2[0];
        out[(size_t)n * 2 + 1] = pb + sbc2[1];
    }
    if (lane == 16) {
        out[2 * NN + n] = pa + sbr2v[0];
    }
}

// ---------------- launch (stream-forked graph) ----------------
extern "C" void kernel_launch(void* const* d_in, const int* in_sizes, int n_in,
                              void* d_out, int out_size) {
    const float* x   = (const float*)d_in[0];
    const int*   ei  = (const int*)d_in[1];     // int32 (JAX x64 disabled)
    const float* ea  = (const float*)d_in[2];
    const float* W1  = (const float*)d_in[3];
    const float* as1 = (const float*)d_in[4];
    const float* ad1 = (const float*)d_in[5];
    const float* We1 = (const float*)d_in[6];
    const float* ae1 = (const float*)d_in[7];
    const float* b1  = (const float*)d_in[8];
    const float* g1  = (const float*)d_in[9];
    const float* be1 = (const float*)d_in[10];
    const float* W2  = (const float*)d_in[11];
    const float* as2 = (const float*)d_in[12];
    const float* ad2 = (const float*)d_in[13];
    const float* We2 = (const float*)d_in[14];
    const float* ae2 = (const float*)d_in[15];
    const float* b2  = (const float*)d_in[16];
    const float* g2  = (const float*)d_in[17];
    const float* be2 = (const float*)d_in[18];
    const float* Wc1 = (const float*)d_in[19];
    const float* bc1 = (const float*)d_in[20];
    const float* Wc2 = (const float*)d_in[21];
    const float* bc2 = (const float*)d_in[22];
    const float* Wr1 = (const float*)d_in[23];
    const float* br1 = (const float*)d_in[24];
    const float* Wr2 = (const float*)d_in[25];
    const float* br2 = (const float*)d_in[26];
    float* out = (float*)d_out;

    cudaStream_t sB;
    cudaStreamCreateWithFlags(&sB, cudaStreamNonBlocking);
    cudaEvent_t eFork, eJoin;
    cudaEventCreateWithFlags(&eFork, cudaEventDisableTiming);
    cudaEventCreateWithFlags(&eJoin, cudaEventDisableTiming);

    cudaEventRecord(eFork, 0);
    cudaStreamWaitEvent(sB, eFork, 0);

    // Branch B (CSR + scatter permutation)
    init_deg_kernel<<<(NN + 255) / 256, 256, 0, sB>>>();
    hist_mean_kernel<<<512, 256, 0, sB>>>(ei, ea);
    mean_fin_kernel<<<1, 512, 0, sB>>>(We1, ae1, We2, ae2);
    scan_part_kernel<<<NB, 256, 0, sB>>>();
    scan_mid_kernel<<<1, 256, 0, sB>>>();
    scan_fin_kernel<<<NB, 256, 0, sB>>>();
    scatter_perm_kernel<<<2048, 256, 0, sB>>>(ei, ea);

    // Branch A (fp16 GEMM1 chain) on main stream
    convW1_kernel<<<(INC * HC / 8 + 255) / 256, 256>>>(W1);
    convx_kernel<<<2048, 256>>>(x);
    sgemm1_wmma<<<(NN + 127) / 128, 256>>>();
    post1_kernel<<<(NN * H1 + 255) / 256, 256>>>(as1, ad1);

    cudaEventRecord(eJoin, sB);
    cudaStreamWaitEvent(0, eJoin, 0);

    // Joined tail on main stream
    logits1_kernel<<<2048, 256>>>();
    agg1_kernel<<<(NN + 7) / 8, 256>>>(b1, g1, be1);
    gemm2_kernel<<<(NN + 7) / 8, 256>>>(W2, as2, ad2);
    agg2_heads_kernel<<<(NN + 7) / 8, 256>>>(b2, g2, be2,
        Wc1, bc1, Wc2, bc2, Wr1, br1, Wr2, br2, out);

    cudaEventDestroy(eFork);
    cudaEventDestroy(eJoin);
    // sB intentionally not destroyed during capture.
}

// round 12
// speedup vs baseline: 1.4051x; 1.0913x over previous
#include <cuda_runtime.h>
#include <cuda_fp16.h>
#include <mma.h>
#include <math.h>

using namespace nvcuda;

#define NN   50000
#define EE   1600000
#define ET   (EE + NN)
#define INC  256
#define HC   128
#define H1   4
#define C1   32
#define BN_EPS 1e-5f
#define NB   196            // ceil(NN/256)
#define NROWS 50048         // 391*128, padded rows for GEMM1 stores

// ---------------- scratch ----------------
struct __align__(32) Slot { float w0, w1, w2, w3; int src; int dst; float ea; float pad; };

__device__ __half  g_W1h [INC * HC];     // fp16 W1
__device__ float   g_xs1 [NROWS * HC];   // fp32 GEMM1 out (padded)
__device__ __half2 g_xs1p[NN * 64];      // packed mirror: [n][p] = (x[p], x[p+64])
__device__ __half  g_out1h[NN * HC];     // fp16 h1
__device__ float   g_xs2 [NN * C1];
__device__ __half  g_xs2h[NN * C1];
__device__ float   g_als1[NN * H1];
__device__ float   g_ald1[NN * H1];
__device__ float   g_als2[NN];
__device__ float   g_ald2[NN];
__device__ int     g_deg   [NN];
__device__ int     g_rowptr[NN + 1];
__device__ int     g_cursor[NN];
__device__ int     g_bsum[NB];
__device__ int     g_boff[NB];
__device__ Slot    g_slot[ET];
__device__ float   g_partial[512];
__device__ float   g_mean;
__device__ float   g_k1v[H1];
__device__ float   g_k2;

// ---------------- helpers ----------------
__device__ __forceinline__ unsigned h2u(__half2 h) { return *(unsigned*)&h; }
__device__ __forceinline__ float leaky(float x) { return x > 0.f ? x : 0.2f * x; }
__device__ __forceinline__ float elu(float x)   { return x > 0.f ? x : expm1f(x); }
__device__ __forceinline__ float wexp(float x)  { return __expf(fminf(x, 80.f)); }

// ---------------- fp16 W1 conversion ----------------
__global__ void convW1_kernel(const float* __restrict__ W1) {
    int i = blockIdx.x * blockDim.x + threadIdx.x;
    if (i >= INC * HC / 8) return;
    const float4* p = (const float4*)W1 + (size_t)i * 2;
    float4 a = p[0], b = p[1];
    uint4 u;
    u.x = h2u(__floats2half2_rn(a.x, a.y));
    u.y = h2u(__floats2half2_rn(a.z, a.w));
    u.z = h2u(__floats2half2_rn(b.x, b.y));
    u.w = h2u(__floats2half2_rn(b.z, b.w));
    ((uint4*)g_W1h)[i] = u;
}

// ---------------- GEMM1: wmma fp16->fp32, converts x fp32->fp16 in-flight ----------
__global__ void __launch_bounds__(256) sgemm1_wmma(const float* __restrict__ x) {
    __shared__ __align__(32) __half As[128][32];    // ld=32
    __shared__ __align__(32) __half Bs[16][144];    // ld=144
    int tid = threadIdx.x;
    int w = tid >> 5, wr = w >> 1, wc = w & 1;
    int brow = blockIdx.x;

    wmma::fragment<wmma::accumulator, 16, 16, 16, float> cf[2][4];
#pragma unroll
    for (int mi = 0; mi < 2; mi++)
#pragma unroll
        for (int ni = 0; ni < 4; ni++) wmma::fill_fragment(cf[mi][ni], 0.f);

    int rA = tid >> 1, segA = (tid & 1) * 8;
    int ag = brow * 128 + rA;
    int qB = tid >> 4, cB = (tid & 15) * 8;

    for (int k0 = 0; k0 < INC; k0 += 16) {
        uint4 ua = make_uint4(0, 0, 0, 0);
        if (ag < NN) {
            const float* xp = x + (size_t)ag * INC + k0 + segA;
            float4 f0 = *(const float4*)(xp);
            float4 f1 = *(const float4*)(xp + 4);
            ua.x = h2u(__floats2half2_rn(f0.x, f0.y));
            ua.y = h2u(__floats2half2_rn(f0.z, f0.w));
            ua.z = h2u(__floats2half2_rn(f1.x, f1.y));
            ua.w = h2u(__floats2half2_rn(f1.z, f1.w));
        }
        *(uint4*)&As[rA][segA] = ua;
        *(uint4*)&Bs[qB][cB] = *(const uint4*)(g_W1h + (size_t)(k0 + qB) * HC + cB);
        __syncthreads();

        wmma::fragment<wmma::matrix_b, 16, 16, 16, __half, wmma::row_major> bf[4];
#pragma unroll
        for (int ni = 0; ni < 4; ni++)
            wmma::load_matrix_sync(bf[ni], &Bs[0][wc * 64 + ni * 16], 144);
#pragma unroll
        for (int mi = 0; mi < 2; mi++) {
            wmma::fragment<wmma::matrix_a, 16, 16, 16, __half, wmma::row_major> af;
            wmma::load_matrix_sync(af, &As[wr * 32 + mi * 16][0], 32);
#pragma unroll
            for (int ni = 0; ni < 4; ni++)
                wmma::mma_sync(cf[mi][ni], af, bf[ni], cf[mi][ni]);
        }
        __syncthreads();
    }
#pragma unroll
    for (int mi = 0; mi < 2; mi++)
#pragma unroll
        for (int ni = 0; ni < 4; ni++)
            wmma::store_matrix_sync(
                g_xs1 + (size_t)(brow * 128 + wr * 32 + mi * 16) * HC + wc * 64 + ni * 16,
                cf[mi][ni], HC, wmma::mem_row_major);
}

// ---------------- post1: al1 dots + packed half2 mirror; 2 threads/node ------------
__global__ void post1_kernel(const float* __restrict__ as1, const float* __restrict__ ad1) {
    int idx = blockIdx.x * blockDim.x + threadIdx.x;
    if (idx >= NN * 2) return;
    int n = idx >> 1, q = idx & 1;
    // thread q handles heads q (channels q*32..+31) and q+2 (channels q*32+64..+95)
    const float4* x1 = (const float4*)(g_xs1 + (size_t)n * HC + q * 32);
    const float4* x2 = (const float4*)(g_xs1 + (size_t)n * HC + q * 32 + 64);
    const float4* aA = (const float4*)(as1 + q * 32);
    const float4* aB = (const float4*)(as1 + q * 32 + 64);
    const float4* dA = (const float4*)(ad1 + q * 32);
    const float4* dB = (const float4*)(ad1 + q * 32 + 64);
    float sA = 0.f, tA = 0.f, sB = 0.f, tB = 0.f;
    uint4 pk[4];
#pragma unroll
    for (int c = 0; c < 8; c++) {
        float4 va = x1[c], vb = x2[c];
        float4 aa = aA[c], ab = aB[c];
        float4 da = dA[c], db = dB[c];
        sA += va.x * aa.x + va.y * aa.y + va.z * aa.z + va.w * aa.w;
        tA += va.x * da.x + va.y * da.y + va.z * da.z + va.w * da.w;
        sB += vb.x * ab.x + vb.y * ab.y + vb.z * ab.z + vb.w * ab.w;
        tB += vb.x * db.x + vb.y * db.y + vb.z * db.z + vb.w * db.w;
        unsigned p0 = h2u(__floats2half2_rn(va.x, vb.x));
        unsigned p1 = h2u(__floats2half2_rn(va.y, vb.y));
        unsigned p2 = h2u(__floats2half2_rn(va.z, vb.z));
        unsigned p3 = h2u(__floats2half2_rn(va.w, vb.w));
        ((unsigned*)pk)[4 * (c & 1) + 0] = p0;
        ((unsigned*)pk)[4 * (c & 1) + 1] = p1;
        ((unsigned*)pk)[4 * (c & 1) + 2] = p2;
        ((unsigned*)pk)[4 * (c & 1) + 3] = p3;
        if ((c & 1) == 1) {
            uint4* op = (uint4*)(g_xs1p + (size_t)n * 64 + q * 32 + (c - 1) * 4);
            op[0] = pk[0];
            op[1] = pk[1];
        }
    }
    g_als1[n * 4 + q]     = sA;
    g_als1[n * 4 + q + 2] = sB;
    g_ald1[n * 4 + q]     = tA;
    g_ald1[n * 4 + q + 2] = tB;
}

// ---------------- CSR build (branch B) ----------------
__global__ void init_deg_kernel() {
    int i = blockIdx.x * blockDim.x + threadIdx.x;
    if (i < NN) g_deg[i] = 1;
}

__global__ void hist_mean_kernel(const int* __restrict__ ei, const float* __restrict__ ea) {
    __shared__ float s[256];
    float v = 0.f;
    for (int e = blockIdx.x * blockDim.x + threadIdx.x; e < EE; e += gridDim.x * blockDim.x) {
        atomicAdd(&g_deg[ei[EE + e]], 1);
        v += ea[e];
    }
    s[threadIdx.x] = v; __syncthreads();
    for (int o = 128; o > 0; o >>= 1) {
        if (threadIdx.x < o) s[threadIdx.x] += s[threadIdx.x + o];
        __syncthreads();
    }
    if (threadIdx.x == 0) g_partial[blockIdx.x] = s[0];
}

__global__ void mean_fin_kernel(const float* __restrict__ We1, const float* __restrict__ ae1,
                                const float* __restrict__ We2, const float* __restrict__ ae2) {
    __shared__ float s[512];
    int t = threadIdx.x;
    s[t] = g_partial[t]; __syncthreads();
    for (int o = 256; o > 0; o >>= 1) {
        if (t < o) s[t] += s[t + o];
        __syncthreads();
    }
    if (t == 0) g_mean = s[0] / (float)EE;
    if (t < H1) {
        float k = 0.f;
        for (int c = 0; c < C1; c++) k += We1[t * C1 + c] * ae1[t * C1 + c];
        g_k1v[t] = k;
    }
    if (t == H1) {
        float k = 0.f;
        for (int c = 0; c < C1; c++) k += We2[c] * ae2[c];
        g_k2 = k;
    }
}

__global__ void scan_part_kernel() {
    __shared__ int s[256];
    int t = threadIdx.x, b = blockIdx.x;
    int i = b * 256 + t;
    int v = (i < NN) ? g_deg[i] : 0;
    s[t] = v; __syncthreads();
    for (int o = 128; o > 0; o >>= 1) {
        if (t < o) s[t] += s[t + o];
        __syncthreads();
    }
    if (t == 0) g_bsum[b] = s[0];
}

__global__ void scan_mid_kernel() {
    __shared__ int s[256];
    int t = threadIdx.x;
    int v = (t < NB) ? g_bsum[t] : 0;
    s[t] = v; __syncthreads();
    for (int o = 1; o < 256; o <<= 1) {
        int u = (t >= o) ? s[t - o] : 0;
        __syncthreads();
        s[t] += u;
        __syncthreads();
    }
    if (t < NB) g_boff[t] = s[t] - v;
}

__global__ void scan_fin_kernel() {
    __shared__ int s[256];
    int t = threadIdx.x, b = blockIdx.x;
    int i = b * 256 + t;
    int v = (i < NN) ? g_deg[i] : 0;
    s[t] = v; __syncthreads();
    for (int o = 1; o < 256; o <<= 1) {
        int u = (t >= o) ? s[t - o] : 0;
        __syncthreads();
        s[t] += u;
        __syncthreads();
    }
    int excl = s[t] - v + g_boff[b];
    if (i < NN) { g_rowptr[i] = excl; g_cursor[i] = excl; }
    if (b == 0 && t == 0) g_rowptr[NN] = ET;
}

__global__ void scatter_perm_kernel(const int* __restrict__ ei, const float* __restrict__ ea) {
    float mn = g_mean;
    for (int idx = blockIdx.x * blockDim.x + threadIdx.x; idx < ET; idx += gridDim.x * blockDim.x) {
        int srcn, dstn; float eav;
        if (idx < EE) {
            srcn = ei[idx];
            dstn = ei[EE + idx];
            eav  = ea[idx];
        } else {
            srcn = dstn = idx - EE;
            eav  = mn;
        }
        int slot = atomicAdd(&g_cursor[dstn], 1);
        ((float4*)&g_slot[slot])[1] =
            make_float4(__int_as_float(srcn), __int_as_float(dstn), eav, 0.f);
    }
}

// ---------------- layer-1 softmax weights (slot-parallel, after join) ----------------
__global__ void logits1_kernel() {
    float k0 = g_k1v[0], k1 = g_k1v[1], k2 = g_k1v[2], k3 = g_k1v[3];
    for (int e = blockIdx.x * blockDim.x + threadIdx.x; e < ET; e += gridDim.x * blockDim.x) {
        float4 meta = ((const float4*)&g_slot[e])[1];
        int src = __float_as_int(meta.x);
        int dst = __float_as_int(meta.y);
        float eav = meta.z;
        float4 als = *(const float4*)(g_als1 + src * 4);
        float4 ald = *(const float4*)(g_ald1 + dst * 4);
        float4 w;
        w.x = wexp(leaky(als.x + ald.x + k0 * eav));
        w.y = wexp(leaky(als.y + ald.y + k1 * eav));
        w.z = wexp(leaky(als.z + ald.z + k2 * eav));
        w.w = wexp(leaky(als.w + ald.w + k3 * eav));
        ((float4*)&g_slot[e])[0] = w;
    }
}

// ---------------- agg1: warp/node, packed half2 gathers, fused bias+bn+elu (fp16 out) ----
__global__ void agg1_kernel(const float* __restrict__ b1, const float* __restrict__ g1,
                            const float* __restrict__ be1) {
    int n    = (blockIdx.x * blockDim.x + threadIdx.x) >> 5;
    int lane = threadIdx.x & 31;
    if (n >= NN) return;
    int beg = g_rowptr[n], end = g_rowptr[n + 1];

    float acc0 = 0.f, acc1 = 0.f, acc2 = 0.f, acc3 = 0.f;
    float den0 = 0.f, den1 = 0.f, den2 = 0.f, den3 = 0.f;
    int e = beg;
    for (; e + 4 <= end; e += 4) {
#pragma unroll
        for (int q = 0; q < 4; q++) {
            float4 w = *(const float4*)&g_slot[e + q];
            int s = ((const int*)&g_slot[e + q])[4];
            const __half2* xr = g_xs1p + (size_t)s * 64;
            float2 a02 = __half22float2(xr[lane]);        // (head0, head2)
            float2 a13 = __half22float2(xr[lane + 32]);   // (head1, head3)
            acc0 += w.x * a02.x;  den0 += w.x;
            acc1 += w.y * a13.x;  den1 += w.y;
            acc2 += w.z * a02.y;  den2 += w.z;
            acc3 += w.w * a13.y;  den3 += w.w;
        }
    }
    for (; e < end; ++e) {
        float4 w = *(const float4*)&g_slot[e];
        int s = ((const int*)&g_slot[e])[4];
        const __half2* xr = g_xs1p + (size_t)s * 64;
        float2 a02 = __half22float2(xr[lane]);
        float2 a13 = __half22float2(xr[lane + 32]);
        acc0 += w.x * a02.x;  den0 += w.x;
        acc1 += w.y * a13.x;  den1 += w.y;
        acc2 += w.z * a02.y;  den2 += w.z;
        acc3 += w.w * a13.y;  den3 += w.w;
    }
    float inv = rsqrtf(1.f + BN_EPS);
    __half* op = g_out1h + (size_t)n * HC + lane;
#pragma unroll
    for (int h = 0; h < 4; h++) {
        float a = (h == 0) ? acc0 : (h == 1) ? acc1 : (h == 2) ? acc2 : acc3;
        float d = (h == 0) ? den0 : (h == 1) ? den1 : (h == 2) ? den2 : den3;
        int c = h * 32 + lane;
        float v = a / (d + 1e-16f) + b1[c];
        v = v * (g1[c] * inv) + be1[c];
        op[h * 32] = __float2half_rn(elu(v));
    }
}

// ---------------- GEMM2 (fp16 h1 in) + fused al2 ----------------
__global__ void gemm2_kernel(const float* __restrict__ W2, const float* __restrict__ as2,
                             const float* __restrict__ ad2) {
    __shared__ float Ws[HC * C1];
    for (int i = threadIdx.x; i < HC * C1; i += blockDim.x) Ws[i] = W2[i];
    __syncthreads();
    int node = blockIdx.x * 8 + threadIdx.x / 32;
    int lane = threadIdx.x & 31;
    if (node >= NN) return;
    const __half2* row2 = (const __half2*)(g_out1h + (size_t)node * HC);
    float s = 0.f;
#pragma unroll 8
    for (int k = 0; k < HC / 2; k++) {
        float2 r = __half22float2(row2[k]);
        s += r.x * Ws[(2 * k) * C1 + lane] + r.y * Ws[(2 * k + 1) * C1 + lane];
    }
    g_xs2[(size_t)node * C1 + lane] = s;
    g_xs2h[(size_t)node * C1 + lane] = __float2half_rn(s);

    float ps = s * as2[lane];
    float pd = s * ad2[lane];
#pragma unroll
    for (int off = 16; off > 0; off >>= 1) {
        ps += __shfl_xor_sync(0xffffffffu, ps, off);
        pd += __shfl_xor_sync(0xffffffffu, pd, off);
    }
    if (lane == 0) { g_als2[node] = ps; g_ald2[node] = pd; }
}

// ---------------- agg2: warp/node, inline weights, fp16 gathers + bn+elu + heads ----
__global__ void agg2_heads_kernel(const float* __restrict__ b2, const float* __restrict__ g2,
                                  const float* __restrict__ be2,
                                  const float* __restrict__ Wc1, const float* __restrict__ bc1,
                                  const float* __restrict__ Wc2, const float* __restrict__ bc2,
                                  const float* __restrict__ Wr1, const float* __restrict__ br1,
                                  const float* __restrict__ Wr2, const float* __restrict__ br2,
                                  float* __restrict__ out) {
    __shared__ float sWc1[C1 * 16], sWr1[C1 * 16];
    __shared__ float sWc2[32], sWr2[16];
    __shared__ float sbc1[16], sbr1[16], sbc2[2], sbr2v[1];
    __shared__ float sh[8][32];
    int t = threadIdx.x;
    for (int i = t; i < C1 * 16; i += blockDim.x) { sWc1[i] = Wc1[i]; sWr1[i] = Wr1[i]; }
    if (t < 32) sWc2[t] = Wc2[t];
    if (t < 16) { sWr2[t] = Wr2[t]; sbc1[t] = bc1[t]; sbr1[t] = br1[t]; }
    if (t < 2)  sbc2[t] = bc2[t];
    if (t == 32) sbr2v[0] = br2[0];
    __syncthreads();

    int wi   = t >> 5;
    int lane = t & 31;
    int n    = blockIdx.x * 8 + wi;
    if (n >= NN) return;
    int beg = g_rowptr[n], end = g_rowptr[n + 1];
    float ald = g_ald2[n];
    float k2  = g_k2;

    float den = 0.f, acc = 0.f;
    int e = beg;
    for (; e + 4 <= end; e += 4) {
#pragma unroll
        for (int q = 0; q < 4; q++) {
            float4 meta = ((const float4*)&g_slot[e + q])[1];
            int s = __float_as_int(meta.x);
            float w = wexp(leaky(g_als2[s] + ald + k2 * meta.z));
            acc += w * __half2float(g_xs2h[(size_t)s * C1 + lane]);
            den += w;
        }
    }
    for (; e < end; ++e) {
        float4 meta = ((const float4*)&g_slot[e])[1];
        int s = __float_as_int(meta.x);
        float w = wexp(leaky(g_als2[s] + ald + k2 * meta.z));
        acc += w * __half2float(g_xs2h[(size_t)s * C1 + lane]);
        den += w;
    }
    float v = acc / (den + 1e-16f) + b2[lane];
    v = v * (g2[lane] * rsqrtf(1.f + BN_EPS)) + be2[lane];
    float h = elu(v);
    out[3 * NN + (size_t)n * C1 + lane] = h;
    sh[wi][lane] = h;
    __syncwarp();

    int j = lane & 15;
    const float* W = (lane < 16) ? sWc1 : sWr1;
    float tt = (lane < 16) ? sbc1[j] : sbr1[j];
#pragma unroll
    for (int c = 0; c < C1; c++) tt += sh[wi][c] * W[c * 16 + j];
    tt = fmaxf(tt, 0.f);
    float pa = (lane < 16) ? tt * sWc2[j * 2 + 0] : tt * sWr2[j];
    float pb = (lane < 16) ? tt * sWc2[j * 2 + 1] : 0.f;
#pragma unroll
    for (int off = 8; off > 0; off >>= 1) {
        pa += __shfl_xor_sync(0xffffffffu, pa, off);
        pb += __shfl_xor_sync(0xffffffffu, pb, off);
    }
    if (lane == 0) {
        out[(size_t)n * 2 + 0] = pa + sbc2[0];
        out[(size_t)n * 2 + 1] = pb + sbc2[1];
    }
    if (lane == 16) {
        out[2 * NN + n] = pa + sbr2v[0];
    }
}

// ---------------- launch (stream-forked graph) ----------------
extern "C" void kernel_launch(void* const* d_in, const int* in_sizes, int n_in,
                              void* d_out, int out_size) {
    const float* x   = (const float*)d_in[0];
    const int*   ei  = (const int*)d_in[1];     // int32 (JAX x64 disabled)
    const float* ea  = (const float*)d_in[2];
    const float* W1  = (const float*)d_in[3];
    const float* as1 = (const float*)d_in[4];
    const float* ad1 = (const float*)d_in[5];
    const float* We1 = (const float*)d_in[6];
    const float* ae1 = (const float*)d_in[7];
    const float* b1  = (const float*)d_in[8];
    const float* g1  = (const float*)d_in[9];
    const float* be1 = (const float*)d_in[10];
    const float* W2  = (const float*)d_in[11];
    const float* as2 = (const float*)d_in[12];
    const float* ad2 = (const float*)d_in[13];
    const float* We2 = (const float*)d_in[14];
    const float* ae2 = (const float*)d_in[15];
    const float* b2  = (const float*)d_in[16];
    const float* g2  = (const float*)d_in[17];
    const float* be2 = (const float*)d_in[18];
    const float* Wc1 = (const float*)d_in[19];
    const float* bc1 = (const float*)d_in[20];
    const float* Wc2 = (const float*)d_in[21];
    const float* bc2 = (const float*)d_in[22];
    const float* Wr1 = (const float*)d_in[23];
    const float* br1 = (const float*)d_in[24];
    const float* Wr2 = (const float*)d_in[25];
    const float* br2 = (const float*)d_in[26];
    float* out = (float*)d_out;

    cudaStream_t sB;
    cudaStreamCreateWithFlags(&sB, cudaStreamNonBlocking);
    cudaEvent_t eFork, eJoin;
    cudaEventCreateWithFlags(&eFork, cudaEventDisableTiming);
    cudaEventCreateWithFlags(&eJoin, cudaEventDisableTiming);

    cudaEventRecord(eFork, 0);
    cudaStreamWaitEvent(sB, eFork, 0);

    // Branch B (CSR + scatter permutation)
    init_deg_kernel<<<(NN + 255) / 256, 256, 0, sB>>>();
    hist_mean_kernel<<<512, 256, 0, sB>>>(ei, ea);
    mean_fin_kernel<<<1, 512, 0, sB>>>(We1, ae1, We2, ae2);
    scan_part_kernel<<<NB, 256, 0, sB>>>();
    scan_mid_kernel<<<1, 256, 0, sB>>>();
    scan_fin_kernel<<<NB, 256, 0, sB>>>();
    scatter_perm_kernel<<<2048, 256, 0, sB>>>(ei, ea);

    // Branch A (fp16 GEMM1 chain) on main stream
    convW1_kernel<<<(INC * HC / 8 + 255) / 256, 256>>>(W1);
    sgemm1_wmma<<<(NN + 127) / 128, 256>>>(x);
    post1_kernel<<<(NN * 2 + 255) / 256, 256>>>(as1, ad1);

    cudaEventRecord(eJoin, sB);
    cudaStreamWaitEvent(0, eJoin, 0);

    // Joined tail on main stream
    logits1_kernel<<<2048, 256>>>();
    agg1_kernel<<<(NN + 7) / 8, 256>>>(b1, g1, be1);
    gemm2_kernel<<<(NN + 7) / 8, 256>>>(W2, as2, ad2);
    agg2_heads_kernel<<<(NN + 7) / 8, 256>>>(b2, g2, be2,
        Wc1, bc1, Wc2, bc2, Wr1, br1, Wr2, br2, out);

    cudaEventDestroy(eFork);
    cudaEventDestroy(eJoin);
    // sB intentionally not destroyed during capture.
}

// round 13
// speedup vs baseline: 1.4847x; 1.0567x over previous
#include <cuda_runtime.h>
#include <cuda_fp16.h>
#include <mma.h>
#include <math.h>

using namespace nvcuda;

#define NN   50000
#define EE   1600000
#define ET   (EE + NN)
#define INC  256
#define HC   128
#define H1   4
#define C1   32
#define BN_EPS 1e-5f
#define NB   196            // ceil(NN/256)
#define NROWS 50048         // 391*128, padded rows for GEMM1 stores

// ---------------- scratch ----------------
// 16B slot: bytes 0-3 w01(half2), 4-7 w23(half2), 8-11 src, 12-15 ea
struct __align__(16) Slot { unsigned w01, w23; int src; float ea; };

__device__ __half  g_W1h [INC * HC];     // fp16 W1
__device__ float   g_xs1 [NROWS * HC];   // fp32 GEMM1 out (padded)
__device__ __half2 g_xs1p[NN * 64];      // packed mirror: [n][p] = (x[p], x[p+64])
__device__ __half  g_out1h[NN * HC];     // fp16 h1
__device__ float   g_xs2 [NN * C1];
__device__ __half  g_xs2h[NN * C1];
__device__ float   g_als1[NN * H1];
__device__ float   g_ald1[NN * H1];
__device__ float   g_als2[NN];
__device__ float   g_ald2[NN];
__device__ int     g_deg   [NN];
__device__ int     g_rowptr[NN + 1];
__device__ int     g_cursor[NN];
__device__ int     g_bsum[NB];
__device__ int     g_boff[NB];
__device__ Slot    g_slot[ET];
__device__ float   g_partial[512];
__device__ float   g_mean;
__device__ float   g_k1v[H1];
__device__ float   g_k2;

// ---------------- helpers ----------------
__device__ __forceinline__ unsigned h2u(__half2 h) { return *(unsigned*)&h; }
__device__ __forceinline__ float leaky(float x) { return x > 0.f ? x : 0.2f * x; }
__device__ __forceinline__ float elu(float x)   { return x > 0.f ? x : expm1f(x); }
__device__ __forceinline__ float wexp(float x)  { return __expf(fminf(x, 80.f)); }
__device__ __forceinline__ float wexp16(float x){ return __expf(fminf(x, 11.f)); } // fp16-safe

// ---------------- fp16 W1 conversion ----------------
__global__ void convW1_kernel(const float* __restrict__ W1) {
    int i = blockIdx.x * blockDim.x + threadIdx.x;
    if (i >= INC * HC / 8) return;
    const float4* p = (const float4*)W1 + (size_t)i * 2;
    float4 a = p[0], b = p[1];
    uint4 u;
    u.x = h2u(__floats2half2_rn(a.x, a.y));
    u.y = h2u(__floats2half2_rn(a.z, a.w));
    u.z = h2u(__floats2half2_rn(b.x, b.y));
    u.w = h2u(__floats2half2_rn(b.z, b.w));
    ((uint4*)g_W1h)[i] = u;
}

// ---------------- GEMM1: wmma fp16->fp32, converts x fp32->fp16 in-flight ----------
__global__ void __launch_bounds__(256) sgemm1_wmma(const float* __restrict__ x) {
    __shared__ __align__(32) __half As[128][32];    // ld=32
    __shared__ __align__(32) __half Bs[16][144];    // ld=144
    int tid = threadIdx.x;
    int w = tid >> 5, wr = w >> 1, wc = w & 1;
    int brow = blockIdx.x;

    wmma::fragment<wmma::accumulator, 16, 16, 16, float> cf[2][4];
#pragma unroll
    for (int mi = 0; mi < 2; mi++)
#pragma unroll
        for (int ni = 0; ni < 4; ni++) wmma::fill_fragment(cf[mi][ni], 0.f);

    int rA = tid >> 1, segA = (tid & 1) * 8;
    int ag = brow * 128 + rA;
    int qB = tid >> 4, cB = (tid & 15) * 8;

    for (int k0 = 0; k0 < INC; k0 += 16) {
        uint4 ua = make_uint4(0, 0, 0, 0);
        if (ag < NN) {
            const float* xp = x + (size_t)ag * INC + k0 + segA;
            float4 f0 = *(const float4*)(xp);
            float4 f1 = *(const float4*)(xp + 4);
            ua.x = h2u(__floats2half2_rn(f0.x, f0.y));
            ua.y = h2u(__floats2half2_rn(f0.z, f0.w));
            ua.z = h2u(__floats2half2_rn(f1.x, f1.y));
            ua.w = h2u(__floats2half2_rn(f1.z, f1.w));
        }
        *(uint4*)&As[rA][segA] = ua;
        *(uint4*)&Bs[qB][cB] = *(const uint4*)(g_W1h + (size_t)(k0 + qB) * HC + cB);
        __syncthreads();

        wmma::fragment<wmma::matrix_b, 16, 16, 16, __half, wmma::row_major> bf[4];
#pragma unroll
        for (int ni = 0; ni < 4; ni++)
            wmma::load_matrix_sync(bf[ni], &Bs[0][wc * 64 + ni * 16], 144);
#pragma unroll
        for (int mi = 0; mi < 2; mi++) {
            wmma::fragment<wmma::matrix_a, 16, 16, 16, __half, wmma::row_major> af;
            wmma::load_matrix_sync(af, &As[wr * 32 + mi * 16][0], 32);
#pragma unroll
            for (int ni = 0; ni < 4; ni++)
                wmma::mma_sync(cf[mi][ni], af, bf[ni], cf[mi][ni]);
        }
        __syncthreads();
    }
#pragma unroll
    for (int mi = 0; mi < 2; mi++)
#pragma unroll
        for (int ni = 0; ni < 4; ni++)
            wmma::store_matrix_sync(
                g_xs1 + (size_t)(brow * 128 + wr * 32 + mi * 16) * HC + wc * 64 + ni * 16,
                cf[mi][ni], HC, wmma::mem_row_major);
}

// ---------------- post1: al1 dots + packed half2 mirror; 2 threads/node ------------
__global__ void post1_kernel(const float* __restrict__ as1, const float* __restrict__ ad1) {
    int idx = blockIdx.x * blockDim.x + threadIdx.x;
    if (idx >= NN * 2) return;
    int n = idx >> 1, q = idx & 1;
    const float4* x1 = (const float4*)(g_xs1 + (size_t)n * HC + q * 32);
    const float4* x2 = (const float4*)(g_xs1 + (size_t)n * HC + q * 32 + 64);
    const float4* aA = (const float4*)(as1 + q * 32);
    const float4* aB = (const float4*)(as1 + q * 32 + 64);
    const float4* dA = (const float4*)(ad1 + q * 32);
    const float4* dB = (const float4*)(ad1 + q * 32 + 64);
    float sA = 0.f, tA = 0.f, sB = 0.f, tB = 0.f;
    uint4 pk[4];
#pragma unroll
    for (int c = 0; c < 8; c++) {
        float4 va = x1[c], vb = x2[c];
        float4 aa = aA[c], ab = aB[c];
        float4 da = dA[c], db = dB[c];
        sA += va.x * aa.x + va.y * aa.y + va.z * aa.z + va.w * aa.w;
        tA += va.x * da.x + va.y * da.y + va.z * da.z + va.w * da.w;
        sB += vb.x * ab.x + vb.y * ab.y + vb.z * ab.z + vb.w * ab.w;
        tB += vb.x * db.x + vb.y * db.y + vb.z * db.z + vb.w * db.w;
        unsigned p0 = h2u(__floats2half2_rn(va.x, vb.x));
        unsigned p1 = h2u(__floats2half2_rn(va.y, vb.y));
        unsigned p2 = h2u(__floats2half2_rn(va.z, vb.z));
        unsigned p3 = h2u(__floats2half2_rn(va.w, vb.w));
        ((unsigned*)pk)[4 * (c & 1) + 0] = p0;
        ((unsigned*)pk)[4 * (c & 1) + 1] = p1;
        ((unsigned*)pk)[4 * (c & 1) + 2] = p2;
        ((unsigned*)pk)[4 * (c & 1) + 3] = p3;
        if ((c & 1) == 1) {
            uint4* op = (uint4*)(g_xs1p + (size_t)n * 64 + q * 32 + (c - 1) * 4);
            op[0] = pk[0];
            op[1] = pk[1];
        }
    }
    g_als1[n * 4 + q]     = sA;
    g_als1[n * 4 + q + 2] = sB;
    g_ald1[n * 4 + q]     = tA;
    g_ald1[n * 4 + q + 2] = tB;
}

// ---------------- CSR build (branch B) ----------------
__global__ void init_deg_kernel() {
    int i = blockIdx.x * blockDim.x + threadIdx.x;
    if (i < NN) g_deg[i] = 1;
}

__global__ void hist_mean_kernel(const int* __restrict__ ei, const float* __restrict__ ea) {
    __shared__ float s[256];
    float v = 0.f;
    for (int e = blockIdx.x * blockDim.x + threadIdx.x; e < EE; e += gridDim.x * blockDim.x) {
        atomicAdd(&g_deg[ei[EE + e]], 1);
        v += ea[e];
    }
    s[threadIdx.x] = v; __syncthreads();
    for (int o = 128; o > 0; o >>= 1) {
        if (threadIdx.x < o) s[threadIdx.x] += s[threadIdx.x + o];
        __syncthreads();
    }
    if (threadIdx.x == 0) g_partial[blockIdx.x] = s[0];
}

__global__ void mean_fin_kernel(const float* __restrict__ We1, const float* __restrict__ ae1,
                                const float* __restrict__ We2, const float* __restrict__ ae2) {
    __shared__ float s[512];
    int t = threadIdx.x;
    s[t] = g_partial[t]; __syncthreads();
    for (int o = 256; o > 0; o >>= 1) {
        if (t < o) s[t] += s[t + o];
        __syncthreads();
    }
    if (t == 0) g_mean = s[0] / (float)EE;
    if (t < H1) {
        float k = 0.f;
        for (int c = 0; c < C1; c++) k += We1[t * C1 + c] * ae1[t * C1 + c];
        g_k1v[t] = k;
    }
    if (t == H1) {
        float k = 0.f;
        for (int c = 0; c < C1; c++) k += We2[c] * ae2[c];
        g_k2 = k;
    }
}

__global__ void scan_part_kernel() {
    __shared__ int s[256];
    int t = threadIdx.x, b = blockIdx.x;
    int i = b * 256 + t;
    int v = (i < NN) ? g_deg[i] : 0;
    s[t] = v; __syncthreads();
    for (int o = 128; o > 0; o >>= 1) {
        if (t < o) s[t] += s[t + o];
        __syncthreads();
    }
    if (t == 0) g_bsum[b] = s[0];
}

__global__ void scan_mid_kernel() {
    __shared__ int s[256];
    int t = threadIdx.x;
    int v = (t < NB) ? g_bsum[t] : 0;
    s[t] = v; __syncthreads();
    for (int o = 1; o < 256; o <<= 1) {
        int u = (t >= o) ? s[t - o] : 0;
        __syncthreads();
        s[t] += u;
        __syncthreads();
    }
    if (t < NB) g_boff[t] = s[t] - v;
}

__global__ void scan_fin_kernel() {
    __shared__ int s[256];
    int t = threadIdx.x, b = blockIdx.x;
    int i = b * 256 + t;
    int v = (i < NN) ? g_deg[i] : 0;
    s[t] = v; __syncthreads();
    for (int o = 1; o < 256; o <<= 1) {
        int u = (t >= o) ? s[t - o] : 0;
        __syncthreads();
        s[t] += u;
        __syncthreads();
    }
    int excl = s[t] - v + g_boff[b];
    if (i < NN) { g_rowptr[i] = excl; g_cursor[i] = excl; }
    if (b == 0 && t == 0) g_rowptr[NN] = ET;
}

// ---------------- scatter: (src, ea) into 16B slots ----------------
__global__ void scatter_perm_kernel(const int* __restrict__ ei, const float* __restrict__ ea) {
    float mn = g_mean;
    for (int idx = blockIdx.x * blockDim.x + threadIdx.x; idx < ET; idx += gridDim.x * blockDim.x) {
        int srcn, dstn; float eav;
        if (idx < EE) {
            srcn = ei[idx];
            dstn = ei[EE + idx];
            eav  = ea[idx];
        } else {
            srcn = dstn = idx - EE;
            eav  = mn;
        }
        int slot = atomicAdd(&g_cursor[dstn], 1);
        ((int2*)&g_slot[slot])[1] = make_int2(srcn, __float_as_int(eav));
    }
}

// ---------------- logits1: warp per node, fp16 weights into slots ----------------
__global__ void logits1_kernel() {
    int n    = (blockIdx.x * blockDim.x + threadIdx.x) >> 5;
    int lane = threadIdx.x & 31;
    if (n >= NN) return;
    int beg = g_rowptr[n], end = g_rowptr[n + 1];
    float4 ald = *(const float4*)(g_ald1 + n * 4);    // uniform broadcast
    float k0 = g_k1v[0], k1 = g_k1v[1], k2 = g_k1v[2], k3 = g_k1v[3];
    for (int e = beg + lane; e < end; e += 32) {
        int2 se = ((const int2*)&g_slot[e])[1];
        float4 als = *(const float4*)(g_als1 + se.x * 4);
        float eav = __int_as_float(se.y);
        float w0 = wexp16(leaky(als.x + ald.x + k0 * eav));
        float w1 = wexp16(leaky(als.y + ald.y + k1 * eav));
        float w2 = wexp16(leaky(als.z + ald.z + k2 * eav));
        float w3 = wexp16(leaky(als.w + ald.w + k3 * eav));
        ((int2*)&g_slot[e])[0] = make_int2(h2u(__floats2half2_rn(w0, w1)),
                                           h2u(__floats2half2_rn(w2, w3)));
    }
}

// ---------------- agg1: warp/node, 1 LDG.128 per edge slot + packed gathers --------
__global__ void agg1_kernel(const float* __restrict__ b1, const float* __restrict__ g1,
                            const float* __restrict__ be1) {
    int n    = (blockIdx.x * blockDim.x + threadIdx.x) >> 5;
    int lane = threadIdx.x & 31;
    if (n >= NN) return;
    int beg = g_rowptr[n], end = g_rowptr[n + 1];

    float acc0 = 0.f, acc1 = 0.f, acc2 = 0.f, acc3 = 0.f;
    float den0 = 0.f, den1 = 0.f, den2 = 0.f, den3 = 0.f;
    int e = beg;
    for (; e + 4 <= end; e += 4) {
#pragma unroll
        for (int q = 0; q < 4; q++) {
            uint4 u = *(const uint4*)&g_slot[e + q];
            float2 w01 = __half22float2(*(__half2*)&u.x);
            float2 w23 = __half22float2(*(__half2*)&u.y);
            int s = (int)u.z;
            const __half2* xr = g_xs1p + (size_t)s * 64;
            float2 a02 = __half22float2(xr[lane]);        // (head0, head2)
            float2 a13 = __half22float2(xr[lane + 32]);   // (head1, head3)
            acc0 += w01.x * a02.x;  den0 += w01.x;
            acc1 += w01.y * a13.x;  den1 += w01.y;
            acc2 += w23.x * a02.y;  den2 += w23.x;
            acc3 += w23.y * a13.y;  den3 += w23.y;
        }
    }
    for (; e < end; ++e) {
        uint4 u = *(const uint4*)&g_slot[e];
        float2 w01 = __half22float2(*(__half2*)&u.x);
        float2 w23 = __half22float2(*(__half2*)&u.y);
        int s = (int)u.z;
        const __half2* xr = g_xs1p + (size_t)s * 64;
        float2 a02 = __half22float2(xr[lane]);
        float2 a13 = __half22float2(xr[lane + 32]);
        acc0 += w01.x * a02.x;  den0 += w01.x;
        acc1 += w01.y * a13.x;  den1 += w01.y;
        acc2 += w23.x * a02.y;  den2 += w23.x;
        acc3 += w23.y * a13.y;  den3 += w23.y;
    }
    float inv = rsqrtf(1.f + BN_EPS);
    __half* op = g_out1h + (size_t)n * HC + lane;
#pragma unroll
    for (int h = 0; h < 4; h++) {
        float a = (h == 0) ? acc0 : (h == 1) ? acc1 : (h == 2) ? acc2 : acc3;
        float d = (h == 0) ? den0 : (h == 1) ? den1 : (h == 2) ? den2 : den3;
        int c = h * 32 + lane;
        float v = a / (d + 1e-16f) + b1[c];
        v = v * (g1[c] * inv) + be1[c];
        op[h * 32] = __float2half_rn(elu(v));
    }
}

// ---------------- GEMM2 (fp16 h1 in) + fused al2 ----------------
__global__ void gemm2_kernel(const float* __restrict__ W2, const float* __restrict__ as2,
                             const float* __restrict__ ad2) {
    __shared__ float Ws[HC * C1];
    for (int i = threadIdx.x; i < HC * C1; i += blockDim.x) Ws[i] = W2[i];
    __syncthreads();
    int node = blockIdx.x * 8 + threadIdx.x / 32;
    int lane = threadIdx.x & 31;
    if (node >= NN) return;
    const __half2* row2 = (const __half2*)(g_out1h + (size_t)node * HC);
    float s = 0.f;
#pragma unroll 8
    for (int k = 0; k < HC / 2; k++) {
        float2 r = __half22float2(row2[k]);
        s += r.x * Ws[(2 * k) * C1 + lane] + r.y * Ws[(2 * k + 1) * C1 + lane];
    }
    g_xs2[(size_t)node * C1 + lane] = s;
    g_xs2h[(size_t)node * C1 + lane] = __float2half_rn(s);

    float ps = s * as2[lane];
    float pd = s * ad2[lane];
#pragma unroll
    for (int off = 16; off > 0; off >>= 1) {
        ps += __shfl_xor_sync(0xffffffffu, ps, off);
        pd += __shfl_xor_sync(0xffffffffu, pd, off);
    }
    if (lane == 0) { g_als2[node] = ps; g_ald2[node] = pd; }
}

// ---------------- agg2: warp/node, inline weights, fp16 gathers + bn+elu + heads ----
__global__ void agg2_heads_kernel(const float* __restrict__ b2, const float* __restrict__ g2,
                                  const float* __restrict__ be2,
                                  const float* __restrict__ Wc1, const float* __restrict__ bc1,
                                  const float* __restrict__ Wc2, const float* __restrict__ bc2,
                                  const float* __restrict__ Wr1, const float* __restrict__ br1,
                                  const float* __restrict__ Wr2, const float* __restrict__ br2,
                                  float* __restrict__ out) {
    __shared__ float sWc1[C1 * 16], sWr1[C1 * 16];
    __shared__ float sWc2[32], sWr2[16];
    __shared__ float sbc1[16], sbr1[16], sbc2[2], sbr2v[1];
    __shared__ float sh[8][32];
    int t = threadIdx.x;
    for (int i = t; i < C1 * 16; i += blockDim.x) { sWc1[i] = Wc1[i]; sWr1[i] = Wr1[i]; }
    if (t < 32) sWc2[t] = Wc2[t];
    if (t < 16) { sWr2[t] = Wr2[t]; sbc1[t] = bc1[t]; sbr1[t] = br1[t]; }
    if (t < 2)  sbc2[t] = bc2[t];
    if (t == 32) sbr2v[0] = br2[0];
    __syncthreads();

    int wi   = t >> 5;
    int lane = t & 31;
    int n    = blockIdx.x * 8 + wi;
    if (n >= NN) return;
    int beg = g_rowptr[n], end = g_rowptr[n + 1];
    float ald = g_ald2[n];
    float k2  = g_k2;

    float den = 0.f, acc = 0.f;
    int e = beg;
    for (; e + 4 <= end; e += 4) {
#pragma unroll
        for (int q = 0; q < 4; q++) {
            int2 se = ((const int2*)&g_slot[e + q])[1];
            int s = se.x;
            float w = wexp(leaky(g_als2[s] + ald + k2 * __int_as_float(se.y)));
            acc += w * __half2float(g_xs2h[(size_t)s * C1 + lane]);
            den += w;
        }
    }
    for (; e < end; ++e) {
        int2 se = ((const int2*)&g_slot[e])[1];
        int s = se.x;
        float w = wexp(leaky(g_als2[s] + ald + k2 * __int_as_float(se.y)));
        acc += w * __half2float(g_xs2h[(size_t)s * C1 + lane]);
        den += w;
    }
    float v = acc / (den + 1e-16f) + b2[lane];
    v = v * (g2[lane] * rsqrtf(1.f + BN_EPS)) + be2[lane];
    float h = elu(v);
    out[3 * NN + (size_t)n * C1 + lane] = h;
    sh[wi][lane] = h;
    __syncwarp();

    int j = lane & 15;
    const float* W = (lane < 16) ? sWc1 : sWr1;
    float tt = (lane < 16) ? sbc1[j] : sbr1[j];
#pragma unroll
    for (int c = 0; c < C1; c++) tt += sh[wi][c] * W[c * 16 + j];
    tt = fmaxf(tt, 0.f);
    float pa = (lane < 16) ? tt * sWc2[j * 2 + 0] : tt * sWr2[j];
    float pb = (lane < 16) ? tt * sWc2[j * 2 + 1] : 0.f;
#pragma unroll
    for (int off = 8; off > 0; off >>= 1) {
        pa += __shfl_xor_sync(0xffffffffu, pa, off);
        pb += __shfl_xor_sync(0xffffffffu, pb, off);
    }
    if (lane == 0) {
        out[(size_t)n * 2 + 0] = pa + sbc2[0];
        out[(size_t)n * 2 + 1] = pb + sbc2[1];
    }
    if (lane == 16) {
        out[2 * NN + n] = pa + sbr2v[0];
    }
}

// ---------------- launch (stream-forked graph) ----------------
extern "C" void kernel_launch(void* const* d_in, const int* in_sizes, int n_in,
                              void* d_out, int out_size) {
    const float* x   = (const float*)d_in[0];
    const int*   ei  = (const int*)d_in[1];     // int32 (JAX x64 disabled)
    const float* ea  = (const float*)d_in[2];
    const float* W1  = (const float*)d_in[3];
    const float* as1 = (const float*)d_in[4];
    const float* ad1 = (const float*)d_in[5];
    const float* We1 = (const float*)d_in[6];
    const float* ae1 = (const float*)d_in[7];
    const float* b1  = (const float*)d_in[8];
    const float* g1  = (const float*)d_in[9];
    const float* be1 = (const float*)d_in[10];
    const float* W2  = (const float*)d_in[11];
    const float* as2 = (const float*)d_in[12];
    const float* ad2 = (const float*)d_in[13];
    const float* We2 = (const float*)d_in[14];
    const float* ae2 = (const float*)d_in[15];
    const float* b2  = (const float*)d_in[16];
    const float* g2  = (const float*)d_in[17];
    const float* be2 = (const float*)d_in[18];
    const float* Wc1 = (const float*)d_in[19];
    const float* bc1 = (const float*)d_in[20];
    const float* Wc2 = (const float*)d_in[21];
    const float* bc2 = (const float*)d_in[22];
    const float* Wr1 = (const float*)d_in[23];
    const float* br1 = (const float*)d_in[24];
    const float* Wr2 = (const float*)d_in[25];
    const float* br2 = (const float*)d_in[26];
    float* out = (float*)d_out;

    cudaStream_t sB;
    cudaStreamCreateWithFlags(&sB, cudaStreamNonBlocking);
    cudaEvent_t eFork, eJoin;
    cudaEventCreateWithFlags(&eFork, cudaEventDisableTiming);
    cudaEventCreateWithFlags(&eJoin, cudaEventDisableTiming);

    cudaEventRecord(eFork, 0);
    cudaStreamWaitEvent(sB, eFork, 0);

    // Branch B (CSR + scatter permutation)
    init_deg_kernel<<<(NN + 255) / 256, 256, 0, sB>>>();
    hist_mean_kernel<<<512, 256, 0, sB>>>(ei, ea);
    mean_fin_kernel<<<1, 512, 0, sB>>>(We1, ae1, We2, ae2);
    scan_part_kernel<<<NB, 256, 0, sB>>>();
    scan_mid_kernel<<<1, 256, 0, sB>>>();
    scan_fin_kernel<<<NB, 256, 0, sB>>>();
    scatter_perm_kernel<<<2048, 256, 0, sB>>>(ei, ea);

    // Branch A (fp16 GEMM1 chain) on main stream
    convW1_kernel<<<(INC * HC / 8 + 255) / 256, 256>>>(W1);
    sgemm1_wmma<<<(NN + 127) / 128, 256>>>(x);
    post1_kernel<<<(NN * 2 + 255) / 256, 256>>>(as1, ad1);

    cudaEventRecord(eJoin, sB);
    cudaStreamWaitEvent(0, eJoin, 0);

    // Joined tail on main stream
    logits1_kernel<<<(NN + 7) / 8, 256>>>();
    agg1_kernel<<<(NN + 7) / 8, 256>>>(b1, g1, be1);
    gemm2_kernel<<<(NN + 7) / 8, 256>>>(W2, as2, ad2);
    agg2_heads_kernel<<<(NN + 7) / 8, 256>>>(b2, g2, be2,
        Wc1, bc1, Wc2, bc2, Wr1, br1, Wr2, br2, out);

    cudaEventDestroy(eFork);
    cudaEventDestroy(eJoin);
    // sB intentionally not destroyed during capture.
}

// round 14
// speedup vs baseline: 1.5793x; 1.0637x over previous
#include <cuda_runtime.h>
#include <cuda_fp16.h>
#include <mma.h>
#include <math.h>

using namespace nvcuda;

#define NN   50000
#define EE   1600000
#define ET   (EE + NN)
#define INC  256
#define HC   128
#define H1   4
#define C1   32
#define BN_EPS 1e-5f
#define NB   196            // ceil(NN/256)
#define NROWS 50048         // 391*128, padded rows for GEMM1 stores

// ---------------- scratch ----------------
__device__ __half  g_W1h [INC * HC];     // fp16 W1
__device__ float   g_xs1 [NROWS * HC];   // fp32 GEMM1 out (padded)
__device__ uint2   g_xs1q[NN * 32];      // quad mirror: [n][c] = (x[c],x[c+32] | x[c+64],x[c+96])
__device__ __half  g_out1h[NN * HC];     // fp16 h1
__device__ float   g_xs2 [NN * C1];
__device__ __half  g_xs2h[NN * C1];
__device__ float   g_als1[NN * H1];
__device__ float   g_ald1[NN * H1];
__device__ float   g_als2[NN];
__device__ float   g_ald2[NN];
__device__ int     g_deg   [NN];
__device__ int     g_rowptr[NN + 1];
__device__ int     g_cursor[NN];
__device__ int     g_bsum[NB];
__device__ int     g_boff[NB];
__device__ int2    g_slot[ET];           // 8B: (src, ea bits)
__device__ float   g_partial[512];
__device__ float   g_mean;
__device__ float   g_k1v[H1];
__device__ float   g_k2;

// ---------------- helpers ----------------
__device__ __forceinline__ unsigned h2u(__half2 h) { return *(unsigned*)&h; }
__device__ __forceinline__ float leaky(float x) { return x > 0.f ? x : 0.2f * x; }
__device__ __forceinline__ float elu(float x)   { return x > 0.f ? x : expm1f(x); }
__device__ __forceinline__ float wexp(float x)  { return __expf(fminf(x, 80.f)); }

// ---------------- fp16 W1 conversion ----------------
__global__ void convW1_kernel(const float* __restrict__ W1) {
    int i = blockIdx.x * blockDim.x + threadIdx.x;
    if (i >= INC * HC / 8) return;
    const float4* p = (const float4*)W1 + (size_t)i * 2;
    float4 a = p[0], b = p[1];
    uint4 u;
    u.x = h2u(__floats2half2_rn(a.x, a.y));
    u.y = h2u(__floats2half2_rn(a.z, a.w));
    u.z = h2u(__floats2half2_rn(b.x, b.y));
    u.w = h2u(__floats2half2_rn(b.z, b.w));
    ((uint4*)g_W1h)[i] = u;
}

// ---------------- GEMM1: wmma fp16->fp32, converts x fp32->fp16 in-flight ----------
__global__ void __launch_bounds__(256) sgemm1_wmma(const float* __restrict__ x) {
    __shared__ __align__(32) __half As[128][32];    // ld=32
    __shared__ __align__(32) __half Bs[16][144];    // ld=144
    int tid = threadIdx.x;
    int w = tid >> 5, wr = w >> 1, wc = w & 1;
    int brow = blockIdx.x;

    wmma::fragment<wmma::accumulator, 16, 16, 16, float> cf[2][4];
#pragma unroll
    for (int mi = 0; mi < 2; mi++)
#pragma unroll
        for (int ni = 0; ni < 4; ni++) wmma::fill_fragment(cf[mi][ni], 0.f);

    int rA = tid >> 1, segA = (tid & 1) * 8;
    int ag = brow * 128 + rA;
    int qB = tid >> 4, cB = (tid & 15) * 8;

    for (int k0 = 0; k0 < INC; k0 += 16) {
        uint4 ua = make_uint4(0, 0, 0, 0);
        if (ag < NN) {
            const float* xp = x + (size_t)ag * INC + k0 + segA;
            float4 f0 = *(const float4*)(xp);
            float4 f1 = *(const float4*)(xp + 4);
            ua.x = h2u(__floats2half2_rn(f0.x, f0.y));
            ua.y = h2u(__floats2half2_rn(f0.z, f0.w));
            ua.z = h2u(__floats2half2_rn(f1.x, f1.y));
            ua.w = h2u(__floats2half2_rn(f1.z, f1.w));
        }
        *(uint4*)&As[rA][segA] = ua;
        *(uint4*)&Bs[qB][cB] = *(const uint4*)(g_W1h + (size_t)(k0 + qB) * HC + cB);
        __syncthreads();

        wmma::fragment<wmma::matrix_b, 16, 16, 16, __half, wmma::row_major> bf[4];
#pragma unroll
        for (int ni = 0; ni < 4; ni++)
            wmma::load_matrix_sync(bf[ni], &Bs[0][wc * 64 + ni * 16], 144);
#pragma unroll
        for (int mi = 0; mi < 2; mi++) {
            wmma::fragment<wmma::matrix_a, 16, 16, 16, __half, wmma::row_major> af;
            wmma::load_matrix_sync(af, &As[wr * 32 + mi * 16][0], 32);
#pragma unroll
            for (int ni = 0; ni < 4; ni++)
                wmma::mma_sync(cf[mi][ni], af, bf[ni], cf[mi][ni]);
        }
        __syncthreads();
    }
#pragma unroll
    for (int mi = 0; mi < 2; mi++)
#pragma unroll
        for (int ni = 0; ni < 4; ni++)
            wmma::store_matrix_sync(
                g_xs1 + (size_t)(brow * 128 + wr * 32 + mi * 16) * HC + wc * 64 + ni * 16,
                cf[mi][ni], HC, wmma::mem_row_major);
}

// ---------------- post1: al1 dots + quad-packed mirror; 2 threads/node --------------
__global__ void post1_kernel(const float* __restrict__ as1, const float* __restrict__ ad1) {
    int idx = blockIdx.x * blockDim.x + threadIdx.x;
    if (idx >= NN * 2) return;
    int n = idx >> 1, q = idx & 1;          // q selects channels [q*16, q*16+16)
    const float* base = g_xs1 + (size_t)n * HC;

    float4 v[4][4];
    float s[4], d[4];
#pragma unroll
    for (int h = 0; h < 4; h++) {
        s[h] = 0.f; d[h] = 0.f;
#pragma unroll
        for (int g = 0; g < 4; g++) {
            int off = h * 32 + q * 16 + g * 4;
            float4 xv = *(const float4*)(base + off);
            float4 av = *(const float4*)(as1 + off);
            float4 dv = *(const float4*)(ad1 + off);
            v[h][g] = xv;
            s[h] += xv.x * av.x + xv.y * av.y + xv.z * av.z + xv.w * av.w;
            d[h] += xv.x * dv.x + xv.y * dv.y + xv.z * dv.z + xv.w * dv.w;
        }
    }
    // quad-pack: channel c = q*16 + g*4 + k  ->  (x[c],x[c+32] | x[c+64],x[c+96])
    uint2* op = g_xs1q + (size_t)n * 32 + q * 16;
#pragma unroll
    for (int g = 0; g < 4; g++) {
        float4 h0 = v[0][g], h1 = v[1][g], h2v = v[2][g], h3 = v[3][g];
        op[g * 4 + 0] = make_uint2(h2u(__floats2half2_rn(h0.x, h1.x)),
                                   h2u(__floats2half2_rn(h2v.x, h3.x)));
        op[g * 4 + 1] = make_uint2(h2u(__floats2half2_rn(h0.y, h1.y)),
                                   h2u(__floats2half2_rn(h2v.y, h3.y)));
        op[g * 4 + 2] = make_uint2(h2u(__floats2half2_rn(h0.z, h1.z)),
                                   h2u(__floats2half2_rn(h2v.z, h3.z)));
        op[g * 4 + 3] = make_uint2(h2u(__floats2half2_rn(h0.w, h1.w)),
                                   h2u(__floats2half2_rn(h2v.w, h3.w)));
    }
    // combine partner partials (threads 2n / 2n+1 are adjacent lanes)
#pragma unroll
    for (int h = 0; h < 4; h++) {
        s[h] += __shfl_xor_sync(0xffffffffu, s[h], 1);
        d[h] += __shfl_xor_sync(0xffffffffu, d[h], 1);
    }
    if (q == 0) {
#pragma unroll
        for (int h = 0; h < 4; h++) {
            g_als1[n * 4 + h] = s[h];
            g_ald1[n * 4 + h] = d[h];
        }
    }
}

// ---------------- CSR build (branch B) ----------------
__global__ void init_deg_kernel() {
    int i = blockIdx.x * blockDim.x + threadIdx.x;
    if (i < NN) g_deg[i] = 1;
}

__global__ void hist_mean_kernel(const int* __restrict__ ei, const float* __restrict__ ea) {
    __shared__ float s[256];
    float v = 0.f;
    for (int e = blockIdx.x * blockDim.x + threadIdx.x; e < EE; e += gridDim.x * blockDim.x) {
        atomicAdd(&g_deg[ei[EE + e]], 1);
        v += ea[e];
    }
    s[threadIdx.x] = v; __syncthreads();
    for (int o = 128; o > 0; o >>= 1) {
        if (threadIdx.x < o) s[threadIdx.x] += s[threadIdx.x + o];
        __syncthreads();
    }
    if (threadIdx.x == 0) g_partial[blockIdx.x] = s[0];
}

__global__ void mean_fin_kernel(const float* __restrict__ We1, const float* __restrict__ ae1,
                                const float* __restrict__ We2, const float* __restrict__ ae2) {
    __shared__ float s[512];
    int t = threadIdx.x;
    s[t] = g_partial[t]; __syncthreads();
    for (int o = 256; o > 0; o >>= 1) {
        if (t < o) s[t] += s[t + o];
        __syncthreads();
    }
    if (t == 0) g_mean = s[0] / (float)EE;
    if (t < H1) {
        float k = 0.f;
        for (int c = 0; c < C1; c++) k += We1[t * C1 + c] * ae1[t * C1 + c];
        g_k1v[t] = k;
    }
    if (t == H1) {
        float k = 0.f;
        for (int c = 0; c < C1; c++) k += We2[c] * ae2[c];
        g_k2 = k;
    }
}

__global__ void scan_part_kernel() {
    __shared__ int s[256];
    int t = threadIdx.x, b = blockIdx.x;
    int i = b * 256 + t;
    int v = (i < NN) ? g_deg[i] : 0;
    s[t] = v; __syncthreads();
    for (int o = 128; o > 0; o >>= 1) {
        if (t < o) s[t] += s[t + o];
        __syncthreads();
    }
    if (t == 0) g_bsum[b] = s[0];
}

__global__ void scan_mid_kernel() {
    __shared__ int s[256];
    int t = threadIdx.x;
    int v = (t < NB) ? g_bsum[t] : 0;
    s[t] = v; __syncthreads();
    for (int o = 1; o < 256; o <<= 1) {
        int u = (t >= o) ? s[t - o] : 0;
        __syncthreads();
        s[t] += u;
        __syncthreads();
    }
    if (t < NB) g_boff[t] = s[t] - v;
}

__global__ void scan_fin_kernel() {
    __shared__ int s[256];
    int t = threadIdx.x, b = blockIdx.x;
    int i = b * 256 + t;
    int v = (i < NN) ? g_deg[i] : 0;
    s[t] = v; __syncthreads();
    for (int o = 1; o < 256; o <<= 1) {
        int u = (t >= o) ? s[t - o] : 0;
        __syncthreads();
        s[t] += u;
        __syncthreads();
    }
    int excl = s[t] - v + g_boff[b];
    if (i < NN) { g_rowptr[i] = excl; g_cursor[i] = excl; }
    if (b == 0 && t == 0) g_rowptr[NN] = ET;
}

// ---------------- scatter: (src, ea) into 8B slots ----------------
__global__ void scatter_perm_kernel(const int* __restrict__ ei, const float* __restrict__ ea) {
    float mn = g_mean;
    for (int idx = blockIdx.x * blockDim.x + threadIdx.x; idx < ET; idx += gridDim.x * blockDim.x) {
        int srcn, dstn; float eav;
        if (idx < EE) {
            srcn = ei[idx];
            dstn = ei[EE + idx];
            eav  = ea[idx];
        } else {
            srcn = dstn = idx - EE;
            eav  = mn;
        }
        int slot = atomicAdd(&g_cursor[dstn], 1);
        g_slot[slot] = make_int2(srcn, __float_as_int(eav));
    }
}

// ---------------- agg1: warp/node, fused logits (smem staged) + quad gathers -------
__global__ void agg1_kernel(const float* __restrict__ b1, const float* __restrict__ g1,
                            const float* __restrict__ be1) {
    __shared__ float4 sw[8][32];
    __shared__ int    ssrc[8][32];
    int wi   = threadIdx.x >> 5;
    int lane = threadIdx.x & 31;
    int n    = blockIdx.x * 8 + wi;
    if (n >= NN) return;
    int beg = g_rowptr[n], end = g_rowptr[n + 1];
    float4 ald = *(const float4*)(g_ald1 + n * 4);    // uniform broadcast
    float k0 = g_k1v[0], k1 = g_k1v[1], k2 = g_k1v[2], k3 = g_k1v[3];

    float acc0 = 0.f, acc1 = 0.f, acc2 = 0.f, acc3 = 0.f;
    float den0 = 0.f, den1 = 0.f, den2 = 0.f, den3 = 0.f;

    for (int c0 = beg; c0 < end; c0 += 32) {
        int m = end - c0; if (m > 32) m = 32;
        if (lane < m) {
            int2 se = g_slot[c0 + lane];
            float4 als = *(const float4*)(g_als1 + se.x * 4);
            float eav = __int_as_float(se.y);
            float4 w;
            w.x = wexp(leaky(als.x + ald.x + k0 * eav));
            w.y = wexp(leaky(als.y + ald.y + k1 * eav));
            w.z = wexp(leaky(als.z + ald.z + k2 * eav));
            w.w = wexp(leaky(als.w + ald.w + k3 * eav));
            sw[wi][lane] = w;
            ssrc[wi][lane] = se.x;
        }
        __syncwarp();
        for (int i = 0; i < m; i++) {
            float4 w = sw[wi][i];
            int s = ssrc[wi][i];
            uint2 xv = g_xs1q[(size_t)s * 32 + lane];
            float2 x01 = __half22float2(*(__half2*)&xv.x);   // (head0, head1)
            float2 x23 = __half22float2(*(__half2*)&xv.y);   // (head2, head3)
            acc0 += w.x * x01.x;  den0 += w.x;
            acc1 += w.y * x01.y;  den1 += w.y;
            acc2 += w.z * x23.x;  den2 += w.z;
            acc3 += w.w * x23.y;  den3 += w.w;
        }
        __syncwarp();
    }
    float inv = rsqrtf(1.f + BN_EPS);
    __half* op = g_out1h + (size_t)n * HC + lane;
#pragma unroll
    for (int h = 0; h < 4; h++) {
        float a = (h == 0) ? acc0 : (h == 1) ? acc1 : (h == 2) ? acc2 : acc3;
        float d = (h == 0) ? den0 : (h == 1) ? den1 : (h == 2) ? den2 : den3;
        int c = h * 32 + lane;
        float v = a / (d + 1e-16f) + b1[c];
        v = v * (g1[c] * inv) + be1[c];
        op[h * 32] = __float2half_rn(elu(v));
    }
}

// ---------------- GEMM2 (fp16 h1 in) + fused al2 ----------------
__global__ void gemm2_kernel(const float* __restrict__ W2, const float* __restrict__ as2,
                             const float* __restrict__ ad2) {
    __shared__ float Ws[HC * C1];
    for (int i = threadIdx.x; i < HC * C1; i += blockDim.x) Ws[i] = W2[i];
    __syncthreads();
    int node = blockIdx.x * 8 + threadIdx.x / 32;
    int lane = threadIdx.x & 31;
    if (node >= NN) return;
    const __half2* row2 = (const __half2*)(g_out1h + (size_t)node * HC);
    float s = 0.f;
#pragma unroll 8
    for (int k = 0; k < HC / 2; k++) {
        float2 r = __half22float2(row2[k]);
        s += r.x * Ws[(2 * k) * C1 + lane] + r.y * Ws[(2 * k + 1) * C1 + lane];
    }
    g_xs2[(size_t)node * C1 + lane] = s;
    g_xs2h[(size_t)node * C1 + lane] = __float2half_rn(s);

    float ps = s * as2[lane];
    float pd = s * ad2[lane];
#pragma unroll
    for (int off = 16; off > 0; off >>= 1) {
        ps += __shfl_xor_sync(0xffffffffu, ps, off);
        pd += __shfl_xor_sync(0xffffffffu, pd, off);
    }
    if (lane == 0) { g_als2[node] = ps; g_ald2[node] = pd; }
}

// ---------------- agg2: warp/node, inline weights, fp16 gathers + bn+elu + heads ----
__global__ void agg2_heads_kernel(const float* __restrict__ b2, const float* __restrict__ g2,
                                  const float* __restrict__ be2,
                                  const float* __restrict__ Wc1, const float* __restrict__ bc1,
                                  const float* __restrict__ Wc2, const float* __restrict__ bc2,
                                  const float* __restrict__ Wr1, const float* __restrict__ br1,
                                  const float* __restrict__ Wr2, const float* __restrict__ br2,
                                  float* __restrict__ out) {
    __shared__ float sWc1[C1 * 16], sWr1[C1 * 16];
    __shared__ float sWc2[32], sWr2[16];
    __shared__ float sbc1[16], sbr1[16], sbc2[2], sbr2v[1];
    __shared__ float sh[8][32];
    int t = threadIdx.x;
    for (int i = t; i < C1 * 16; i += blockDim.x) { sWc1[i] = Wc1[i]; sWr1[i] = Wr1[i]; }
    if (t < 32) sWc2[t] = Wc2[t];
    if (t < 16) { sWr2[t] = Wr2[t]; sbc1[t] = bc1[t]; sbr1[t] = br1[t]; }
    if (t < 2)  sbc2[t] = bc2[t];
    if (t == 32) sbr2v[0] = br2[0];
    __syncthreads();

    int wi   = t >> 5;
    int lane = t & 31;
    int n    = blockIdx.x * 8 + wi;
    if (n >= NN) return;
    int beg = g_rowptr[n], end = g_rowptr[n + 1];
    float ald = g_ald2[n];
    float k2  = g_k2;

    float den = 0.f, acc = 0.f;
    int e = beg;
    for (; e + 4 <= end; e += 4) {
#pragma unroll
        for (int q = 0; q < 4; q++) {
            int2 se = g_slot[e + q];
            int s = se.x;
            float w = wexp(leaky(g_als2[s] + ald + k2 * __int_as_float(se.y)));
            acc += w * __half2float(g_xs2h[(size_t)s * C1 + lane]);
            den += w;
        }
    }
    for (; e < end; ++e) {
        int2 se = g_slot[e];
        int s = se.x;
        float w = wexp(leaky(g_als2[s] + ald + k2 * __int_as_float(se.y)));
        acc += w * __half2float(g_xs2h[(size_t)s * C1 + lane]);
        den += w;
    }
    float v = acc / (den + 1e-16f) + b2[lane];
    v = v * (g2[lane] * rsqrtf(1.f + BN_EPS)) + be2[lane];
    float h = elu(v);
    out[3 * NN + (size_t)n * C1 + lane] = h;
    sh[wi][lane] = h;
    __syncwarp();

    int j = lane & 15;
    const float* W = (lane < 16) ? sWc1 : sWr1;
    float tt = (lane < 16) ? sbc1[j] : sbr1[j];
#pragma unroll
    for (int c = 0; c < C1; c++) tt += sh[wi][c] * W[c * 16 + j];
    tt = fmaxf(tt, 0.f);
    float pa = (lane < 16) ? tt * sWc2[j * 2 + 0] : tt * sWr2[j];
    float pb = (lane < 16) ? tt * sWc2[j * 2 + 1] : 0.f;
#pragma unroll
    for (int off = 8; off > 0; off >>= 1) {
        pa += __shfl_xor_sync(0xffffffffu, pa, off);
        pb += __shfl_xor_sync(0xffffffffu, pb, off);
    }
    if (lane == 0) {
        out[(size_t)n * 2 + 0] = pa + sbc2[0];
        out[(size_t)n * 2 + 1] = pb + sbc2[1];
    }
    if (lane == 16) {
        out[2 * NN + n] = pa + sbr2v[0];
    }
}

// ---------------- launch (stream-forked graph) ----------------
extern "C" void kernel_launch(void* const* d_in, const int* in_sizes, int n_in,
                              void* d_out, int out_size) {
    const float* x   = (const float*)d_in[0];
    const int*   ei  = (const int*)d_in[1];     // int32 (JAX x64 disabled)
    const float* ea  = (const float*)d_in[2];
    const float* W1  = (const float*)d_in[3];
    const float* as1 = (const float*)d_in[4];
    const float* ad1 = (const float*)d_in[5];
    const float* We1 = (const float*)d_in[6];
    const float* ae1 = (const float*)d_in[7];
    const float* b1  = (const float*)d_in[8];
    const float* g1  = (const float*)d_in[9];
    const float* be1 = (const float*)d_in[10];
    const float* W2  = (const float*)d_in[11];
    const float* as2 = (const float*)d_in[12];
    const float* ad2 = (const float*)d_in[13];
    const float* We2 = (const float*)d_in[14];
    const float* ae2 = (const float*)d_in[15];
    const float* b2  = (const float*)d_in[16];
    const float* g2  = (const float*)d_in[17];
    const float* be2 = (const float*)d_in[18];
    const float* Wc1 = (const float*)d_in[19];
    const float* bc1 = (const float*)d_in[20];
    const float* Wc2 = (const float*)d_in[21];
    const float* bc2 = (const float*)d_in[22];
    const float* Wr1 = (const float*)d_in[23];
    const float* br1 = (const float*)d_in[24];
    const float* Wr2 = (const float*)d_in[25];
    const float* br2 = (const float*)d_in[26];
    float* out = (float*)d_out;

    cudaStream_t sB;
    cudaStreamCreateWithFlags(&sB, cudaStreamNonBlocking);
    cudaEvent_t eFork, eJoin;
    cudaEventCreateWithFlags(&eFork, cudaEventDisableTiming);
    cudaEventCreateWithFlags(&eJoin, cudaEventDisableTiming);

    cudaEventRecord(eFork, 0);
    cudaStreamWaitEvent(sB, eFork, 0);

    // Branch B (CSR + scatter permutation)
    init_deg_kernel<<<(NN + 255) / 256, 256, 0, sB>>>();
    hist_mean_kernel<<<512, 256, 0, sB>>>(ei, ea);
    mean_fin_kernel<<<1, 512, 0, sB>>>(We1, ae1, We2, ae2);
    scan_part_kernel<<<NB, 256, 0, sB>>>();
    scan_mid_kernel<<<1, 256, 0, sB>>>();
    scan_fin_kernel<<<NB, 256, 0, sB>>>();
    scatter_perm_kernel<<<2048, 256, 0, sB>>>(ei, ea);

    // Branch A (fp16 GEMM1 chain) on main stream
    convW1_kernel<<<(INC * HC / 8 + 255) / 256, 256>>>(W1);
    sgemm1_wmma<<<(NN + 127) / 128, 256>>>(x);
    post1_kernel<<<(NN * 2 + 255) / 256, 256>>>(as1, ad1);

    cudaEventRecord(eJoin, sB);
    cudaStreamWaitEvent(0, eJoin, 0);

    // Joined tail on main stream
    agg1_kernel<<<(NN + 7) / 8, 256>>>(b1, g1, be1);
    gemm2_kernel<<<(NN + 7) / 8, 256>>>(W2, as2, ad2);
    agg2_heads_kernel<<<(NN + 7) / 8, 256>>>(b2, g2, be2,
        Wc1, bc1, Wc2, bc2, Wr1, br1, Wr2, br2, out);

    cudaEventDestroy(eFork);
    cudaEventDestroy(eJoin);
    // sB intentionally not destroyed during capture.
}

// round 15
// speedup vs baseline: 1.7735x; 1.1230x over previous
#include <cuda_runtime.h>
#include <cuda_fp16.h>
#include <mma.h>
#include <math.h>

using namespace nvcuda;

#define NN   50000
#define EE   1600000
#define ET   (EE + NN)
#define INC  256
#define HC   128
#define H1   4
#define C1   32
#define BN_EPS 1e-5f
#define NB   196            // ceil(NN/256)
#define NROWS 50048         // 391*128, padded rows for GEMM1 stores

// ---------------- scratch ----------------
__device__ __half  g_W1h [INC * HC];     // fp16 W1
__device__ float   g_xs1 [NROWS * HC];   // fp32 GEMM1 out (padded)
__device__ uint2   g_xs1q[NN * 32];      // quad mirror: [n][c] = (x[c],x[c+32] | x[c+64],x[c+96])
__device__ __half  g_xs2h[NN * C1];
__device__ float   g_als1[NN * H1];
__device__ float   g_ald1[NN * H1];
__device__ float   g_als2[NN];
__device__ float   g_ald2[NN];
__device__ int     g_deg   [NN];
__device__ int     g_rowptr[NN + 1];
__device__ int     g_cursor[NN];
__device__ int     g_bsum[NB];
__device__ int     g_boff[NB];
__device__ int2    g_slot[ET];           // 8B: (src, ea bits)
__device__ float   g_partial[512];
__device__ float   g_mean;
__device__ float   g_k1v[H1];
__device__ float   g_k2;

// ---------------- helpers ----------------
__device__ __forceinline__ unsigned h2u(__half2 h) { return *(unsigned*)&h; }
__device__ __forceinline__ float leaky(float x) { return x > 0.f ? x : 0.2f * x; }
__device__ __forceinline__ float elu(float x)   { return x > 0.f ? x : expm1f(x); }
__device__ __forceinline__ float wexp(float x)  { return __expf(fminf(x, 80.f)); }

// ---------------- fp16 W1 conversion ----------------
__global__ void convW1_kernel(const float* __restrict__ W1) {
    int i = blockIdx.x * blockDim.x + threadIdx.x;
    if (i >= INC * HC / 8) return;
    const float4* p = (const float4*)W1 + (size_t)i * 2;
    float4 a = p[0], b = p[1];
    uint4 u;
    u.x = h2u(__floats2half2_rn(a.x, a.y));
    u.y = h2u(__floats2half2_rn(a.z, a.w));
    u.z = h2u(__floats2half2_rn(b.x, b.y));
    u.w = h2u(__floats2half2_rn(b.z, b.w));
    ((uint4*)g_W1h)[i] = u;
}

// ---------------- GEMM1: wmma fp16->fp32, converts x fp32->fp16 in-flight ----------
__global__ void __launch_bounds__(256) sgemm1_wmma(const float* __restrict__ x) {
    __shared__ __align__(32) __half As[128][32];    // ld=32
    __shared__ __align__(32) __half Bs[16][144];    // ld=144
    int tid = threadIdx.x;
    int w = tid >> 5, wr = w >> 1, wc = w & 1;
    int brow = blockIdx.x;

    wmma::fragment<wmma::accumulator, 16, 16, 16, float> cf[2][4];
#pragma unroll
    for (int mi = 0; mi < 2; mi++)
#pragma unroll
        for (int ni = 0; ni < 4; ni++) wmma::fill_fragment(cf[mi][ni], 0.f);

    int rA = tid >> 1, segA = (tid & 1) * 8;
    int ag = brow * 128 + rA;
    int qB = tid >> 4, cB = (tid & 15) * 8;

    for (int k0 = 0; k0 < INC; k0 += 16) {
        uint4 ua = make_uint4(0, 0, 0, 0);
        if (ag < NN) {
            const float* xp = x + (size_t)ag * INC + k0 + segA;
            float4 f0 = *(const float4*)(xp);
            float4 f1 = *(const float4*)(xp + 4);
            ua.x = h2u(__floats2half2_rn(f0.x, f0.y));
            ua.y = h2u(__floats2half2_rn(f0.z, f0.w));
            ua.z = h2u(__floats2half2_rn(f1.x, f1.y));
            ua.w = h2u(__floats2half2_rn(f1.z, f1.w));
        }
        *(uint4*)&As[rA][segA] = ua;
        *(uint4*)&Bs[qB][cB] = *(const uint4*)(g_W1h + (size_t)(k0 + qB) * HC + cB);
        __syncthreads();

        wmma::fragment<wmma::matrix_b, 16, 16, 16, __half, wmma::row_major> bf[4];
#pragma unroll
        for (int ni = 0; ni < 4; ni++)
            wmma::load_matrix_sync(bf[ni], &Bs[0][wc * 64 + ni * 16], 144);
#pragma unroll
        for (int mi = 0; mi < 2; mi++) {
            wmma::fragment<wmma::matrix_a, 16, 16, 16, __half, wmma::row_major> af;
            wmma::load_matrix_sync(af, &As[wr * 32 + mi * 16][0], 32);
#pragma unroll
            for (int ni = 0; ni < 4; ni++)
                wmma::mma_sync(cf[mi][ni], af, bf[ni], cf[mi][ni]);
        }
        __syncthreads();
    }
#pragma unroll
    for (int mi = 0; mi < 2; mi++)
#pragma unroll
        for (int ni = 0; ni < 4; ni++)
            wmma::store_matrix_sync(
                g_xs1 + (size_t)(brow * 128 + wr * 32 + mi * 16) * HC + wc * 64 + ni * 16,
                cf[mi][ni], HC, wmma::mem_row_major);
}

// ---------------- post1: al1 dots + quad-packed mirror; 2 threads/node --------------
__global__ void post1_kernel(const float* __restrict__ as1, const float* __restrict__ ad1) {
    int idx = blockIdx.x * blockDim.x + threadIdx.x;
    if (idx >= NN * 2) return;
    int n = idx >> 1, q = idx & 1;          // q selects channels [q*16, q*16+16)
    const float* base = g_xs1 + (size_t)n * HC;

    float4 v[4][4];
    float s[4], d[4];
#pragma unroll
    for (int h = 0; h < 4; h++) {
        s[h] = 0.f; d[h] = 0.f;
#pragma unroll
        for (int g = 0; g < 4; g++) {
            int off = h * 32 + q * 16 + g * 4;
            float4 xv = *(const float4*)(base + off);
            float4 av = *(const float4*)(as1 + off);
            float4 dv = *(const float4*)(ad1 + off);
            v[h][g] = xv;
            s[h] += xv.x * av.x + xv.y * av.y + xv.z * av.z + xv.w * av.w;
            d[h] += xv.x * dv.x + xv.y * dv.y + xv.z * dv.z + xv.w * dv.w;
        }
    }
    uint2* op = g_xs1q + (size_t)n * 32 + q * 16;
#pragma unroll
    for (int g = 0; g < 4; g++) {
        float4 h0 = v[0][g], h1 = v[1][g], h2v = v[2][g], h3 = v[3][g];
        op[g * 4 + 0] = make_uint2(h2u(__floats2half2_rn(h0.x, h1.x)),
                                   h2u(__floats2half2_rn(h2v.x, h3.x)));
        op[g * 4 + 1] = make_uint2(h2u(__floats2half2_rn(h0.y, h1.y)),
                                   h2u(__floats2half2_rn(h2v.y, h3.y)));
        op[g * 4 + 2] = make_uint2(h2u(__floats2half2_rn(h0.z, h1.z)),
                                   h2u(__floats2half2_rn(h2v.z, h3.z)));
        op[g * 4 + 3] = make_uint2(h2u(__floats2half2_rn(h0.w, h1.w)),
                                   h2u(__floats2half2_rn(h2v.w, h3.w)));
    }
#pragma unroll
    for (int h = 0; h < 4; h++) {
        s[h] += __shfl_xor_sync(0xffffffffu, s[h], 1);
        d[h] += __shfl_xor_sync(0xffffffffu, d[h], 1);
    }
    if (q == 0) {
#pragma unroll
        for (int h = 0; h < 4; h++) {
            g_als1[n * 4 + h] = s[h];
            g_ald1[n * 4 + h] = d[h];
        }
    }
}

// ---------------- CSR build (branch B) ----------------
__global__ void init_deg_kernel() {
    int i = blockIdx.x * blockDim.x + threadIdx.x;
    if (i < NN) g_deg[i] = 1;
}

__global__ void hist_mean_kernel(const int* __restrict__ ei, const float* __restrict__ ea) {
    __shared__ float s[256];
    float v = 0.f;
    for (int e = blockIdx.x * blockDim.x + threadIdx.x; e < EE; e += gridDim.x * blockDim.x) {
        atomicAdd(&g_deg[ei[EE + e]], 1);
        v += ea[e];
    }
    s[threadIdx.x] = v; __syncthreads();
    for (int o = 128; o > 0; o >>= 1) {
        if (threadIdx.x < o) s[threadIdx.x] += s[threadIdx.x + o];
        __syncthreads();
    }
    if (threadIdx.x == 0) g_partial[blockIdx.x] = s[0];
}

__global__ void mean_fin_kernel(const float* __restrict__ We1, const float* __restrict__ ae1,
                                const float* __restrict__ We2, const float* __restrict__ ae2) {
    __shared__ float s[512];
    int t = threadIdx.x;
    s[t] = g_partial[t]; __syncthreads();
    for (int o = 256; o > 0; o >>= 1) {
        if (t < o) s[t] += s[t + o];
        __syncthreads();
    }
    if (t == 0) g_mean = s[0] / (float)EE;
    if (t < H1) {
        float k = 0.f;
        for (int c = 0; c < C1; c++) k += We1[t * C1 + c] * ae1[t * C1 + c];
        g_k1v[t] = k;
    }
    if (t == H1) {
        float k = 0.f;
        for (int c = 0; c < C1; c++) k += We2[c] * ae2[c];
        g_k2 = k;
    }
}

__global__ void scan_part_kernel() {
    __shared__ int s[256];
    int t = threadIdx.x, b = blockIdx.x;
    int i = b * 256 + t;
    int v = (i < NN) ? g_deg[i] : 0;
    s[t] = v; __syncthreads();
    for (int o = 128; o > 0; o >>= 1) {
        if (t < o) s[t] += s[t + o];
        __syncthreads();
    }
    if (t == 0) g_bsum[b] = s[0];
}

__global__ void scan_mid_kernel() {
    __shared__ int s[256];
    int t = threadIdx.x;
    int v = (t < NB) ? g_bsum[t] : 0;
    s[t] = v; __syncthreads();
    for (int o = 1; o < 256; o <<= 1) {
        int u = (t >= o) ? s[t - o] : 0;
        __syncthreads();
        s[t] += u;
        __syncthreads();
    }
    if (t < NB) g_boff[t] = s[t] - v;
}

__global__ void scan_fin_kernel() {
    __shared__ int s[256];
    int t = threadIdx.x, b = blockIdx.x;
    int i = b * 256 + t;
    int v = (i < NN) ? g_deg[i] : 0;
    s[t] = v; __syncthreads();
    for (int o = 1; o < 256; o <<= 1) {
        int u = (t >= o) ? s[t - o] : 0;
        __syncthreads();
        s[t] += u;
        __syncthreads();
    }
    int excl = s[t] - v + g_boff[b];
    if (i < NN) { g_rowptr[i] = excl; g_cursor[i] = excl; }
    if (b == 0 && t == 0) g_rowptr[NN] = ET;
}

// ---------------- scatter: (src, ea) into 8B slots ----------------
__global__ void scatter_perm_kernel(const int* __restrict__ ei, const float* __restrict__ ea) {
    float mn = g_mean;
    for (int idx = blockIdx.x * blockDim.x + threadIdx.x; idx < ET; idx += gridDim.x * blockDim.x) {
        int srcn, dstn; float eav;
        if (idx < EE) {
            srcn = ei[idx];
            dstn = ei[EE + idx];
            eav  = ea[idx];
        } else {
            srcn = dstn = idx - EE;
            eav  = mn;
        }
        int slot = atomicAdd(&g_cursor[dstn], 1);
        g_slot[slot] = make_int2(srcn, __float_as_int(eav));
    }
}

// ---------------- agg1 + gemm2 + al2, fully fused (warp per node) ----------------
__global__ void __launch_bounds__(256) agg1_gemm2_kernel(
        const float* __restrict__ b1, const float* __restrict__ g1,
        const float* __restrict__ be1, const float* __restrict__ W2,
        const float* __restrict__ as2, const float* __restrict__ ad2) {
    __shared__ float  Ws[HC * C1];     // 16KB
    __shared__ float4 sw[8][32];       // 4KB
    __shared__ int    ssrc[8][32];     // 1KB
    __shared__ float  sh1[8][HC];      // 4KB
    int tid = threadIdx.x;
    for (int i = tid; i < HC * C1; i += blockDim.x) Ws[i] = W2[i];
    __syncthreads();

    int wi   = tid >> 5;
    int lane = tid & 31;
    int n    = blockIdx.x * 8 + wi;
    if (n >= NN) return;
    int beg = g_rowptr[n], end = g_rowptr[n + 1];
    float4 ald = *(const float4*)(g_ald1 + n * 4);
    float k0 = g_k1v[0], k1 = g_k1v[1], k2 = g_k1v[2], k3 = g_k1v[3];

    float acc0 = 0.f, acc1 = 0.f, acc2 = 0.f, acc3 = 0.f;
    float den0 = 0.f, den1 = 0.f, den2 = 0.f, den3 = 0.f;

    for (int c0 = beg; c0 < end; c0 += 32) {
        int m = end - c0; if (m > 32) m = 32;
        if (lane < m) {
            int2 se = g_slot[c0 + lane];
            float4 als = *(const float4*)(g_als1 + se.x * 4);
            float eav = __int_as_float(se.y);
            float4 w;
            w.x = wexp(leaky(als.x + ald.x + k0 * eav));
            w.y = wexp(leaky(als.y + ald.y + k1 * eav));
            w.z = wexp(leaky(als.z + ald.z + k2 * eav));
            w.w = wexp(leaky(als.w + ald.w + k3 * eav));
            sw[wi][lane] = w;
            ssrc[wi][lane] = se.x;
        }
        __syncwarp();
        for (int i = 0; i < m; i++) {
            float4 w = sw[wi][i];
            int s = ssrc[wi][i];
            uint2 xv = g_xs1q[(size_t)s * 32 + lane];
            float2 x01 = __half22float2(*(__half2*)&xv.x);   // (head0, head1)
            float2 x23 = __half22float2(*(__half2*)&xv.y);   // (head2, head3)
            acc0 += w.x * x01.x;  den0 += w.x;
            acc1 += w.y * x01.y;  den1 += w.y;
            acc2 += w.z * x23.x;  den2 += w.z;
            acc3 += w.w * x23.y;  den3 += w.w;
        }
        __syncwarp();
    }

    // bias + bn + elu -> h1 (fp32) staged into smem
    float inv = rsqrtf(1.f + BN_EPS);
#pragma unroll
    for (int h = 0; h < 4; h++) {
        float a = (h == 0) ? acc0 : (h == 1) ? acc1 : (h == 2) ? acc2 : acc3;
        float d = (h == 0) ? den0 : (h == 1) ? den1 : (h == 2) ? den2 : den3;
        int c = h * 32 + lane;
        float v = a / (d + 1e-16f) + b1[c];
        v = v * (g1[c] * inv) + be1[c];
        sh1[wi][c] = elu(v);
    }
    __syncwarp();

    // gemm2: xs2[lane] = sum_k h1[k] * W2[k][lane]
    float s2 = 0.f;
    const float* hp = sh1[wi];
#pragma unroll 8
    for (int k = 0; k < HC; k++) s2 += hp[k] * Ws[k * C1 + lane];
    g_xs2h[(size_t)n * C1 + lane] = __float2half_rn(s2);

    // al2 warp reduction
    float ps = s2 * as2[lane];
    float pd = s2 * ad2[lane];
#pragma unroll
    for (int off = 16; off > 0; off >>= 1) {
        ps += __shfl_xor_sync(0xffffffffu, ps, off);
        pd += __shfl_xor_sync(0xffffffffu, pd, off);
    }
    if (lane == 0) { g_als2[n] = ps; g_ald2[n] = pd; }
}

// ---------------- agg2: warp/node, smem-staged weights + bn+elu + heads ----------
__global__ void agg2_heads_kernel(const float* __restrict__ b2, const float* __restrict__ g2,
                                  const float* __restrict__ be2,
                                  const float* __restrict__ Wc1, const float* __restrict__ bc1,
                                  const float* __restrict__ Wc2, const float* __restrict__ bc2,
                                  const float* __restrict__ Wr1, const float* __restrict__ br1,
                                  const float* __restrict__ Wr2, const float* __restrict__ br2,
                                  float* __restrict__ out) {
    __shared__ float sWc1[C1 * 16], sWr1[C1 * 16];
    __shared__ float sWc2[32], sWr2[16];
    __shared__ float sbc1[16], sbr1[16], sbc2[2], sbr2v[1];
    __shared__ float sh[8][32];
    __shared__ float sw2[8][32];
    __shared__ int   ssrc2[8][32];
    int t = threadIdx.x;
    for (int i = t; i < C1 * 16; i += blockDim.x) { sWc1[i] = Wc1[i]; sWr1[i] = Wr1[i]; }
    if (t < 32) sWc2[t] = Wc2[t];
    if (t < 16) { sWr2[t] = Wr2[t]; sbc1[t] = bc1[t]; sbr1[t] = br1[t]; }
    if (t < 2)  sbc2[t] = bc2[t];
    if (t == 32) sbr2v[0] = br2[0];
    __syncthreads();

    int wi   = t >> 5;
    int lane = t & 31;
    int n    = blockIdx.x * 8 + wi;
    if (n >= NN) return;
    int beg = g_rowptr[n], end = g_rowptr[n + 1];
    float ald = g_ald2[n];
    float k2  = g_k2;

    float den = 0.f, acc = 0.f;
    for (int c0 = beg; c0 < end; c0 += 32) {
        int m = end - c0; if (m > 32) m = 32;
        if (lane < m) {
            int2 se = g_slot[c0 + lane];
            sw2[wi][lane] = wexp(leaky(g_als2[se.x] + ald + k2 * __int_as_float(se.y)));
            ssrc2[wi][lane] = se.x;
        }
        __syncwarp();
        for (int i = 0; i < m; i++) {
            float w = sw2[wi][i];
            int s = ssrc2[wi][i];
            acc += w * __half2float(g_xs2h[(size_t)s * C1 + lane]);
            den += w;
        }
        __syncwarp();
    }
    float v = acc / (den + 1e-16f) + b2[lane];
    v = v * (g2[lane] * rsqrtf(1.f + BN_EPS)) + be2[lane];
    float h = elu(v);
    out[3 * NN + (size_t)n * C1 + lane] = h;
    sh[wi][lane] = h;
    __syncwarp();

    int j = lane & 15;
    const float* W = (lane < 16) ? sWc1 : sWr1;
    float tt = (lane < 16) ? sbc1[j] : sbr1[j];
#pragma unroll
    for (int c = 0; c < C1; c++) tt += sh[wi][c] * W[c * 16 + j];
    tt = fmaxf(tt, 0.f);
    float pa = (lane < 16) ? tt * sWc2[j * 2 + 0] : tt * sWr2[j];
    float pb = (lane < 16) ? tt * sWc2[j * 2 + 1] : 0.f;
#pragma unroll
    for (int off = 8; off > 0; off >>= 1) {
        pa += __shfl_xor_sync(0xffffffffu, pa, off);
        pb += __shfl_xor_sync(0xffffffffu, pb, off);
    }
    if (lane == 0) {
        out[(size_t)n * 2 + 0] = pa + sbc2[0];
        out[(size_t)n * 2 + 1] = pb + sbc2[1];
    }
    if (lane == 16) {
        out[2 * NN + n] = pa + sbr2v[0];
    }
}

// ---------------- launch (stream-forked graph) ----------------
extern "C" void kernel_launch(void* const* d_in, const int* in_sizes, int n_in,
                              void* d_out, int out_size) {
    const float* x   = (const float*)d_in[0];
    const int*   ei  = (const int*)d_in[1];     // int32 (JAX x64 disabled)
    const float* ea  = (const float*)d_in[2];
    const float* W1  = (const float*)d_in[3];
    const float* as1 = (const float*)d_in[4];
    const float* ad1 = (const float*)d_in[5];
    const float* We1 = (const float*)d_in[6];
    const float* ae1 = (const float*)d_in[7];
    const float* b1  = (const float*)d_in[8];
    const float* g1  = (const float*)d_in[9];
    const float* be1 = (const float*)d_in[10];
    const float* W2  = (const float*)d_in[11];
    const float* as2 = (const float*)d_in[12];
    const float* ad2 = (const float*)d_in[13];
    const float* We2 = (const float*)d_in[14];
    const float* ae2 = (const float*)d_in[15];
    const float* b2  = (const float*)d_in[16];
    const float* g2  = (const float*)d_in[17];
    const float* be2 = (const float*)d_in[18];
    const float* Wc1 = (const float*)d_in[19];
    const float* bc1 = (const float*)d_in[20];
    const float* Wc2 = (const float*)d_in[21];
    const float* bc2 = (const float*)d_in[22];
    const float* Wr1 = (const float*)d_in[23];
    const float* br1 = (const float*)d_in[24];
    const float* Wr2 = (const float*)d_in[25];
    const float* br2 = (const float*)d_in[26];
    float* out = (float*)d_out;

    cudaStream_t sB;
    cudaStreamCreateWithFlags(&sB, cudaStreamNonBlocking);
    cudaEvent_t eFork, eJoin;
    cudaEventCreateWithFlags(&eFork, cudaEventDisableTiming);
    cudaEventCreateWithFlags(&eJoin, cudaEventDisableTiming);

    cudaEventRecord(eFork, 0);
    cudaStreamWaitEvent(sB, eFork, 0);

    // Branch B (CSR + scatter permutation)
    init_deg_kernel<<<(NN + 255) / 256, 256, 0, sB>>>();
    hist_mean_kernel<<<512, 256, 0, sB>>>(ei, ea);
    mean_fin_kernel<<<1, 512, 0, sB>>>(We1, ae1, We2, ae2);
    scan_part_kernel<<<NB, 256, 0, sB>>>();
    scan_mid_kernel<<<1, 256, 0, sB>>>();
    scan_fin_kernel<<<NB, 256, 0, sB>>>();
    scatter_perm_kernel<<<2048, 256, 0, sB>>>(ei, ea);

    // Branch A (fp16 GEMM1 chain) on main stream
    convW1_kernel<<<(INC * HC / 8 + 255) / 256, 256>>>(W1);
    sgemm1_wmma<<<(NN + 127) / 128, 256>>>(x);
    post1_kernel<<<(NN * 2 + 255) / 256, 256>>>(as1, ad1);

    cudaEventRecord(eJoin, sB);
    cudaStreamWaitEvent(0, eJoin, 0);

    // Joined tail on main stream
    agg1_gemm2_kernel<<<(NN + 7) / 8, 256>>>(b1, g1, be1, W2, as2, ad2);
    agg2_heads_kernel<<<(NN + 7) / 8, 256>>>(b2, g2, be2,
        Wc1, bc1, Wc2, bc2, Wr1, br1, Wr2, br2, out);

    cudaEventDestroy(eFork);
    cudaEventDestroy(eJoin);
    // sB intentionally not destroyed during capture.
}